// round 6
// baseline (speedup 1.0000x reference)
#include <cuda_runtime.h>
#include <cstdint>

#define BATCHES 8
#define NB      32768
#define NCLS    81
#define PRE_K   2048
#define CAP     4096
#define MAX_OUT 200
#define SB_ANCH 128
#define NBINS   16384
#define BINBASE 0x3D4CCu          /* bits(0.05f) >> 12 */
#define PADIDX(i) ((i) + ((i) >> 4))

// ---------------- scratch (device globals) ---------------------------------
__device__ unsigned long long g_keys[BATCHES * NB];   // (score_bits<<32)|(NB-1-idx), 0 if invalid
__device__ unsigned char      g_cat [BATCHES * NB];   // argmax class
__device__ unsigned int       g_hist[BATCHES * NBINS];// per-batch score-bucket histogram
__device__ unsigned int       g_thresh[BATCHES];      // selection threshold (score bits)
__device__ unsigned int       g_selcnt[BATCHES];      // selected count
__device__ unsigned long long g_sel[BATCHES * CAP];   // selected keys (unordered)

// ---------------- kernel 1: score/argmax (TMA-staged) + histogram ----------
__global__ void __launch_bounds__(SB_ANCH)
score_kernel(const float* __restrict__ confs) {
    __shared__ alignas(16) float s[SB_ANCH * NCLS];       // 41472 B
    __shared__ alignas(8)  unsigned long long mbar;

    const unsigned bytes  = SB_ANCH * NCLS * 4;
    unsigned mbar_a = (unsigned)__cvta_generic_to_shared(&mbar);
    unsigned smem_a = (unsigned)__cvta_generic_to_shared(s);
    const int a0 = blockIdx.x * SB_ANCH;

    if (threadIdx.x == 0)
        asm volatile("mbarrier.init.shared.b64 [%0], 1;" :: "r"(mbar_a) : "memory");
    __syncthreads();
    if (threadIdx.x == 0) {
        asm volatile("mbarrier.arrive.expect_tx.shared.b64 _, [%0], %1;"
                     :: "r"(mbar_a), "r"(bytes) : "memory");
        asm volatile("cp.async.bulk.shared::cta.global.mbarrier::complete_tx::bytes [%0], [%1], %2, [%3];"
                     :: "r"(smem_a), "l"(confs + (size_t)a0 * NCLS), "r"(bytes), "r"(mbar_a)
                     : "memory");
    }
    unsigned done = 0;
    do {
        asm volatile("{\n\t.reg .pred P;\n\t"
                     "mbarrier.try_wait.parity.acquire.cta.shared::cta.b64 P, [%1], %2, 0x989680;\n\t"
                     "selp.b32 %0, 1, 0, P;\n\t}"
                     : "=r"(done) : "r"(mbar_a), "r"(0u) : "memory");
    } while (!done);

    const float* row = s + threadIdx.x * NCLS;   // stride 81 floats: conflict-free
    float m = -1.0f; int mi = 0;
    #pragma unroll
    for (int j = 0; j < NCLS; j++) {
        float v = row[j];
        if (v > m) { m = v; mi = j; }            // ascending j + '>' keeps first max
    }
    const int a = a0 + threadIdx.x;
    bool valid = (m > 0.05f) && (mi != 0);
    unsigned int n = (unsigned int)a & (NB - 1);
    unsigned long long key = 0ULL;
    if (valid) {
        unsigned int sb = __float_as_uint(m);
        key = (((unsigned long long)sb) << 32) | (unsigned long long)(NB - 1u - n);
        unsigned int bucket = (sb >> 12) - BINBASE;   // monotone, < NBINS
        atomicAdd(&g_hist[(a >> 15) * NBINS + bucket], 1u);
    }
    g_keys[a] = key;
    g_cat[a]  = (unsigned char)mi;
}

// ---------------- kernel 2: per-batch threshold from histogram -------------
// dyn smem: bins (padded u32[NBINS + NBINS/16]) = 69632 B
__global__ void __launch_bounds__(1024)
thresh_kernel() {
    extern __shared__ unsigned int bins[];
    __shared__ unsigned int sarr[1024];
    __shared__ unsigned int wsum[32];
    __shared__ unsigned int sh_Tb;

    const int b = blockIdx.x;
    const int tid  = threadIdx.x;
    const int lane = tid & 31;
    const int warp = tid >> 5;

    const unsigned int* gh = g_hist + (size_t)b * NBINS;
    for (int i = tid; i < NBINS; i += 1024) bins[PADIDX(i)] = gh[i];
    if (tid == 0) { sh_Tb = 0; g_selcnt[b] = 0; }
    __syncthreads();

    unsigned int ls = 0;
    #pragma unroll
    for (int j = 0; j < 16; j++) ls += bins[PADIDX(tid * 16 + j)];
    sarr[1023 - tid] = ls;
    __syncthreads();

    {   // inclusive block scan over sarr (reversed order => suffix sums)
        unsigned int v = sarr[tid], sc = v;
        #pragma unroll
        for (int off = 1; off < 32; off <<= 1) {
            unsigned int t = __shfl_up_sync(0xffffffffu, sc, off);
            if (lane >= off) sc += t;
        }
        if (lane == 31) wsum[warp] = sc;
        __syncthreads();
        if (warp == 0) {
            unsigned int ws = wsum[lane];
            #pragma unroll
            for (int off = 1; off < 32; off <<= 1) {
                unsigned int t = __shfl_up_sync(0xffffffffu, ws, off);
                if (lane >= off) ws += t;
            }
            wsum[lane] = ws;
        }
        __syncthreads();
        sarr[tid] = sc + (warp ? wsum[warp - 1] : 0u);
    }
    __syncthreads();
    {
        unsigned int sincl = sarr[1023 - tid];    // sum over threads >= tid
        unsigned int run = sincl - ls;            // suffix strictly above my bins
        #pragma unroll
        for (int j = 15; j >= 0; j--) {
            unsigned int c = bins[PADIDX(tid * 16 + j)];
            run += c;
            if (run >= PRE_K && run - c < PRE_K) sh_Tb = (unsigned)(tid * 16 + j);
        }
    }
    __syncthreads();
    if (tid == 0) g_thresh[b] = (sh_Tb + BINBASE) << 12;
}

// ---------------- kernel 3: parallel compaction (8 blocks per batch) -------
__global__ void __launch_bounds__(256)
compact_kernel() {
    const int b    = blockIdx.x >> 3;
    const int part = blockIdx.x & 7;
    const unsigned int Tsb = g_thresh[b];
    const unsigned long long* keys = g_keys + (size_t)b * NB + part * (NB / 8);
    unsigned long long* sel = g_sel + (size_t)b * CAP;
    const int tid  = threadIdx.x;
    const int lane = tid & 31;

    #pragma unroll
    for (int it = 0; it < 4; it++) {
        unsigned long long kk[4];
        #pragma unroll
        for (int u = 0; u < 4; u++) kk[u] = keys[it * 1024 + u * 256 + tid];
        #pragma unroll
        for (int u = 0; u < 4; u++) {
            unsigned int sb = (unsigned int)(kk[u] >> 32);
            bool c = (sb >= Tsb);
            unsigned bal = __ballot_sync(0xffffffffu, c);
            if (bal) {
                int leader = __ffs(bal) - 1;
                unsigned int basep = 0;
                if (lane == leader) basep = atomicAdd(&g_selcnt[b], (unsigned)__popc(bal));
                basep = __shfl_sync(0xffffffffu, basep, leader);
                if (c) {
                    unsigned int pos = basep + (unsigned)__popc(bal & ((1u << lane) - 1u));
                    if (pos < CAP) sel[pos] = kk[u];
                }
            }
        }
    }
}

// ---------------- kernel 4: sort + NMS + output ----------------------------
// dyn smem: [0,32768) cand u64[4096]; [32768,65536) scand float4[2048];
//           [65536,69632) scls short[2048]
__global__ void __launch_bounds__(1024)
sortnms_kernel(const float* __restrict__ boxes, float* __restrict__ out, int write_cats) {
    extern __shared__ unsigned char dyn[];
    unsigned long long* cand  = (unsigned long long*)dyn;
    float4*             scand = (float4*)(dyn + 32768);
    short*              scls  = (short*)(dyn + 65536);

    __shared__ short kept_idx[MAX_OUT];
    __shared__ int   sh_nk;

    const int b = blockIdx.x;
    const int tid  = threadIdx.x;
    const int lane = tid & 31;

    // ---- load selected keys (zero-pad) ----
    unsigned int cnt = g_selcnt[b]; if (cnt > CAP) cnt = CAP;
    const unsigned long long* sel = g_sel + (size_t)b * CAP;
    #pragma unroll
    for (int s = 0; s < 4; s++) {
        int i = s * 1024 + tid;
        cand[i] = (i < (int)cnt) ? sel[i] : 0ULL;
    }
    __syncthreads();

    // ---- hybrid bitonic sort (descending), n = 4096 ----
    {
        unsigned long long v[4];
        #pragma unroll
        for (int s = 0; s < 4; s++) v[s] = cand[s * 1024 + tid];
        #pragma unroll
        for (int k = 2; k <= 32; k <<= 1) {
            #pragma unroll
            for (int j = k >> 1; j >= 1; j >>= 1) {
                #pragma unroll
                for (int s = 0; s < 4; s++) {
                    int i = s * 1024 + tid;
                    unsigned long long o = __shfl_xor_sync(0xffffffffu, v[s], j);
                    bool up    = ((i & k) == 0);
                    bool lower = ((i & j) == 0);
                    unsigned long long mx = v[s] > o ? v[s] : o;
                    unsigned long long mn = v[s] > o ? o : v[s];
                    v[s] = (up == lower) ? mx : mn;
                }
            }
        }
        #pragma unroll
        for (int s = 0; s < 4; s++) cand[s * 1024 + tid] = v[s];
    }
    __syncthreads();
    for (int k = 64; k <= CAP; k <<= 1) {
        for (int j = k >> 1; j >= 32; j >>= 1) {
            #pragma unroll
            for (int s0 = 0; s0 < CAP; s0 += 1024) {
                int i = s0 + tid;
                int l = i ^ j;
                if (l > i) {
                    unsigned long long a = cand[i], bb = cand[l];
                    bool up = ((i & k) == 0);
                    if ((a < bb) == up) { cand[i] = bb; cand[l] = a; }
                }
            }
            __syncthreads();
        }
        {
            unsigned long long v[4];
            #pragma unroll
            for (int s = 0; s < 4; s++) v[s] = cand[s * 1024 + tid];
            #pragma unroll
            for (int j = 16; j >= 1; j >>= 1) {
                #pragma unroll
                for (int s = 0; s < 4; s++) {
                    int i = s * 1024 + tid;
                    unsigned long long o = __shfl_xor_sync(0xffffffffu, v[s], j);
                    bool up    = ((i & k) == 0);
                    bool lower = ((i & j) == 0);
                    unsigned long long mx = v[s] > o ? v[s] : o;
                    unsigned long long mn = v[s] > o ? o : v[s];
                    v[s] = (up == lower) ? mx : mn;
                }
            }
            #pragma unroll
            for (int s = 0; s < 4; s++) cand[s * 1024 + tid] = v[s];
        }
        __syncthreads();
    }

    // ---- stage candidate boxes/classes ----
    const float*         bxs  = boxes + (size_t)b * NB * 4;
    const unsigned char* cats = g_cat + (size_t)b * NB;
    for (int i = tid; i < PRE_K; i += 1024) {
        unsigned long long k = cand[i];
        if (k == 0ULL) {
            scls[i] = -1;
            scand[i] = make_float4(0.f, 0.f, 0.f, 0.f);
        } else {
            int idx = (NB - 1) - (int)(unsigned int)k;
            scand[i] = *(const float4*)(bxs + (size_t)idx * 4);
            scls[i]  = (short)cats[idx];
        }
    }
    __syncthreads();

    // ---- warp 0: order-exact greedy NMS, register kept list, prefetched ----
    if (tid < 32) {
        float kx1[7], ky1[7], kx2[7], ky2[7], kar[7];
        short kcl[7];
        int nk = 0;
        short  ci = scls[0];
        float4 bb = scand[0];
        for (int i = 0; i < PRE_K && nk < MAX_OUT; i++) {
            if (ci < 0) break;             // sorted desc: zero tail
            int ip = (i + 1 < PRE_K) ? i + 1 : i;
            short  nci = scls[ip];         // prefetch next candidate
            float4 nbb = scand[ip];
            float ar = fmaxf(bb.z - bb.x, 0.f) * fmaxf(bb.w - bb.y, 0.f);
            bool sup = false;
            const int ns = (nk + 31) >> 5;
            #pragma unroll
            for (int s = 0; s < 7; s++) {
                if (s >= ns) break;
                if ((s * 32 + lane) < nk && kcl[s] == ci) {
                    float ix1 = fmaxf(bb.x, kx1[s]);
                    float iy1 = fmaxf(bb.y, ky1[s]);
                    float ix2 = fminf(bb.z, kx2[s]);
                    float iy2 = fminf(bb.w, ky2[s]);
                    float inter = fmaxf(ix2 - ix1, 0.f) * fmaxf(iy2 - iy1, 0.f);
                    float uni   = ar + kar[s] - inter;
                    if (inter / fmaxf(uni, 1e-9f) > 0.5f) sup = true;
                }
            }
            sup = __any_sync(0xffffffffu, sup);
            if (!sup) {
                int slot = nk >> 5;
                if ((nk & 31) == lane) {
                    #pragma unroll
                    for (int s = 0; s < 7; s++) {
                        if (slot == s) {
                            kx1[s] = bb.x; ky1[s] = bb.y;
                            kx2[s] = bb.z; ky2[s] = bb.w;
                            kar[s] = ar;   kcl[s] = ci;
                        }
                    }
                }
                if (lane == 0) kept_idx[nk] = (short)i;
                nk++;
            }
            ci = nci; bb = nbb;
        }
        if (lane == 0) sh_nk = nk;
    }
    __syncthreads();

    // ---- output ----
    const int nk = sh_nk;
    float* out5 = out + (size_t)b * MAX_OUT * 5;
    float* ocat = out + (size_t)BATCHES * MAX_OUT * 5 + (size_t)b * MAX_OUT;
    for (int k0 = tid; k0 < MAX_OUT; k0 += 1024) {
        float vx1 = 0, vy1 = 0, vx2 = 0, vy2 = 0, vs = 0, vc = 0;
        if (k0 < nk) {
            int i = kept_idx[k0];
            float4 bbv = scand[i];
            vx1 = bbv.x; vy1 = bbv.y; vx2 = bbv.z; vy2 = bbv.w;
            vs  = __uint_as_float((unsigned int)(cand[i] >> 32));
            vc  = (float)scls[i];
        }
        out5[k0 * 5 + 0] = vx1;
        out5[k0 * 5 + 1] = vy1;
        out5[k0 * 5 + 2] = vx2;
        out5[k0 * 5 + 3] = vy2;
        out5[k0 * 5 + 4] = vs;
        if (write_cats) ocat[k0] = vc;
    }
}

// ---------------- launch ----------------------------------------------------
extern "C" void kernel_launch(void* const* d_in, const int* in_sizes, int n_in,
                              void* d_out, int out_size) {
    const float* boxes = (const float*)d_in[0];
    const float* confs = (const float*)d_in[1];
    if (n_in >= 2 && in_sizes[0] > in_sizes[1]) {
        boxes = (const float*)d_in[1];
        confs = (const float*)d_in[0];
    }
    float* out = (float*)d_out;

    cudaMemsetAsync(d_out, 0, (size_t)out_size * sizeof(float), 0);
    void* hp = nullptr;
    cudaGetSymbolAddress(&hp, g_hist);
    cudaMemsetAsync(hp, 0, sizeof(unsigned int) * BATCHES * NBINS, 0);

    score_kernel<<<(BATCHES * NB) / SB_ANCH, SB_ANCH>>>(confs);

    const int thresh_dyn = (NBINS + NBINS / 16) * 4;   // 69632
    cudaFuncSetAttribute(thresh_kernel,
                         cudaFuncAttributeMaxDynamicSharedMemorySize, thresh_dyn);
    thresh_kernel<<<BATCHES, 1024, thresh_dyn>>>();

    compact_kernel<<<BATCHES * 8, 256>>>();

    const int dyn_bytes = 69632;
    cudaFuncSetAttribute(sortnms_kernel,
                         cudaFuncAttributeMaxDynamicSharedMemorySize, dyn_bytes);
    int write_cats = (out_size >= BATCHES * MAX_OUT * 6) ? 1 : 0;
    sortnms_kernel<<<BATCHES, 1024, dyn_bytes>>>(boxes, out, write_cats);
}

// round 7
// speedup vs baseline: 1.0840x; 1.0840x over previous
#include <cuda_runtime.h>
#include <cstdint>

#define BATCHES 8
#define NB      32768
#define NCLS    81
#define PRE_K   2048
#define FKTGT   256
#define FCAP    1024
#define CAP     4096
#define MAX_OUT 200
#define SB_ANCH 128
#define NBINS   16384
#define BINBASE 0x3D4CCu          /* bits(0.05f) >> 12 */
#define PADIDX(i) ((i) + ((i) >> 4))

// ---------------- scratch (device globals) ---------------------------------
__device__ unsigned long long g_keys[BATCHES * NB];   // (score_bits<<32)|(NB-1-idx), 0 if invalid
__device__ unsigned char      g_cat [BATCHES * NB];   // argmax class
__device__ unsigned int       g_hist[BATCHES * NBINS];// per-batch score-bucket histogram
__device__ unsigned int       g_thresh[BATCHES];      // full selection threshold (top-2048)
__device__ unsigned int       g_tfast[BATCHES];       // fast selection threshold (top-~256)
__device__ unsigned int       g_fastcnt[BATCHES];     // suffix count at g_tfast
__device__ unsigned int       g_selcnt[BATCHES];      // selected count (full threshold)
__device__ unsigned int       g_need_full[BATCHES];   // 1 => fallback kernel must run
__device__ unsigned long long g_sel[BATCHES * CAP];   // selected keys (unordered)

// ---------------- kernel 1: score/argmax (TMA-staged) + histogram ----------
__global__ void __launch_bounds__(SB_ANCH)
score_kernel(const float* __restrict__ confs) {
    __shared__ alignas(16) float s[SB_ANCH * NCLS];       // 41472 B
    __shared__ alignas(8)  unsigned long long mbar;

    const unsigned bytes  = SB_ANCH * NCLS * 4;
    unsigned mbar_a = (unsigned)__cvta_generic_to_shared(&mbar);
    unsigned smem_a = (unsigned)__cvta_generic_to_shared(s);
    const int a0 = blockIdx.x * SB_ANCH;

    if (threadIdx.x == 0)
        asm volatile("mbarrier.init.shared.b64 [%0], 1;" :: "r"(mbar_a) : "memory");
    __syncthreads();
    if (threadIdx.x == 0) {
        asm volatile("mbarrier.arrive.expect_tx.shared.b64 _, [%0], %1;"
                     :: "r"(mbar_a), "r"(bytes) : "memory");
        asm volatile("cp.async.bulk.shared::cta.global.mbarrier::complete_tx::bytes [%0], [%1], %2, [%3];"
                     :: "r"(smem_a), "l"(confs + (size_t)a0 * NCLS), "r"(bytes), "r"(mbar_a)
                     : "memory");
    }
    unsigned done = 0;
    do {
        asm volatile("{\n\t.reg .pred P;\n\t"
                     "mbarrier.try_wait.parity.acquire.cta.shared::cta.b64 P, [%1], %2, 0x989680;\n\t"
                     "selp.b32 %0, 1, 0, P;\n\t}"
                     : "=r"(done) : "r"(mbar_a), "r"(0u) : "memory");
    } while (!done);

    const float* row = s + threadIdx.x * NCLS;   // stride 81 floats: conflict-free
    float m = -1.0f; int mi = 0;
    #pragma unroll
    for (int j = 0; j < NCLS; j++) {
        float v = row[j];
        if (v > m) { m = v; mi = j; }            // ascending j + '>' keeps first max
    }
    const int a = a0 + threadIdx.x;
    bool valid = (m > 0.05f) && (mi != 0);
    unsigned int n = (unsigned int)a & (NB - 1);
    unsigned long long key = 0ULL;
    if (valid) {
        unsigned int sb = __float_as_uint(m);
        key = (((unsigned long long)sb) << 32) | (unsigned long long)(NB - 1u - n);
        unsigned int bucket = (sb >> 12) - BINBASE;   // monotone, < NBINS
        atomicAdd(&g_hist[(a >> 15) * NBINS + bucket], 1u);
    }
    g_keys[a] = key;
    g_cat[a]  = (unsigned char)mi;
}

// ---------------- kernel 2: per-batch thresholds from histogram ------------
// dyn smem: bins (padded u32[NBINS + NBINS/16]) = 69632 B
__global__ void __launch_bounds__(1024)
thresh_kernel() {
    extern __shared__ unsigned int bins[];
    __shared__ unsigned int sarr[1024];
    __shared__ unsigned int wsum[32];
    __shared__ unsigned int sh_Tb, sh_Tbf, sh_fcnt;

    const int b = blockIdx.x;
    const int tid  = threadIdx.x;
    const int lane = tid & 31;
    const int warp = tid >> 5;

    const unsigned int* gh = g_hist + (size_t)b * NBINS;
    for (int i = tid; i < NBINS; i += 1024) bins[PADIDX(i)] = gh[i];
    if (tid == 0) { sh_Tb = 0; sh_Tbf = 0; sh_fcnt = 0; g_selcnt[b] = 0; }
    __syncthreads();

    unsigned int ls = 0;
    #pragma unroll
    for (int j = 0; j < 16; j++) ls += bins[PADIDX(tid * 16 + j)];
    sarr[1023 - tid] = ls;
    __syncthreads();

    {   // inclusive block scan over sarr (reversed order => suffix sums)
        unsigned int v = sarr[tid], sc = v;
        #pragma unroll
        for (int off = 1; off < 32; off <<= 1) {
            unsigned int t = __shfl_up_sync(0xffffffffu, sc, off);
            if (lane >= off) sc += t;
        }
        if (lane == 31) wsum[warp] = sc;
        __syncthreads();
        if (warp == 0) {
            unsigned int ws = wsum[lane];
            #pragma unroll
            for (int off = 1; off < 32; off <<= 1) {
                unsigned int t = __shfl_up_sync(0xffffffffu, ws, off);
                if (lane >= off) ws += t;
            }
            wsum[lane] = ws;
        }
        __syncthreads();
        sarr[tid] = sc + (warp ? wsum[warp - 1] : 0u);
    }
    __syncthreads();
    {
        unsigned int sincl = sarr[1023 - tid];    // sum over threads >= tid
        unsigned int run = sincl - ls;            // suffix strictly above my bins
        #pragma unroll
        for (int j = 15; j >= 0; j--) {
            unsigned int c = bins[PADIDX(tid * 16 + j)];
            run += c;
            if (run >= PRE_K && run - c < PRE_K) sh_Tb = (unsigned)(tid * 16 + j);
            if (run >= FKTGT && run - c < FKTGT) { sh_Tbf = (unsigned)(tid * 16 + j); sh_fcnt = run; }
        }
    }
    __syncthreads();
    if (tid == 0) {
        unsigned total = sarr[1023];
        unsigned fc  = (total <= FKTGT) ? total : sh_fcnt;
        unsigned tbf = (total <= FKTGT) ? 0u    : sh_Tbf;
        g_thresh[b]    = (sh_Tb + BINBASE) << 12;
        g_tfast[b]     = (tbf + BINBASE) << 12;
        g_fastcnt[b]   = fc;
        g_need_full[b] = (fc > FCAP) ? 1u : 0u;
    }
}

// ---------------- kernel 3: parallel compaction (8 blocks per batch) -------
__global__ void __launch_bounds__(256)
compact_kernel() {
    const int b    = blockIdx.x >> 3;
    const int part = blockIdx.x & 7;
    const unsigned int Tsb = g_thresh[b];
    const unsigned long long* keys = g_keys + (size_t)b * NB + part * (NB / 8);
    unsigned long long* sel = g_sel + (size_t)b * CAP;
    const int tid  = threadIdx.x;
    const int lane = tid & 31;

    #pragma unroll
    for (int it = 0; it < 4; it++) {
        unsigned long long kk[4];
        #pragma unroll
        for (int u = 0; u < 4; u++) kk[u] = keys[it * 1024 + u * 256 + tid];
        #pragma unroll
        for (int u = 0; u < 4; u++) {
            unsigned int sb = (unsigned int)(kk[u] >> 32);
            bool c = (sb >= Tsb);
            unsigned bal = __ballot_sync(0xffffffffu, c);
            if (bal) {
                int leader = __ffs(bal) - 1;
                unsigned int basep = 0;
                if (lane == leader) basep = atomicAdd(&g_selcnt[b], (unsigned)__popc(bal));
                basep = __shfl_sync(0xffffffffu, basep, leader);
                if (c) {
                    unsigned int pos = basep + (unsigned)__popc(bal & ((1u << lane) - 1u));
                    if (pos < CAP) sel[pos] = kk[u];
                }
            }
        }
    }
}

// ---------------- shared NMS + output (device inline) ----------------------
__device__ __forceinline__ int run_nms_warp(const float4* scand, const short* scls,
                                            short* kept_idx, int lim, int lane) {
    float kx1[7], ky1[7], kx2[7], ky2[7], kar[7];
    short kcl[7];
    int nk = 0;
    for (int i = 0; i < lim && nk < MAX_OUT; i++) {
        short ci = scls[i];
        if (ci < 0) break;
        float4 bb = scand[i];
        float ar = fmaxf(bb.z - bb.x, 0.f) * fmaxf(bb.w - bb.y, 0.f);
        bool sup = false;
        const int ns = (nk + 31) >> 5;
        #pragma unroll
        for (int s = 0; s < 7; s++) {
            if (s >= ns) break;
            if ((s * 32 + lane) < nk && kcl[s] == ci) {
                float ix1 = fmaxf(bb.x, kx1[s]);
                float iy1 = fmaxf(bb.y, ky1[s]);
                float ix2 = fminf(bb.z, kx2[s]);
                float iy2 = fminf(bb.w, ky2[s]);
                float inter = fmaxf(ix2 - ix1, 0.f) * fmaxf(iy2 - iy1, 0.f);
                float uni   = ar + kar[s] - inter;
                if (inter / fmaxf(uni, 1e-9f) > 0.5f) sup = true;
            }
        }
        sup = __any_sync(0xffffffffu, sup);
        if (!sup) {
            int slot = nk >> 5;
            if ((nk & 31) == lane) {
                #pragma unroll
                for (int s = 0; s < 7; s++) {
                    if (slot == s) {
                        kx1[s] = bb.x; ky1[s] = bb.y;
                        kx2[s] = bb.z; ky2[s] = bb.w;
                        kar[s] = ar;   kcl[s] = ci;
                    }
                }
            }
            if (lane == 0) kept_idx[nk] = (short)i;
            nk++;
        }
    }
    return nk;
}

__device__ __forceinline__ void write_out(const float4* scand, const short* scls,
                                          const unsigned long long* cand,
                                          const short* kept_idx, int nk, int b,
                                          float* out, int write_cats, int tid, int nthr) {
    float* out5 = out + (size_t)b * MAX_OUT * 5;
    float* ocat = out + (size_t)BATCHES * MAX_OUT * 5 + (size_t)b * MAX_OUT;
    for (int k0 = tid; k0 < MAX_OUT; k0 += nthr) {
        float vx1 = 0, vy1 = 0, vx2 = 0, vy2 = 0, vs = 0, vc = 0;
        if (k0 < nk) {
            int i = kept_idx[k0];
            float4 bbv = scand[i];
            vx1 = bbv.x; vy1 = bbv.y; vx2 = bbv.z; vy2 = bbv.w;
            vs  = __uint_as_float((unsigned int)(cand[i] >> 32));
            vc  = (float)scls[i];
        }
        out5[k0 * 5 + 0] = vx1;
        out5[k0 * 5 + 1] = vy1;
        out5[k0 * 5 + 2] = vx2;
        out5[k0 * 5 + 3] = vy2;
        out5[k0 * 5 + 4] = vs;
        if (write_cats) ocat[k0] = vc;
    }
}

// ---------------- kernel 4: FAST path — prefix sort (<=1024) + NMS ---------
__global__ void __launch_bounds__(1024)
fast_sortnms_kernel(const float* __restrict__ boxes, float* __restrict__ out, int write_cats) {
    __shared__ unsigned long long fcand[FCAP];   // 8 KB
    __shared__ float4 scand[FCAP];               // 16 KB
    __shared__ short  scls[FCAP];                // 2 KB
    __shared__ short  kept_idx[MAX_OUT];
    __shared__ int    sh_nk;
    __shared__ unsigned int sh_cnt;

    const int b = blockIdx.x;
    const int tid  = threadIdx.x;
    const int lane = tid & 31;

    if (g_need_full[b]) return;                  // fastcnt > capacity: full path handles

    const unsigned int Tf   = g_tfast[b];
    unsigned int avail = g_selcnt[b]; if (avail > CAP) avail = CAP;
    const unsigned long long* sel = g_sel + (size_t)b * CAP;

    if (tid == 0) sh_cnt = 0;
    __syncthreads();

    // filter full selection (<=4096) down to fast prefix (sb >= Tf)
    #pragma unroll
    for (int it = 0; it < 4; it++) {
        int i = it * 1024 + tid;
        unsigned long long k = (i < (int)avail) ? sel[i] : 0ULL;
        bool c = ((unsigned int)(k >> 32) >= Tf) && (k != 0ULL);
        unsigned bal = __ballot_sync(0xffffffffu, c);
        if (bal) {
            int leader = __ffs(bal) - 1;
            unsigned int basep = 0;
            if (lane == leader) basep = atomicAdd(&sh_cnt, (unsigned)__popc(bal));
            basep = __shfl_sync(0xffffffffu, basep, leader);
            if (c) {
                unsigned int pos = basep + (unsigned)__popc(bal & ((1u << lane) - 1u));
                if (pos < FCAP) fcand[pos] = k;
            }
        }
    }
    __syncthreads();
    unsigned int cnt = sh_cnt; if (cnt > FCAP) cnt = FCAP;
    if (tid >= (int)cnt) fcand[tid] = 0ULL;
    __syncthreads();

    // bitonic sort 1024 (descending), 1 element per thread
    {
        unsigned long long v = fcand[tid];
        #pragma unroll
        for (int k = 2; k <= 32; k <<= 1) {
            #pragma unroll
            for (int j = k >> 1; j >= 1; j >>= 1) {
                unsigned long long o = __shfl_xor_sync(0xffffffffu, v, j);
                bool up    = ((tid & k) == 0);
                bool lower = ((tid & j) == 0);
                unsigned long long mx = v > o ? v : o;
                unsigned long long mn = v > o ? o : v;
                v = (up == lower) ? mx : mn;
            }
        }
        fcand[tid] = v;
    }
    __syncthreads();
    for (int k = 64; k <= FCAP; k <<= 1) {
        for (int j = k >> 1; j >= 32; j >>= 1) {
            int l = tid ^ j;
            if (l > tid) {
                unsigned long long a = fcand[tid], bb = fcand[l];
                bool up = ((tid & k) == 0);
                if ((a < bb) == up) { fcand[tid] = bb; fcand[l] = a; }
            }
            __syncthreads();
        }
        {
            unsigned long long v = fcand[tid];
            #pragma unroll
            for (int j = 16; j >= 1; j >>= 1) {
                unsigned long long o = __shfl_xor_sync(0xffffffffu, v, j);
                bool up    = ((tid & k) == 0);
                bool lower = ((tid & j) == 0);
                unsigned long long mx = v > o ? v : o;
                unsigned long long mn = v > o ? o : v;
                v = (up == lower) ? mx : mn;
            }
            fcand[tid] = v;
        }
        __syncthreads();
    }

    // stage boxes/classes
    const float*         bxs  = boxes + (size_t)b * NB * 4;
    const unsigned char* cats = g_cat + (size_t)b * NB;
    {
        unsigned long long k = fcand[tid];
        if (k == 0ULL) {
            scls[tid] = -1;
            scand[tid] = make_float4(0.f, 0.f, 0.f, 0.f);
        } else {
            int idx = (NB - 1) - (int)(unsigned int)k;
            scand[tid] = *(const float4*)(bxs + (size_t)idx * 4);
            scls[tid]  = (short)cats[idx];
        }
    }
    __syncthreads();

    if (tid < 32) {
        int nk = run_nms_warp(scand, scls, kept_idx, (int)cnt, lane);
        if (lane == 0) sh_nk = nk;
    }
    __syncthreads();

    const int nk = sh_nk;
    bool final = (nk >= MAX_OUT) || (cnt >= avail);
    if (final) {
        write_out(scand, scls, fcand, kept_idx, nk, b, out, write_cats, tid, 1024);
        if (tid == 0) g_need_full[b] = 0u;
    } else {
        if (tid == 0) g_need_full[b] = 1u;
    }
}

// ---------------- kernel 5: FULL fallback (flag-guarded) -------------------
// dyn smem: [0,32768) cand u64[4096]; [32768,65536) scand float4[2048];
//           [65536,69632) scls short[2048]
__global__ void __launch_bounds__(1024)
full_sortnms_kernel(const float* __restrict__ boxes, float* __restrict__ out, int write_cats) {
    extern __shared__ unsigned char dyn[];
    unsigned long long* cand  = (unsigned long long*)dyn;
    float4*             scand = (float4*)(dyn + 32768);
    short*              scls  = (short*)(dyn + 65536);

    __shared__ short kept_idx[MAX_OUT];
    __shared__ int   sh_nk;

    const int b = blockIdx.x;
    const int tid  = threadIdx.x;
    const int lane = tid & 31;

    if (!g_need_full[b]) return;

    unsigned int cnt = g_selcnt[b]; if (cnt > CAP) cnt = CAP;
    const unsigned long long* sel = g_sel + (size_t)b * CAP;
    #pragma unroll
    for (int s = 0; s < 4; s++) {
        int i = s * 1024 + tid;
        cand[i] = (i < (int)cnt) ? sel[i] : 0ULL;
    }
    __syncthreads();

    // hybrid bitonic sort (descending), n = 4096
    {
        unsigned long long v[4];
        #pragma unroll
        for (int s = 0; s < 4; s++) v[s] = cand[s * 1024 + tid];
        #pragma unroll
        for (int k = 2; k <= 32; k <<= 1) {
            #pragma unroll
            for (int j = k >> 1; j >= 1; j >>= 1) {
                #pragma unroll
                for (int s = 0; s < 4; s++) {
                    int i = s * 1024 + tid;
                    unsigned long long o = __shfl_xor_sync(0xffffffffu, v[s], j);
                    bool up    = ((i & k) == 0);
                    bool lower = ((i & j) == 0);
                    unsigned long long mx = v[s] > o ? v[s] : o;
                    unsigned long long mn = v[s] > o ? o : v[s];
                    v[s] = (up == lower) ? mx : mn;
                }
            }
        }
        #pragma unroll
        for (int s = 0; s < 4; s++) cand[s * 1024 + tid] = v[s];
    }
    __syncthreads();
    for (int k = 64; k <= CAP; k <<= 1) {
        for (int j = k >> 1; j >= 32; j >>= 1) {
            #pragma unroll
            for (int s0 = 0; s0 < CAP; s0 += 1024) {
                int i = s0 + tid;
                int l = i ^ j;
                if (l > i) {
                    unsigned long long a = cand[i], bb = cand[l];
                    bool up = ((i & k) == 0);
                    if ((a < bb) == up) { cand[i] = bb; cand[l] = a; }
                }
            }
            __syncthreads();
        }
        {
            unsigned long long v[4];
            #pragma unroll
            for (int s = 0; s < 4; s++) v[s] = cand[s * 1024 + tid];
            #pragma unroll
            for (int j = 16; j >= 1; j >>= 1) {
                #pragma unroll
                for (int s = 0; s < 4; s++) {
                    int i = s * 1024 + tid;
                    unsigned long long o = __shfl_xor_sync(0xffffffffu, v[s], j);
                    bool up    = ((i & k) == 0);
                    bool lower = ((i & j) == 0);
                    unsigned long long mx = v[s] > o ? v[s] : o;
                    unsigned long long mn = v[s] > o ? o : v[s];
                    v[s] = (up == lower) ? mx : mn;
                }
            }
            #pragma unroll
            for (int s = 0; s < 4; s++) cand[s * 1024 + tid] = v[s];
        }
        __syncthreads();
    }

    const float*         bxs  = boxes + (size_t)b * NB * 4;
    const unsigned char* cats = g_cat + (size_t)b * NB;
    for (int i = tid; i < PRE_K; i += 1024) {
        unsigned long long k = cand[i];
        if (k == 0ULL) {
            scls[i] = -1;
            scand[i] = make_float4(0.f, 0.f, 0.f, 0.f);
        } else {
            int idx = (NB - 1) - (int)(unsigned int)k;
            scand[i] = *(const float4*)(bxs + (size_t)idx * 4);
            scls[i]  = (short)cats[idx];
        }
    }
    __syncthreads();

    if (tid < 32) {
        int nk = run_nms_warp(scand, scls, kept_idx, PRE_K, lane);
        if (lane == 0) sh_nk = nk;
    }
    __syncthreads();

    write_out(scand, scls, cand, kept_idx, sh_nk, b, out, write_cats, tid, 1024);
}

// ---------------- launch ----------------------------------------------------
extern "C" void kernel_launch(void* const* d_in, const int* in_sizes, int n_in,
                              void* d_out, int out_size) {
    const float* boxes = (const float*)d_in[0];
    const float* confs = (const float*)d_in[1];
    if (n_in >= 2 && in_sizes[0] > in_sizes[1]) {
        boxes = (const float*)d_in[1];
        confs = (const float*)d_in[0];
    }
    float* out = (float*)d_out;

    cudaMemsetAsync(d_out, 0, (size_t)out_size * sizeof(float), 0);
    void* hp = nullptr;
    cudaGetSymbolAddress(&hp, g_hist);
    cudaMemsetAsync(hp, 0, sizeof(unsigned int) * BATCHES * NBINS, 0);

    score_kernel<<<(BATCHES * NB) / SB_ANCH, SB_ANCH>>>(confs);

    const int thresh_dyn = (NBINS + NBINS / 16) * 4;   // 69632
    cudaFuncSetAttribute(thresh_kernel,
                         cudaFuncAttributeMaxDynamicSharedMemorySize, thresh_dyn);
    thresh_kernel<<<BATCHES, 1024, thresh_dyn>>>();

    compact_kernel<<<BATCHES * 8, 256>>>();

    int write_cats = (out_size >= BATCHES * MAX_OUT * 6) ? 1 : 0;
    fast_sortnms_kernel<<<BATCHES, 1024>>>(boxes, out, write_cats);

    const int dyn_bytes = 69632;
    cudaFuncSetAttribute(full_sortnms_kernel,
                         cudaFuncAttributeMaxDynamicSharedMemorySize, dyn_bytes);
    full_sortnms_kernel<<<BATCHES, 1024, dyn_bytes>>>(boxes, out, write_cats);
}

// round 8
// speedup vs baseline: 1.9437x; 1.7930x over previous
#include <cuda_runtime.h>
#include <cstdint>

#define BATCHES 8
#define NB      32768
#define NCLS    81
#define PRE_K   2048
#define FKTGT   256
#define FCAP    1024
#define CAP     4096
#define MAX_OUT 200
#define SB_ANCH 128
#define NBINS   16384
#define BINBASE 0x3D4CCu          /* bits(0.05f) >> 12 */
#define PADIDX(i) ((i) + ((i) >> 4))
#define MROWS   384
#define MWORDS  12                /* 384/32 */

// ---------------- scratch (device globals) ---------------------------------
__device__ unsigned long long g_keys[BATCHES * NB];   // (score_bits<<32)|(NB-1-idx), 0 if invalid
__device__ unsigned char      g_cat [BATCHES * NB];   // argmax class
__device__ unsigned int       g_hist[BATCHES * NBINS];// per-batch score-bucket histogram
__device__ unsigned int       g_thresh[BATCHES];      // full selection threshold (top-2048)
__device__ unsigned int       g_tfast[BATCHES];       // fast selection threshold (top-~256)
__device__ unsigned int       g_fastcnt[BATCHES];     // suffix count at g_tfast
__device__ unsigned int       g_selcnt[BATCHES];      // selected count (full threshold)
__device__ unsigned int       g_need_full[BATCHES];   // 1 => fallback kernel must run
__device__ unsigned long long g_sel[BATCHES * CAP];   // selected keys (unordered)

// ---------------- kernel 1: score/argmax (TMA-staged) + histogram ----------
__global__ void __launch_bounds__(SB_ANCH)
score_kernel(const float* __restrict__ confs) {
    __shared__ alignas(16) float s[SB_ANCH * NCLS];       // 41472 B
    __shared__ alignas(8)  unsigned long long mbar;

    const unsigned bytes  = SB_ANCH * NCLS * 4;
    unsigned mbar_a = (unsigned)__cvta_generic_to_shared(&mbar);
    unsigned smem_a = (unsigned)__cvta_generic_to_shared(s);
    const int a0 = blockIdx.x * SB_ANCH;

    if (threadIdx.x == 0)
        asm volatile("mbarrier.init.shared.b64 [%0], 1;" :: "r"(mbar_a) : "memory");
    __syncthreads();
    if (threadIdx.x == 0) {
        asm volatile("mbarrier.arrive.expect_tx.shared.b64 _, [%0], %1;"
                     :: "r"(mbar_a), "r"(bytes) : "memory");
        asm volatile("cp.async.bulk.shared::cta.global.mbarrier::complete_tx::bytes [%0], [%1], %2, [%3];"
                     :: "r"(smem_a), "l"(confs + (size_t)a0 * NCLS), "r"(bytes), "r"(mbar_a)
                     : "memory");
    }
    unsigned done = 0;
    do {
        asm volatile("{\n\t.reg .pred P;\n\t"
                     "mbarrier.try_wait.parity.acquire.cta.shared::cta.b64 P, [%1], %2, 0x989680;\n\t"
                     "selp.b32 %0, 1, 0, P;\n\t}"
                     : "=r"(done) : "r"(mbar_a), "r"(0u) : "memory");
    } while (!done);

    const float* row = s + threadIdx.x * NCLS;   // stride 81 floats: conflict-free
    float m = -1.0f; int mi = 0;
    #pragma unroll
    for (int j = 0; j < NCLS; j++) {
        float v = row[j];
        if (v > m) { m = v; mi = j; }            // ascending j + '>' keeps first max
    }
    const int a = a0 + threadIdx.x;
    bool valid = (m > 0.05f) && (mi != 0);
    unsigned int n = (unsigned int)a & (NB - 1);
    unsigned long long key = 0ULL;
    if (valid) {
        unsigned int sb = __float_as_uint(m);
        key = (((unsigned long long)sb) << 32) | (unsigned long long)(NB - 1u - n);
        unsigned int bucket = (sb >> 12) - BINBASE;   // monotone, < NBINS
        atomicAdd(&g_hist[(a >> 15) * NBINS + bucket], 1u);
    }
    g_keys[a] = key;
    g_cat[a]  = (unsigned char)mi;
}

// ---------------- kernel 2: per-batch thresholds from histogram ------------
// dyn smem: bins (padded u32[NBINS + NBINS/16]) = 69632 B
__global__ void __launch_bounds__(1024)
thresh_kernel() {
    extern __shared__ unsigned int bins[];
    __shared__ unsigned int sarr[1024];
    __shared__ unsigned int wsum[32];
    __shared__ unsigned int sh_Tb, sh_Tbf, sh_fcnt;

    const int b = blockIdx.x;
    const int tid  = threadIdx.x;
    const int lane = tid & 31;
    const int warp = tid >> 5;

    const unsigned int* gh = g_hist + (size_t)b * NBINS;
    for (int i = tid; i < NBINS; i += 1024) bins[PADIDX(i)] = gh[i];
    if (tid == 0) { sh_Tb = 0; sh_Tbf = 0; sh_fcnt = 0; g_selcnt[b] = 0; }
    __syncthreads();

    unsigned int ls = 0;
    #pragma unroll
    for (int j = 0; j < 16; j++) ls += bins[PADIDX(tid * 16 + j)];
    sarr[1023 - tid] = ls;
    __syncthreads();

    {   // inclusive block scan over sarr (reversed order => suffix sums)
        unsigned int v = sarr[tid], sc = v;
        #pragma unroll
        for (int off = 1; off < 32; off <<= 1) {
            unsigned int t = __shfl_up_sync(0xffffffffu, sc, off);
            if (lane >= off) sc += t;
        }
        if (lane == 31) wsum[warp] = sc;
        __syncthreads();
        if (warp == 0) {
            unsigned int ws = wsum[lane];
            #pragma unroll
            for (int off = 1; off < 32; off <<= 1) {
                unsigned int t = __shfl_up_sync(0xffffffffu, ws, off);
                if (lane >= off) ws += t;
            }
            wsum[lane] = ws;
        }
        __syncthreads();
        sarr[tid] = sc + (warp ? wsum[warp - 1] : 0u);
    }
    __syncthreads();
    {
        unsigned int sincl = sarr[1023 - tid];    // sum over threads >= tid
        unsigned int run = sincl - ls;            // suffix strictly above my bins
        #pragma unroll
        for (int j = 15; j >= 0; j--) {
            unsigned int c = bins[PADIDX(tid * 16 + j)];
            run += c;
            if (run >= PRE_K && run - c < PRE_K) sh_Tb = (unsigned)(tid * 16 + j);
            if (run >= FKTGT && run - c < FKTGT) { sh_Tbf = (unsigned)(tid * 16 + j); sh_fcnt = run; }
        }
    }
    __syncthreads();
    if (tid == 0) {
        unsigned total = sarr[1023];
        unsigned fc  = (total <= FKTGT) ? total : sh_fcnt;
        unsigned tbf = (total <= FKTGT) ? 0u    : sh_Tbf;
        g_thresh[b]    = (sh_Tb + BINBASE) << 12;
        g_tfast[b]     = (tbf + BINBASE) << 12;
        g_fastcnt[b]   = fc;
        g_need_full[b] = (fc > FCAP) ? 1u : 0u;
    }
}

// ---------------- kernel 3: parallel compaction (8 blocks per batch) -------
__global__ void __launch_bounds__(256)
compact_kernel() {
    const int b    = blockIdx.x >> 3;
    const int part = blockIdx.x & 7;
    const unsigned int Tsb = g_thresh[b];
    const unsigned long long* keys = g_keys + (size_t)b * NB + part * (NB / 8);
    unsigned long long* sel = g_sel + (size_t)b * CAP;
    const int tid  = threadIdx.x;
    const int lane = tid & 31;

    #pragma unroll
    for (int it = 0; it < 4; it++) {
        unsigned long long kk[4];
        #pragma unroll
        for (int u = 0; u < 4; u++) kk[u] = keys[it * 1024 + u * 256 + tid];
        #pragma unroll
        for (int u = 0; u < 4; u++) {
            unsigned int sb = (unsigned int)(kk[u] >> 32);
            bool c = (sb >= Tsb);
            unsigned bal = __ballot_sync(0xffffffffu, c);
            if (bal) {
                int leader = __ffs(bal) - 1;
                unsigned int basep = 0;
                if (lane == leader) basep = atomicAdd(&g_selcnt[b], (unsigned)__popc(bal));
                basep = __shfl_sync(0xffffffffu, basep, leader);
                if (c) {
                    unsigned int pos = basep + (unsigned)__popc(bal & ((1u << lane) - 1u));
                    if (pos < CAP) sel[pos] = kk[u];
                }
            }
        }
    }
}

// ---------------- shared NMS (slow path) + output helpers ------------------
__device__ __forceinline__ int run_nms_warp(const float4* scand, const short* scls,
                                            short* kept_idx, int lim, int lane) {
    float kx1[7], ky1[7], kx2[7], ky2[7], kar[7];
    short kcl[7];
    int nk = 0;
    for (int i = 0; i < lim && nk < MAX_OUT; i++) {
        short ci = scls[i];
        if (ci < 0) break;
        float4 bb = scand[i];
        float ar = fmaxf(bb.z - bb.x, 0.f) * fmaxf(bb.w - bb.y, 0.f);
        bool sup = false;
        const int ns = (nk + 31) >> 5;
        #pragma unroll
        for (int s = 0; s < 7; s++) {
            if (s >= ns) break;
            if ((s * 32 + lane) < nk && kcl[s] == ci) {
                float ix1 = fmaxf(bb.x, kx1[s]);
                float iy1 = fmaxf(bb.y, ky1[s]);
                float ix2 = fminf(bb.z, kx2[s]);
                float iy2 = fminf(bb.w, ky2[s]);
                float inter = fmaxf(ix2 - ix1, 0.f) * fmaxf(iy2 - iy1, 0.f);
                float uni   = ar + kar[s] - inter;
                if (inter / fmaxf(uni, 1e-9f) > 0.5f) sup = true;
            }
        }
        sup = __any_sync(0xffffffffu, sup);
        if (!sup) {
            int slot = nk >> 5;
            if ((nk & 31) == lane) {
                #pragma unroll
                for (int s = 0; s < 7; s++) {
                    if (slot == s) {
                        kx1[s] = bb.x; ky1[s] = bb.y;
                        kx2[s] = bb.z; ky2[s] = bb.w;
                        kar[s] = ar;   kcl[s] = ci;
                    }
                }
            }
            if (lane == 0) kept_idx[nk] = (short)i;
            nk++;
        }
    }
    return nk;
}

__device__ __forceinline__ void write_out(const float4* scand, const short* scls,
                                          const unsigned long long* cand,
                                          const short* kept_idx, int nk, int b,
                                          float* out, int write_cats, int tid, int nthr) {
    float* out5 = out + (size_t)b * MAX_OUT * 5;
    float* ocat = out + (size_t)BATCHES * MAX_OUT * 5 + (size_t)b * MAX_OUT;
    for (int k0 = tid; k0 < MAX_OUT; k0 += nthr) {
        float vx1 = 0, vy1 = 0, vx2 = 0, vy2 = 0, vs = 0, vc = 0;
        if (k0 < nk) {
            int i = kept_idx[k0];
            float4 bbv = scand[i];
            vx1 = bbv.x; vy1 = bbv.y; vx2 = bbv.z; vy2 = bbv.w;
            vs  = __uint_as_float((unsigned int)(cand[i] >> 32));
            vc  = (float)scls[i];
        }
        out5[k0 * 5 + 0] = vx1;
        out5[k0 * 5 + 1] = vy1;
        out5[k0 * 5 + 2] = vx2;
        out5[k0 * 5 + 3] = vy2;
        out5[k0 * 5 + 4] = vs;
        if (write_cats) ocat[k0] = vc;
    }
}

// ---------------- kernel 4: FAST path — sort + bit-matrix NMS --------------
__global__ void __launch_bounds__(1024)
fast_sortnms_kernel(const float* __restrict__ boxes, float* __restrict__ out, int write_cats) {
    __shared__ unsigned long long fcand[FCAP];     // 8 KB
    __shared__ float4 scand[FCAP];                 // 16 KB
    __shared__ short  scls[FCAP];                  // 2 KB
    __shared__ unsigned int M[MROWS * MWORDS];     // 18 KB suppression bit-matrix
    __shared__ short  kept_idx[MAX_OUT];
    __shared__ int    sh_nk;
    __shared__ unsigned int sh_cnt;

    const int b = blockIdx.x;
    const int tid  = threadIdx.x;
    const int lane = tid & 31;

    if (g_need_full[b]) return;                  // fastcnt > capacity: full path handles

    const unsigned int Tf   = g_tfast[b];
    unsigned int avail = g_selcnt[b]; if (avail > CAP) avail = CAP;
    const unsigned long long* sel = g_sel + (size_t)b * CAP;

    if (tid == 0) sh_cnt = 0;
    __syncthreads();

    // filter full selection (<=4096) down to fast prefix (sb >= Tf)
    #pragma unroll
    for (int it = 0; it < 4; it++) {
        int i = it * 1024 + tid;
        unsigned long long k = (i < (int)avail) ? sel[i] : 0ULL;
        bool c = ((unsigned int)(k >> 32) >= Tf) && (k != 0ULL);
        unsigned bal = __ballot_sync(0xffffffffu, c);
        if (bal) {
            int leader = __ffs(bal) - 1;
            unsigned int basep = 0;
            if (lane == leader) basep = atomicAdd(&sh_cnt, (unsigned)__popc(bal));
            basep = __shfl_sync(0xffffffffu, basep, leader);
            if (c) {
                unsigned int pos = basep + (unsigned)__popc(bal & ((1u << lane) - 1u));
                if (pos < FCAP) fcand[pos] = k;
            }
        }
    }
    __syncthreads();
    unsigned int cnt = sh_cnt; if (cnt > FCAP) cnt = FCAP;
    if (tid >= (int)cnt) fcand[tid] = 0ULL;
    __syncthreads();

    // bitonic sort 1024 (descending), 1 element per thread
    {
        unsigned long long v = fcand[tid];
        #pragma unroll
        for (int k = 2; k <= 32; k <<= 1) {
            #pragma unroll
            for (int j = k >> 1; j >= 1; j >>= 1) {
                unsigned long long o = __shfl_xor_sync(0xffffffffu, v, j);
                bool up    = ((tid & k) == 0);
                bool lower = ((tid & j) == 0);
                unsigned long long mx = v > o ? v : o;
                unsigned long long mn = v > o ? o : v;
                v = (up == lower) ? mx : mn;
            }
        }
        fcand[tid] = v;
    }
    __syncthreads();
    for (int k = 64; k <= FCAP; k <<= 1) {
        for (int j = k >> 1; j >= 32; j >>= 1) {
            int l = tid ^ j;
            if (l > tid) {
                unsigned long long a = fcand[tid], bb = fcand[l];
                bool up = ((tid & k) == 0);
                if ((a < bb) == up) { fcand[tid] = bb; fcand[l] = a; }
            }
            __syncthreads();
        }
        {
            unsigned long long v = fcand[tid];
            #pragma unroll
            for (int j = 16; j >= 1; j >>= 1) {
                unsigned long long o = __shfl_xor_sync(0xffffffffu, v, j);
                bool up    = ((tid & k) == 0);
                bool lower = ((tid & j) == 0);
                unsigned long long mx = v > o ? v : o;
                unsigned long long mn = v > o ? o : v;
                v = (up == lower) ? mx : mn;
            }
            fcand[tid] = v;
        }
        __syncthreads();
    }

    // stage boxes/classes
    const float*         bxs  = boxes + (size_t)b * NB * 4;
    const unsigned char* cats = g_cat + (size_t)b * NB;
    {
        unsigned long long k = fcand[tid];
        if (k == 0ULL) {
            scls[tid] = -1;
            scand[tid] = make_float4(0.f, 0.f, 0.f, 0.f);
        } else {
            int idx = (NB - 1) - (int)(unsigned int)k;
            scand[tid] = *(const float4*)(bxs + (size_t)idx * 4);
            scls[tid]  = (short)cats[idx];
        }
    }
    __syncthreads();

    // build symmetric suppression bit-matrix over first MROWS sorted candidates
    for (int u = tid; u < MROWS * MWORDS; u += 1024) {
        int r = u / MWORDS;
        int w = u - r * MWORDS;
        short cr = scls[r];
        float4 br = scand[r];
        float arr = fmaxf(br.z - br.x, 0.f) * fmaxf(br.w - br.y, 0.f);
        unsigned bits = 0;
        if (cr >= 0) {
            int i0 = w * 32;
            #pragma unroll 4
            for (int t2 = 0; t2 < 32; t2++) {
                int i = i0 + t2;
                if (scls[i] == cr) {
                    float4 bi = scand[i];
                    float ix1 = fmaxf(br.x, bi.x);
                    float iy1 = fmaxf(br.y, bi.y);
                    float ix2 = fminf(br.z, bi.z);
                    float iy2 = fminf(br.w, bi.w);
                    float inter = fmaxf(ix2 - ix1, 0.f) * fmaxf(iy2 - iy1, 0.f);
                    float ai = fmaxf(bi.z - bi.x, 0.f) * fmaxf(bi.w - bi.y, 0.f);
                    float uni = arr + ai - inter;
                    if (inter / fmaxf(uni, 1e-9f) > 0.5f) bits |= (1u << t2);
                }
            }
        }
        M[u] = bits;
    }
    __syncthreads();

    // warp 0: greedy scan over bit-matrix; suppressed mask lives in registers
    const int lim = ((int)cnt < MROWS) ? (int)cnt : MROWS;
    if (tid < 32) {
        unsigned sup = 0;   // lane l (<MWORDS) holds suppressed bits [32l, 32l+32)
        int nk = 0;
        for (int i = 0; i < lim && nk < MAX_OUT; i++) {
            short ci = scls[i];
            if (ci < 0) break;
            unsigned sw = __shfl_sync(0xffffffffu, sup, i >> 5);
            if (!((sw >> (i & 31)) & 1u)) {
                if (lane < MWORDS) sup |= M[i * MWORDS + lane];
                if (lane == 0) kept_idx[nk] = (short)i;
                nk++;
            }
        }
        if (lane == 0) sh_nk = nk;
    }
    __syncthreads();

    const int nk = sh_nk;
    // complete iff: reached MAX_OUT, or we scanned every existing candidate
    bool complete = (nk >= MAX_OUT) || ((int)cnt <= MROWS && cnt >= avail);
    if (complete) {
        write_out(scand, scls, fcand, kept_idx, nk, b, out, write_cats, tid, 1024);
        if (tid == 0) g_need_full[b] = 0u;
    } else {
        if (tid == 0) g_need_full[b] = 1u;
    }
}

// ---------------- kernel 5: FULL fallback (flag-guarded) -------------------
// dyn smem: [0,32768) cand u64[4096]; [32768,65536) scand float4[2048];
//           [65536,69632) scls short[2048]
__global__ void __launch_bounds__(1024)
full_sortnms_kernel(const float* __restrict__ boxes, float* __restrict__ out, int write_cats) {
    extern __shared__ unsigned char dyn[];
    unsigned long long* cand  = (unsigned long long*)dyn;
    float4*             scand = (float4*)(dyn + 32768);
    short*              scls  = (short*)(dyn + 65536);

    __shared__ short kept_idx[MAX_OUT];
    __shared__ int   sh_nk;

    const int b = blockIdx.x;
    const int tid  = threadIdx.x;
    const int lane = tid & 31;

    if (!g_need_full[b]) return;

    unsigned int cnt = g_selcnt[b]; if (cnt > CAP) cnt = CAP;
    const unsigned long long* sel = g_sel + (size_t)b * CAP;
    #pragma unroll
    for (int s = 0; s < 4; s++) {
        int i = s * 1024 + tid;
        cand[i] = (i < (int)cnt) ? sel[i] : 0ULL;
    }
    __syncthreads();

    // hybrid bitonic sort (descending), n = 4096
    {
        unsigned long long v[4];
        #pragma unroll
        for (int s = 0; s < 4; s++) v[s] = cand[s * 1024 + tid];
        #pragma unroll
        for (int k = 2; k <= 32; k <<= 1) {
            #pragma unroll
            for (int j = k >> 1; j >= 1; j >>= 1) {
                #pragma unroll
                for (int s = 0; s < 4; s++) {
                    int i = s * 1024 + tid;
                    unsigned long long o = __shfl_xor_sync(0xffffffffu, v[s], j);
                    bool up    = ((i & k) == 0);
                    bool lower = ((i & j) == 0);
                    unsigned long long mx = v[s] > o ? v[s] : o;
                    unsigned long long mn = v[s] > o ? o : v[s];
                    v[s] = (up == lower) ? mx : mn;
                }
            }
        }
        #pragma unroll
        for (int s = 0; s < 4; s++) cand[s * 1024 + tid] = v[s];
    }
    __syncthreads();
    for (int k = 64; k <= CAP; k <<= 1) {
        for (int j = k >> 1; j >= 32; j >>= 1) {
            #pragma unroll
            for (int s0 = 0; s0 < CAP; s0 += 1024) {
                int i = s0 + tid;
                int l = i ^ j;
                if (l > i) {
                    unsigned long long a = cand[i], bb = cand[l];
                    bool up = ((i & k) == 0);
                    if ((a < bb) == up) { cand[i] = bb; cand[l] = a; }
                }
            }
            __syncthreads();
        }
        {
            unsigned long long v[4];
            #pragma unroll
            for (int s = 0; s < 4; s++) v[s] = cand[s * 1024 + tid];
            #pragma unroll
            for (int j = 16; j >= 1; j >>= 1) {
                #pragma unroll
                for (int s = 0; s < 4; s++) {
                    int i = s * 1024 + tid;
                    unsigned long long o = __shfl_xor_sync(0xffffffffu, v[s], j);
                    bool up    = ((i & k) == 0);
                    bool lower = ((i & j) == 0);
                    unsigned long long mx = v[s] > o ? v[s] : o;
                    unsigned long long mn = v[s] > o ? o : v[s];
                    v[s] = (up == lower) ? mx : mn;
                }
            }
            #pragma unroll
            for (int s = 0; s < 4; s++) cand[s * 1024 + tid] = v[s];
        }
        __syncthreads();
    }

    const float*         bxs  = boxes + (size_t)b * NB * 4;
    const unsigned char* cats = g_cat + (size_t)b * NB;
    for (int i = tid; i < PRE_K; i += 1024) {
        unsigned long long k = cand[i];
        if (k == 0ULL) {
            scls[i] = -1;
            scand[i] = make_float4(0.f, 0.f, 0.f, 0.f);
        } else {
            int idx = (NB - 1) - (int)(unsigned int)k;
            scand[i] = *(const float4*)(bxs + (size_t)idx * 4);
            scls[i]  = (short)cats[idx];
        }
    }
    __syncthreads();

    if (tid < 32) {
        int nk = run_nms_warp(scand, scls, kept_idx, PRE_K, lane);
        if (lane == 0) sh_nk = nk;
    }
    __syncthreads();

    write_out(scand, scls, cand, kept_idx, sh_nk, b, out, write_cats, tid, 1024);
}

// ---------------- launch ----------------------------------------------------
extern "C" void kernel_launch(void* const* d_in, const int* in_sizes, int n_in,
                              void* d_out, int out_size) {
    const float* boxes = (const float*)d_in[0];
    const float* confs = (const float*)d_in[1];
    if (n_in >= 2 && in_sizes[0] > in_sizes[1]) {
        boxes = (const float*)d_in[1];
        confs = (const float*)d_in[0];
    }
    float* out = (float*)d_out;

    cudaMemsetAsync(d_out, 0, (size_t)out_size * sizeof(float), 0);
    void* hp = nullptr;
    cudaGetSymbolAddress(&hp, g_hist);
    cudaMemsetAsync(hp, 0, sizeof(unsigned int) * BATCHES * NBINS, 0);

    score_kernel<<<(BATCHES * NB) / SB_ANCH, SB_ANCH>>>(confs);

    const int thresh_dyn = (NBINS + NBINS / 16) * 4;   // 69632
    cudaFuncSetAttribute(thresh_kernel,
                         cudaFuncAttributeMaxDynamicSharedMemorySize, thresh_dyn);
    thresh_kernel<<<BATCHES, 1024, thresh_dyn>>>();

    compact_kernel<<<BATCHES * 8, 256>>>();

    int write_cats = (out_size >= BATCHES * MAX_OUT * 6) ? 1 : 0;
    fast_sortnms_kernel<<<BATCHES, 1024>>>(boxes, out, write_cats);

    const int dyn_bytes = 69632;
    cudaFuncSetAttribute(full_sortnms_kernel,
                         cudaFuncAttributeMaxDynamicSharedMemorySize, dyn_bytes);
    full_sortnms_kernel<<<BATCHES, 1024, dyn_bytes>>>(boxes, out, write_cats);
}

// round 9
// speedup vs baseline: 2.5116x; 1.2922x over previous
#include <cuda_runtime.h>
#include <cstdint>

#define BATCHES 8
#define NB      32768
#define NCLS    81
#define PRE_K   2048
#define FKTGT   256
#define FCAP    1024
#define CAP     4096
#define MAX_OUT 200
#define SB_ANCH 128
#define NBINS   16384
#define BINBASE 0x3D4CCu          /* bits(0.05f) >> 12 */
#define PADIDX(i) ((i) + ((i) >> 4))
#define MROWS   384
#define MWORDS  12                /* 384/32 */

// ---------------- scratch (device globals) ---------------------------------
__device__ unsigned long long g_keys[BATCHES * NB];   // (score_bits<<32)|(NB-1-idx), 0 if invalid
__device__ unsigned char      g_cat [BATCHES * NB];   // argmax class
__device__ unsigned int       g_hist[BATCHES * NBINS];// per-batch score-bucket histogram
__device__ unsigned int       g_thresh[BATCHES];      // full selection threshold (top-2048)
__device__ unsigned int       g_tfast[BATCHES];       // fast selection threshold (top-~256)
__device__ unsigned int       g_selcnt[BATCHES];      // selected count (full threshold)
__device__ unsigned int       g_fcnt[BATCHES];        // selected count (fast threshold)
__device__ unsigned int       g_need_full[BATCHES];   // 1 => fallback kernel must run
__device__ unsigned long long g_sel [BATCHES * CAP];  // selected keys, full threshold (unordered)
__device__ unsigned long long g_fsel[BATCHES * FCAP]; // selected keys, fast threshold (unordered)

// ---------------- kernel 1: score/argmax (TMA-staged) + histogram ----------
__global__ void __launch_bounds__(SB_ANCH)
score_kernel(const float* __restrict__ confs) {
    __shared__ alignas(16) float s[SB_ANCH * NCLS];       // 41472 B
    __shared__ alignas(8)  unsigned long long mbar;

    const unsigned bytes  = SB_ANCH * NCLS * 4;
    unsigned mbar_a = (unsigned)__cvta_generic_to_shared(&mbar);
    unsigned smem_a = (unsigned)__cvta_generic_to_shared(s);
    const int a0 = blockIdx.x * SB_ANCH;

    if (threadIdx.x == 0)
        asm volatile("mbarrier.init.shared.b64 [%0], 1;" :: "r"(mbar_a) : "memory");
    __syncthreads();
    if (threadIdx.x == 0) {
        asm volatile("mbarrier.arrive.expect_tx.shared.b64 _, [%0], %1;"
                     :: "r"(mbar_a), "r"(bytes) : "memory");
        asm volatile("cp.async.bulk.shared::cta.global.mbarrier::complete_tx::bytes [%0], [%1], %2, [%3];"
                     :: "r"(smem_a), "l"(confs + (size_t)a0 * NCLS), "r"(bytes), "r"(mbar_a)
                     : "memory");
    }
    unsigned done = 0;
    do {
        asm volatile("{\n\t.reg .pred P;\n\t"
                     "mbarrier.try_wait.parity.acquire.cta.shared::cta.b64 P, [%1], %2, 0x989680;\n\t"
                     "selp.b32 %0, 1, 0, P;\n\t}"
                     : "=r"(done) : "r"(mbar_a), "r"(0u) : "memory");
    } while (!done);

    const float* row = s + threadIdx.x * NCLS;   // stride 81 floats: conflict-free
    float m = -1.0f; int mi = 0;
    #pragma unroll
    for (int j = 0; j < NCLS; j++) {
        float v = row[j];
        if (v > m) { m = v; mi = j; }            // ascending j + '>' keeps first max
    }
    const int a = a0 + threadIdx.x;
    bool valid = (m > 0.05f) && (mi != 0);
    unsigned int n = (unsigned int)a & (NB - 1);
    unsigned long long key = 0ULL;
    if (valid) {
        unsigned int sb = __float_as_uint(m);
        key = (((unsigned long long)sb) << 32) | (unsigned long long)(NB - 1u - n);
        unsigned int bucket = (sb >> 12) - BINBASE;   // monotone, < NBINS
        atomicAdd(&g_hist[(a >> 15) * NBINS + bucket], 1u);
    }
    g_keys[a] = key;
    g_cat[a]  = (unsigned char)mi;
}

// ---------------- kernel 2: per-batch thresholds from histogram ------------
// dyn smem: bins (padded u32[NBINS + NBINS/16]) = 69632 B
__global__ void __launch_bounds__(1024)
thresh_kernel() {
    extern __shared__ unsigned int bins[];
    __shared__ unsigned int sarr[1024];
    __shared__ unsigned int wsum[32];
    __shared__ unsigned int sh_Tb, sh_Tbf, sh_fcnt;

    const int b = blockIdx.x;
    const int tid  = threadIdx.x;
    const int lane = tid & 31;
    const int warp = tid >> 5;

    const unsigned int* gh = g_hist + (size_t)b * NBINS;
    for (int i = tid; i < NBINS; i += 1024) bins[PADIDX(i)] = gh[i];
    if (tid == 0) { sh_Tb = 0; sh_Tbf = 0; sh_fcnt = 0; g_selcnt[b] = 0; g_fcnt[b] = 0; }
    __syncthreads();

    unsigned int ls = 0;
    #pragma unroll
    for (int j = 0; j < 16; j++) ls += bins[PADIDX(tid * 16 + j)];
    sarr[1023 - tid] = ls;
    __syncthreads();

    {   // inclusive block scan over sarr (reversed order => suffix sums)
        unsigned int v = sarr[tid], sc = v;
        #pragma unroll
        for (int off = 1; off < 32; off <<= 1) {
            unsigned int t = __shfl_up_sync(0xffffffffu, sc, off);
            if (lane >= off) sc += t;
        }
        if (lane == 31) wsum[warp] = sc;
        __syncthreads();
        if (warp == 0) {
            unsigned int ws = wsum[lane];
            #pragma unroll
            for (int off = 1; off < 32; off <<= 1) {
                unsigned int t = __shfl_up_sync(0xffffffffu, ws, off);
                if (lane >= off) ws += t;
            }
            wsum[lane] = ws;
        }
        __syncthreads();
        sarr[tid] = sc + (warp ? wsum[warp - 1] : 0u);
    }
    __syncthreads();
    {
        unsigned int sincl = sarr[1023 - tid];    // sum over threads >= tid
        unsigned int run = sincl - ls;            // suffix strictly above my bins
        #pragma unroll
        for (int j = 15; j >= 0; j--) {
            unsigned int c = bins[PADIDX(tid * 16 + j)];
            run += c;
            if (run >= PRE_K && run - c < PRE_K) sh_Tb = (unsigned)(tid * 16 + j);
            if (run >= FKTGT && run - c < FKTGT) { sh_Tbf = (unsigned)(tid * 16 + j); sh_fcnt = run; }
        }
    }
    __syncthreads();
    if (tid == 0) {
        unsigned total = sarr[1023];
        unsigned fc  = (total <= FKTGT) ? total : sh_fcnt;
        unsigned tbf = (total <= FKTGT) ? 0u    : sh_Tbf;
        g_thresh[b]    = (sh_Tb + BINBASE) << 12;
        g_tfast[b]     = (tbf + BINBASE) << 12;
        g_need_full[b] = (fc > FCAP) ? 1u : 0u;
    }
}

// ---------------- kernel 3: compaction, dual threshold (8 blk/batch) -------
__global__ void __launch_bounds__(256)
compact_kernel() {
    const int b    = blockIdx.x >> 3;
    const int part = blockIdx.x & 7;
    const unsigned int Tsb = g_thresh[b];
    const unsigned int Tf  = g_tfast[b];
    const unsigned long long* keys = g_keys + (size_t)b * NB + part * (NB / 8);
    unsigned long long* sel  = g_sel  + (size_t)b * CAP;
    unsigned long long* fsel = g_fsel + (size_t)b * FCAP;
    const int tid  = threadIdx.x;
    const int lane = tid & 31;

    #pragma unroll
    for (int it = 0; it < 4; it++) {
        unsigned long long kk[4];
        #pragma unroll
        for (int u = 0; u < 4; u++) kk[u] = keys[it * 1024 + u * 256 + tid];
        #pragma unroll
        for (int u = 0; u < 4; u++) {
            unsigned int sb = (unsigned int)(kk[u] >> 32);
            bool c = (sb >= Tsb);
            unsigned bal = __ballot_sync(0xffffffffu, c);
            if (bal) {
                int leader = __ffs(bal) - 1;
                unsigned int basep = 0;
                if (lane == leader) basep = atomicAdd(&g_selcnt[b], (unsigned)__popc(bal));
                basep = __shfl_sync(0xffffffffu, basep, leader);
                if (c) {
                    unsigned int pos = basep + (unsigned)__popc(bal & ((1u << lane) - 1u));
                    if (pos < CAP) sel[pos] = kk[u];
                }
            }
            bool cf = (sb >= Tf);
            unsigned balf = __ballot_sync(0xffffffffu, cf);
            if (balf) {
                int leader = __ffs(balf) - 1;
                unsigned int basep = 0;
                if (lane == leader) basep = atomicAdd(&g_fcnt[b], (unsigned)__popc(balf));
                basep = __shfl_sync(0xffffffffu, basep, leader);
                if (cf) {
                    unsigned int pos = basep + (unsigned)__popc(balf & ((1u << lane) - 1u));
                    if (pos < FCAP) fsel[pos] = kk[u];
                }
            }
        }
    }
}

// ---------------- shared NMS (slow path) + output helper -------------------
__device__ __forceinline__ int run_nms_warp(const float4* scand, const short* scls,
                                            short* kept_idx, int lim, int lane) {
    float kx1[7], ky1[7], kx2[7], ky2[7], kar[7];
    short kcl[7];
    int nk = 0;
    for (int i = 0; i < lim && nk < MAX_OUT; i++) {
        short ci = scls[i];
        if (ci < 0) break;
        float4 bb = scand[i];
        float ar = fmaxf(bb.z - bb.x, 0.f) * fmaxf(bb.w - bb.y, 0.f);
        bool sup = false;
        const int ns = (nk + 31) >> 5;
        #pragma unroll
        for (int s = 0; s < 7; s++) {
            if (s >= ns) break;
            if ((s * 32 + lane) < nk && kcl[s] == ci) {
                float ix1 = fmaxf(bb.x, kx1[s]);
                float iy1 = fmaxf(bb.y, ky1[s]);
                float ix2 = fminf(bb.z, kx2[s]);
                float iy2 = fminf(bb.w, ky2[s]);
                float inter = fmaxf(ix2 - ix1, 0.f) * fmaxf(iy2 - iy1, 0.f);
                float uni   = ar + kar[s] - inter;
                if (inter / fmaxf(uni, 1e-9f) > 0.5f) sup = true;
            }
        }
        sup = __any_sync(0xffffffffu, sup);
        if (!sup) {
            int slot = nk >> 5;
            if ((nk & 31) == lane) {
                #pragma unroll
                for (int s = 0; s < 7; s++) {
                    if (slot == s) {
                        kx1[s] = bb.x; ky1[s] = bb.y;
                        kx2[s] = bb.z; ky2[s] = bb.w;
                        kar[s] = ar;   kcl[s] = ci;
                    }
                }
            }
            if (lane == 0) kept_idx[nk] = (short)i;
            nk++;
        }
    }
    return nk;
}

// ---------------- kernel 4: FAST path — sort + class-bucketed matrix NMS ---
__global__ void __launch_bounds__(1024)
fast_sortnms_kernel(const float* __restrict__ boxes, float* __restrict__ out, int write_cats) {
    __shared__ unsigned long long fcand[FCAP];               // 8 KB
    __shared__ alignas(16) float4 scand[FCAP];               // 16 KB
    __shared__ alignas(16) unsigned char cls8[FCAP];         // 1 KB
    __shared__ alignas(16) unsigned int M[MROWS * MWORDS];   // 18 KB suppression bit-matrix
    __shared__ unsigned short clist[MROWS];                  // candidates grouped by class
    __shared__ unsigned short coff[NCLS + 1];                // class list offsets
    __shared__ unsigned int   cpos[NCLS];                    // scatter cursors
    __shared__ short  kept_idx[MAX_OUT];
    __shared__ int    sh_nk;

    const int b = blockIdx.x;
    const int tid  = threadIdx.x;
    const int lane = tid & 31;

    if (g_need_full[b]) return;                  // fastcnt > capacity: full path handles

    unsigned int cnt = g_fcnt[b]; if (cnt > FCAP) cnt = FCAP;   // (>FCAP guarded above)
    unsigned int avail = g_selcnt[b]; if (avail > CAP) avail = CAP;

    // ---- load fast-selected keys (zero-pad) ----
    fcand[tid] = (tid < (int)cnt) ? g_fsel[(size_t)b * FCAP + tid] : 0ULL;
    __syncthreads();

    // ---- bitonic sort 1024 (descending), 1 element per thread ----
    {
        unsigned long long v = fcand[tid];
        #pragma unroll
        for (int k = 2; k <= 32; k <<= 1) {
            #pragma unroll
            for (int j = k >> 1; j >= 1; j >>= 1) {
                unsigned long long o = __shfl_xor_sync(0xffffffffu, v, j);
                bool up    = ((tid & k) == 0);
                bool lower = ((tid & j) == 0);
                unsigned long long mx = v > o ? v : o;
                unsigned long long mn = v > o ? o : v;
                v = (up == lower) ? mx : mn;
            }
        }
        fcand[tid] = v;
    }
    __syncthreads();
    for (int k = 64; k <= FCAP; k <<= 1) {
        for (int j = k >> 1; j >= 32; j >>= 1) {
            int l = tid ^ j;
            if (l > tid) {
                unsigned long long a = fcand[tid], bb = fcand[l];
                bool up = ((tid & k) == 0);
                if ((a < bb) == up) { fcand[tid] = bb; fcand[l] = a; }
            }
            __syncthreads();
        }
        {
            unsigned long long v = fcand[tid];
            #pragma unroll
            for (int j = 16; j >= 1; j >>= 1) {
                unsigned long long o = __shfl_xor_sync(0xffffffffu, v, j);
                bool up    = ((tid & k) == 0);
                bool lower = ((tid & j) == 0);
                unsigned long long mx = v > o ? v : o;
                unsigned long long mn = v > o ? o : v;
                v = (up == lower) ? mx : mn;
            }
            fcand[tid] = v;
        }
        __syncthreads();
    }

    // ---- stage boxes/classes; zero matrix; init class counters ----
    const float*         bxs  = boxes + (size_t)b * NB * 4;
    const unsigned char* cats = g_cat + (size_t)b * NB;
    {
        unsigned long long k = fcand[tid];
        if (k == 0ULL) {
            cls8[tid] = 0xFF;
            scand[tid] = make_float4(0.f, 0.f, 0.f, 0.f);
        } else {
            int idx = (NB - 1) - (int)(unsigned int)k;
            scand[tid] = *(const float4*)(bxs + (size_t)idx * 4);
            cls8[tid]  = cats[idx];
        }
    }
    #pragma unroll
    for (int u = tid; u < MROWS * MWORDS; u += 1024) M[u] = 0u;
    if (tid < NCLS) cpos[tid] = 0u;
    __syncthreads();

    const int lim = ((int)cnt < MROWS) ? (int)cnt : MROWS;

    // ---- class histogram over first lim candidates ----
    if (tid < lim) atomicAdd(&cpos[cls8[tid]], 1u);
    __syncthreads();
    if (tid == 0) {
        unsigned run = 0;
        for (int c = 0; c < NCLS; c++) { coff[c] = (unsigned short)run; run += cpos[c]; }
        coff[NCLS] = (unsigned short)run;
    }
    __syncthreads();
    if (tid < NCLS) cpos[tid] = coff[tid];
    __syncthreads();
    if (tid < lim) {
        unsigned p = atomicAdd(&cpos[cls8[tid]], 1u);
        clist[p] = (unsigned short)tid;
    }
    __syncthreads();

    // ---- suppression matrix via class lists (one thread per row) ----
    if (tid < lim) {
        const int r = tid;
        const int c = cls8[r];
        float4 br = scand[r];
        float arr = fmaxf(br.z - br.x, 0.f) * fmaxf(br.w - br.y, 0.f);
        const int e0 = coff[c], e1 = coff[c + 1];
        for (int e = e0; e < e1; e++) {
            int j = clist[e];
            if (j == r) continue;
            float4 bj = scand[j];
            float ix1 = fmaxf(br.x, bj.x);
            float iy1 = fmaxf(br.y, bj.y);
            float ix2 = fminf(br.z, bj.z);
            float iy2 = fminf(br.w, bj.w);
            float inter = fmaxf(ix2 - ix1, 0.f) * fmaxf(iy2 - iy1, 0.f);
            float aj = fmaxf(bj.z - bj.x, 0.f) * fmaxf(bj.w - bj.y, 0.f);
            float uni = arr + aj - inter;
            if (inter / fmaxf(uni, 1e-9f) > 0.5f)
                atomicOr(&M[r * MWORDS + (j >> 5)], 1u << (j & 31));
        }
    }
    __syncthreads();

    // ---- warp 0: greedy scan over bit-matrix ----
    if (tid < 32) {
        unsigned sup = 0;   // lane l (<MWORDS) holds suppressed bits [32l, 32l+32)
        int nk = 0;
        for (int i = 0; i < lim && nk < MAX_OUT; i++) {
            unsigned sw = __shfl_sync(0xffffffffu, sup, i >> 5);
            if (!((sw >> (i & 31)) & 1u)) {
                if (lane < MWORDS) sup |= M[i * MWORDS + lane];
                if (lane == 0) kept_idx[nk] = (short)i;
                nk++;
            }
        }
        if (lane == 0) sh_nk = nk;
    }
    __syncthreads();

    const int nk = sh_nk;
    // complete iff: reached MAX_OUT, or we scanned every existing candidate
    bool complete = (nk >= MAX_OUT) || ((int)cnt <= MROWS && cnt >= avail);
    if (complete) {
        float* out5 = out + (size_t)b * MAX_OUT * 5;
        float* ocat = out + (size_t)BATCHES * MAX_OUT * 5 + (size_t)b * MAX_OUT;
        if (tid < MAX_OUT) {
            int k0 = tid;
            float vx1 = 0, vy1 = 0, vx2 = 0, vy2 = 0, vs = 0, vc = 0;
            if (k0 < nk) {
                int i = kept_idx[k0];
                float4 bbv = scand[i];
                vx1 = bbv.x; vy1 = bbv.y; vx2 = bbv.z; vy2 = bbv.w;
                vs  = __uint_as_float((unsigned int)(fcand[i] >> 32));
                vc  = (float)cls8[i];
            }
            out5[k0 * 5 + 0] = vx1;
            out5[k0 * 5 + 1] = vy1;
            out5[k0 * 5 + 2] = vx2;
            out5[k0 * 5 + 3] = vy2;
            out5[k0 * 5 + 4] = vs;
            if (write_cats) ocat[k0] = vc;
        }
        if (tid == 0) g_need_full[b] = 0u;
    } else {
        if (tid == 0) g_need_full[b] = 1u;
    }
}

// ---------------- kernel 5: FULL fallback (flag-guarded) -------------------
// dyn smem: [0,32768) cand u64[4096]; [32768,65536) scand float4[2048];
//           [65536,69632) scls short[2048]
__global__ void __launch_bounds__(1024)
full_sortnms_kernel(const float* __restrict__ boxes, float* __restrict__ out, int write_cats) {
    extern __shared__ unsigned char dyn[];
    unsigned long long* cand  = (unsigned long long*)dyn;
    float4*             scand = (float4*)(dyn + 32768);
    short*              scls  = (short*)(dyn + 65536);

    __shared__ short kept_idx[MAX_OUT];
    __shared__ int   sh_nk;

    const int b = blockIdx.x;
    const int tid  = threadIdx.x;
    const int lane = tid & 31;

    if (!g_need_full[b]) return;

    unsigned int cnt = g_selcnt[b]; if (cnt > CAP) cnt = CAP;
    const unsigned long long* sel = g_sel + (size_t)b * CAP;
    #pragma unroll
    for (int s = 0; s < 4; s++) {
        int i = s * 1024 + tid;
        cand[i] = (i < (int)cnt) ? sel[i] : 0ULL;
    }
    __syncthreads();

    // hybrid bitonic sort (descending), n = 4096
    {
        unsigned long long v[4];
        #pragma unroll
        for (int s = 0; s < 4; s++) v[s] = cand[s * 1024 + tid];
        #pragma unroll
        for (int k = 2; k <= 32; k <<= 1) {
            #pragma unroll
            for (int j = k >> 1; j >= 1; j >>= 1) {
                #pragma unroll
                for (int s = 0; s < 4; s++) {
                    int i = s * 1024 + tid;
                    unsigned long long o = __shfl_xor_sync(0xffffffffu, v[s], j);
                    bool up    = ((i & k) == 0);
                    bool lower = ((i & j) == 0);
                    unsigned long long mx = v[s] > o ? v[s] : o;
                    unsigned long long mn = v[s] > o ? o : v[s];
                    v[s] = (up == lower) ? mx : mn;
                }
            }
        }
        #pragma unroll
        for (int s = 0; s < 4; s++) cand[s * 1024 + tid] = v[s];
    }
    __syncthreads();
    for (int k = 64; k <= CAP; k <<= 1) {
        for (int j = k >> 1; j >= 32; j >>= 1) {
            #pragma unroll
            for (int s0 = 0; s0 < CAP; s0 += 1024) {
                int i = s0 + tid;
                int l = i ^ j;
                if (l > i) {
                    unsigned long long a = cand[i], bb = cand[l];
                    bool up = ((i & k) == 0);
                    if ((a < bb) == up) { cand[i] = bb; cand[l] = a; }
                }
            }
            __syncthreads();
        }
        {
            unsigned long long v[4];
            #pragma unroll
            for (int s = 0; s < 4; s++) v[s] = cand[s * 1024 + tid];
            #pragma unroll
            for (int j = 16; j >= 1; j >>= 1) {
                #pragma unroll
                for (int s = 0; s < 4; s++) {
                    int i = s * 1024 + tid;
                    unsigned long long o = __shfl_xor_sync(0xffffffffu, v[s], j);
                    bool up    = ((i & k) == 0);
                    bool lower = ((i & j) == 0);
                    unsigned long long mx = v[s] > o ? v[s] : o;
                    unsigned long long mn = v[s] > o ? o : v[s];
                    v[s] = (up == lower) ? mx : mn;
                }
            }
            #pragma unroll
            for (int s = 0; s < 4; s++) cand[s * 1024 + tid] = v[s];
        }
        __syncthreads();
    }

    const float*         bxs  = boxes + (size_t)b * NB * 4;
    const unsigned char* cats = g_cat + (size_t)b * NB;
    for (int i = tid; i < PRE_K; i += 1024) {
        unsigned long long k = cand[i];
        if (k == 0ULL) {
            scls[i] = -1;
            scand[i] = make_float4(0.f, 0.f, 0.f, 0.f);
        } else {
            int idx = (NB - 1) - (int)(unsigned int)k;
            scand[i] = *(const float4*)(bxs + (size_t)idx * 4);
            scls[i]  = (short)cats[idx];
        }
    }
    __syncthreads();

    if (tid < 32) {
        int nk = run_nms_warp(scand, scls, kept_idx, PRE_K, lane);
        if (lane == 0) sh_nk = nk;
    }
    __syncthreads();

    const int nk = sh_nk;
    float* out5 = out + (size_t)b * MAX_OUT * 5;
    float* ocat = out + (size_t)BATCHES * MAX_OUT * 5 + (size_t)b * MAX_OUT;
    for (int k0 = tid; k0 < MAX_OUT; k0 += 1024) {
        float vx1 = 0, vy1 = 0, vx2 = 0, vy2 = 0, vs = 0, vc = 0;
        if (k0 < nk) {
            int i = kept_idx[k0];
            float4 bbv = scand[i];
            vx1 = bbv.x; vy1 = bbv.y; vx2 = bbv.z; vy2 = bbv.w;
            vs  = __uint_as_float((unsigned int)(cand[i] >> 32));
            vc  = (float)scls[i];
        }
        out5[k0 * 5 + 0] = vx1;
        out5[k0 * 5 + 1] = vy1;
        out5[k0 * 5 + 2] = vx2;
        out5[k0 * 5 + 3] = vy2;
        out5[k0 * 5 + 4] = vs;
        if (write_cats) ocat[k0] = vc;
    }
}

// ---------------- launch ----------------------------------------------------
extern "C" void kernel_launch(void* const* d_in, const int* in_sizes, int n_in,
                              void* d_out, int out_size) {
    const float* boxes = (const float*)d_in[0];
    const float* confs = (const float*)d_in[1];
    if (n_in >= 2 && in_sizes[0] > in_sizes[1]) {
        boxes = (const float*)d_in[1];
        confs = (const float*)d_in[0];
    }
    float* out = (float*)d_out;

    cudaMemsetAsync(d_out, 0, (size_t)out_size * sizeof(float), 0);
    void* hp = nullptr;
    cudaGetSymbolAddress(&hp, g_hist);
    cudaMemsetAsync(hp, 0, sizeof(unsigned int) * BATCHES * NBINS, 0);

    score_kernel<<<(BATCHES * NB) / SB_ANCH, SB_ANCH>>>(confs);

    const int thresh_dyn = (NBINS + NBINS / 16) * 4;   // 69632
    cudaFuncSetAttribute(thresh_kernel,
                         cudaFuncAttributeMaxDynamicSharedMemorySize, thresh_dyn);
    thresh_kernel<<<BATCHES, 1024, thresh_dyn>>>();

    compact_kernel<<<BATCHES * 8, 256>>>();

    int write_cats = (out_size >= BATCHES * MAX_OUT * 6) ? 1 : 0;
    fast_sortnms_kernel<<<BATCHES, 1024>>>(boxes, out, write_cats);

    const int dyn_bytes = 69632;
    cudaFuncSetAttribute(full_sortnms_kernel,
                         cudaFuncAttributeMaxDynamicSharedMemorySize, dyn_bytes);
    full_sortnms_kernel<<<BATCHES, 1024, dyn_bytes>>>(boxes, out, write_cats);
}

// round 10
// speedup vs baseline: 2.6393x; 1.0508x over previous
#include <cuda_runtime.h>
#include <cstdint>

#define BATCHES 8
#define NB      32768
#define NCLS    81
#define PRE_K   2048
#define FKTGT   256
#define FCAP    1024
#define CAP     4096
#define MAX_OUT 200
#define SB_ANCH 128
#define NBINS   16384
#define BINBASE 0x3D4CCu          /* bits(0.05f) >> 12 */
#define PADIDX(i) ((i) + ((i) >> 4))
#define MROWS   384
#define MWORDS  12                /* 384/32 */

// ---------------- scratch (device globals) ---------------------------------
__device__ unsigned long long g_keys[BATCHES * NB];   // (score_bits<<32)|(NB-1-idx), 0 if invalid
__device__ unsigned char      g_cat [BATCHES * NB];   // argmax class
__device__ unsigned int       g_hist[BATCHES * NBINS];// per-batch score-bucket histogram (self-zeroing)
__device__ unsigned int       g_thresh[BATCHES];      // full selection threshold (top-2048)
__device__ unsigned int       g_tfast[BATCHES];       // fast selection threshold (top-~256)
__device__ unsigned int       g_selcnt[BATCHES];      // selected count (full threshold)
__device__ unsigned int       g_fcnt[BATCHES];        // selected count (fast threshold)
__device__ unsigned int       g_need_full[BATCHES];   // 1 => fallback kernel must run
__device__ unsigned long long g_sel [BATCHES * CAP];  // selected keys, full threshold (unordered)
__device__ unsigned long long g_fsel[BATCHES * FCAP]; // selected keys, fast threshold (unordered)

// ---------------- kernel 1: score/argmax (TMA-staged) + histogram ----------
__global__ void __launch_bounds__(SB_ANCH)
score_kernel(const float* __restrict__ confs) {
    __shared__ alignas(16) float s[SB_ANCH * NCLS];       // 41472 B
    __shared__ alignas(8)  unsigned long long mbar;

    const unsigned bytes  = SB_ANCH * NCLS * 4;
    unsigned mbar_a = (unsigned)__cvta_generic_to_shared(&mbar);
    unsigned smem_a = (unsigned)__cvta_generic_to_shared(s);
    const int a0 = blockIdx.x * SB_ANCH;

    if (threadIdx.x == 0)
        asm volatile("mbarrier.init.shared.b64 [%0], 1;" :: "r"(mbar_a) : "memory");
    __syncthreads();
    if (threadIdx.x == 0) {
        asm volatile("mbarrier.arrive.expect_tx.shared.b64 _, [%0], %1;"
                     :: "r"(mbar_a), "r"(bytes) : "memory");
        asm volatile("cp.async.bulk.shared::cta.global.mbarrier::complete_tx::bytes [%0], [%1], %2, [%3];"
                     :: "r"(smem_a), "l"(confs + (size_t)a0 * NCLS), "r"(bytes), "r"(mbar_a)
                     : "memory");
    }
    unsigned done = 0;
    do {
        asm volatile("{\n\t.reg .pred P;\n\t"
                     "mbarrier.try_wait.parity.acquire.cta.shared::cta.b64 P, [%1], %2, 0x989680;\n\t"
                     "selp.b32 %0, 1, 0, P;\n\t}"
                     : "=r"(done) : "r"(mbar_a), "r"(0u) : "memory");
    } while (!done);

    const float* row = s + threadIdx.x * NCLS;   // stride 81 floats: conflict-free
    float m = -1.0f; int mi = 0;
    #pragma unroll
    for (int j = 0; j < NCLS; j++) {
        float v = row[j];
        if (v > m) { m = v; mi = j; }            // ascending j + '>' keeps first max
    }
    const int a = a0 + threadIdx.x;
    bool valid = (m > 0.05f) && (mi != 0);
    unsigned int n = (unsigned int)a & (NB - 1);
    unsigned long long key = 0ULL;
    if (valid) {
        unsigned int sb = __float_as_uint(m);
        key = (((unsigned long long)sb) << 32) | (unsigned long long)(NB - 1u - n);
        unsigned int bucket = (sb >> 12) - BINBASE;   // monotone, < NBINS
        atomicAdd(&g_hist[(a >> 15) * NBINS + bucket], 1u);
    }
    g_keys[a] = key;
    g_cat[a]  = (unsigned char)mi;
}

// ---------------- kernel 2: per-batch thresholds from histogram ------------
// dyn smem: bins (padded u32[NBINS + NBINS/16]) = 69632 B
// Also re-zeroes g_hist for the next graph replay (same thread reads then clears).
__global__ void __launch_bounds__(1024)
thresh_kernel() {
    extern __shared__ unsigned int bins[];
    __shared__ unsigned int sarr[1024];
    __shared__ unsigned int wsum[32];
    __shared__ unsigned int sh_Tb, sh_Tbf, sh_fcnt;

    const int b = blockIdx.x;
    const int tid  = threadIdx.x;
    const int lane = tid & 31;
    const int warp = tid >> 5;

    unsigned int* gh = g_hist + (size_t)b * NBINS;
    for (int i = tid; i < NBINS; i += 1024) {
        bins[PADIDX(i)] = gh[i];
        gh[i] = 0u;                               // self-zero for next replay
    }
    if (tid == 0) { sh_Tb = 0; sh_Tbf = 0; sh_fcnt = 0; g_selcnt[b] = 0; g_fcnt[b] = 0; }
    __syncthreads();

    unsigned int ls = 0;
    #pragma unroll
    for (int j = 0; j < 16; j++) ls += bins[PADIDX(tid * 16 + j)];
    sarr[1023 - tid] = ls;
    __syncthreads();

    {   // inclusive block scan over sarr (reversed order => suffix sums)
        unsigned int v = sarr[tid], sc = v;
        #pragma unroll
        for (int off = 1; off < 32; off <<= 1) {
            unsigned int t = __shfl_up_sync(0xffffffffu, sc, off);
            if (lane >= off) sc += t;
        }
        if (lane == 31) wsum[warp] = sc;
        __syncthreads();
        if (warp == 0) {
            unsigned int ws = wsum[lane];
            #pragma unroll
            for (int off = 1; off < 32; off <<= 1) {
                unsigned int t = __shfl_up_sync(0xffffffffu, ws, off);
                if (lane >= off) ws += t;
            }
            wsum[lane] = ws;
        }
        __syncthreads();
        sarr[tid] = sc + (warp ? wsum[warp - 1] : 0u);
    }
    __syncthreads();
    {
        unsigned int sincl = sarr[1023 - tid];    // sum over threads >= tid
        unsigned int run = sincl - ls;            // suffix strictly above my bins
        #pragma unroll
        for (int j = 15; j >= 0; j--) {
            unsigned int c = bins[PADIDX(tid * 16 + j)];
            run += c;
            if (run >= PRE_K && run - c < PRE_K) sh_Tb = (unsigned)(tid * 16 + j);
            if (run >= FKTGT && run - c < FKTGT) { sh_Tbf = (unsigned)(tid * 16 + j); sh_fcnt = run; }
        }
    }
    __syncthreads();
    if (tid == 0) {
        unsigned total = sarr[1023];
        unsigned fc  = (total <= FKTGT) ? total : sh_fcnt;
        unsigned tbf = (total <= FKTGT) ? 0u    : sh_Tbf;
        g_thresh[b]    = (sh_Tb + BINBASE) << 12;
        g_tfast[b]     = (tbf + BINBASE) << 12;
        g_need_full[b] = (fc > FCAP) ? 1u : 0u;
    }
}

// ---------------- kernel 3: compaction, dual threshold (8 blk/batch) -------
__global__ void __launch_bounds__(256)
compact_kernel() {
    const int b    = blockIdx.x >> 3;
    const int part = blockIdx.x & 7;
    const unsigned int Tsb = g_thresh[b];
    const unsigned int Tf  = g_tfast[b];
    const unsigned long long* keys = g_keys + (size_t)b * NB + part * (NB / 8);
    unsigned long long* sel  = g_sel  + (size_t)b * CAP;
    unsigned long long* fsel = g_fsel + (size_t)b * FCAP;
    const int tid  = threadIdx.x;
    const int lane = tid & 31;

    #pragma unroll
    for (int it = 0; it < 4; it++) {
        unsigned long long kk[4];
        #pragma unroll
        for (int u = 0; u < 4; u++) kk[u] = keys[it * 1024 + u * 256 + tid];
        #pragma unroll
        for (int u = 0; u < 4; u++) {
            unsigned int sb = (unsigned int)(kk[u] >> 32);
            bool c = (sb >= Tsb);
            unsigned bal = __ballot_sync(0xffffffffu, c);
            if (bal) {
                int leader = __ffs(bal) - 1;
                unsigned int basep = 0;
                if (lane == leader) basep = atomicAdd(&g_selcnt[b], (unsigned)__popc(bal));
                basep = __shfl_sync(0xffffffffu, basep, leader);
                if (c) {
                    unsigned int pos = basep + (unsigned)__popc(bal & ((1u << lane) - 1u));
                    if (pos < CAP) sel[pos] = kk[u];
                }
            }
            bool cf = (sb >= Tf);
            unsigned balf = __ballot_sync(0xffffffffu, cf);
            if (balf) {
                int leader = __ffs(balf) - 1;
                unsigned int basep = 0;
                if (lane == leader) basep = atomicAdd(&g_fcnt[b], (unsigned)__popc(balf));
                basep = __shfl_sync(0xffffffffu, basep, leader);
                if (cf) {
                    unsigned int pos = basep + (unsigned)__popc(balf & ((1u << lane) - 1u));
                    if (pos < FCAP) fsel[pos] = kk[u];
                }
            }
        }
    }
}

// ---------------- shared NMS (slow path) -----------------------------------
__device__ __forceinline__ int run_nms_warp(const float4* scand, const short* scls,
                                            short* kept_idx, int lim, int lane) {
    float kx1[7], ky1[7], kx2[7], ky2[7], kar[7];
    short kcl[7];
    int nk = 0;
    for (int i = 0; i < lim && nk < MAX_OUT; i++) {
        short ci = scls[i];
        if (ci < 0) break;
        float4 bb = scand[i];
        float ar = fmaxf(bb.z - bb.x, 0.f) * fmaxf(bb.w - bb.y, 0.f);
        bool sup = false;
        const int ns = (nk + 31) >> 5;
        #pragma unroll
        for (int s = 0; s < 7; s++) {
            if (s >= ns) break;
            if ((s * 32 + lane) < nk && kcl[s] == ci) {
                float ix1 = fmaxf(bb.x, kx1[s]);
                float iy1 = fmaxf(bb.y, ky1[s]);
                float ix2 = fminf(bb.z, kx2[s]);
                float iy2 = fminf(bb.w, ky2[s]);
                float inter = fmaxf(ix2 - ix1, 0.f) * fmaxf(iy2 - iy1, 0.f);
                float uni   = ar + kar[s] - inter;
                if (inter / fmaxf(uni, 1e-9f) > 0.5f) sup = true;
            }
        }
        sup = __any_sync(0xffffffffu, sup);
        if (!sup) {
            int slot = nk >> 5;
            if ((nk & 31) == lane) {
                #pragma unroll
                for (int s = 0; s < 7; s++) {
                    if (slot == s) {
                        kx1[s] = bb.x; ky1[s] = bb.y;
                        kx2[s] = bb.z; ky2[s] = bb.w;
                        kar[s] = ar;   kcl[s] = ci;
                    }
                }
            }
            if (lane == 0) kept_idx[nk] = (short)i;
            nk++;
        }
    }
    return nk;
}

// ---------------- kernel 4: FAST path — sort + class-bucketed matrix NMS ---
__global__ void __launch_bounds__(1024)
fast_sortnms_kernel(const float* __restrict__ boxes, float* __restrict__ out, int write_cats) {
    __shared__ unsigned long long fcand[FCAP];               // 8 KB
    __shared__ alignas(16) float4 scand[FCAP];               // 16 KB
    __shared__ alignas(16) unsigned char cls8[FCAP];         // 1 KB
    __shared__ alignas(16) unsigned int M[MROWS * MWORDS];   // 18 KB suppression bit-matrix
    __shared__ unsigned short clist[MROWS];                  // candidates grouped by class
    __shared__ unsigned short coff[NCLS + 1];                // class list offsets
    __shared__ unsigned int   cpos[NCLS];                    // scatter cursors
    __shared__ short  kept_idx[MAX_OUT];
    __shared__ int    sh_nk;

    const int b = blockIdx.x;
    const int tid  = threadIdx.x;
    const int lane = tid & 31;

    if (g_need_full[b]) return;                  // fastcnt > capacity: full path handles

    unsigned int cnt = g_fcnt[b]; if (cnt > FCAP) cnt = FCAP;
    unsigned int avail = g_selcnt[b]; if (avail > CAP) avail = CAP;

    // ---- load fast-selected keys (zero-pad) ----
    fcand[tid] = (tid < (int)cnt) ? g_fsel[(size_t)b * FCAP + tid] : 0ULL;
    __syncthreads();

    // ---- bitonic sort 1024 (descending), 1 element per thread ----
    {
        unsigned long long v = fcand[tid];
        #pragma unroll
        for (int k = 2; k <= 32; k <<= 1) {
            #pragma unroll
            for (int j = k >> 1; j >= 1; j >>= 1) {
                unsigned long long o = __shfl_xor_sync(0xffffffffu, v, j);
                bool up    = ((tid & k) == 0);
                bool lower = ((tid & j) == 0);
                unsigned long long mx = v > o ? v : o;
                unsigned long long mn = v > o ? o : v;
                v = (up == lower) ? mx : mn;
            }
        }
        fcand[tid] = v;
    }
    __syncthreads();
    for (int k = 64; k <= FCAP; k <<= 1) {
        for (int j = k >> 1; j >= 32; j >>= 1) {
            int l = tid ^ j;
            if (l > tid) {
                unsigned long long a = fcand[tid], bb = fcand[l];
                bool up = ((tid & k) == 0);
                if ((a < bb) == up) { fcand[tid] = bb; fcand[l] = a; }
            }
            __syncthreads();
        }
        {
            unsigned long long v = fcand[tid];
            #pragma unroll
            for (int j = 16; j >= 1; j >>= 1) {
                unsigned long long o = __shfl_xor_sync(0xffffffffu, v, j);
                bool up    = ((tid & k) == 0);
                bool lower = ((tid & j) == 0);
                unsigned long long mx = v > o ? v : o;
                unsigned long long mn = v > o ? o : v;
                v = (up == lower) ? mx : mn;
            }
            fcand[tid] = v;
        }
        __syncthreads();
    }

    // ---- stage boxes/classes; zero matrix; init class counters ----
    const float*         bxs  = boxes + (size_t)b * NB * 4;
    const unsigned char* cats = g_cat + (size_t)b * NB;
    {
        unsigned long long k = fcand[tid];
        if (k == 0ULL) {
            cls8[tid] = 0xFF;
            scand[tid] = make_float4(0.f, 0.f, 0.f, 0.f);
        } else {
            int idx = (NB - 1) - (int)(unsigned int)k;
            scand[tid] = *(const float4*)(bxs + (size_t)idx * 4);
            cls8[tid]  = cats[idx];
        }
    }
    #pragma unroll
    for (int u = tid; u < MROWS * MWORDS; u += 1024) M[u] = 0u;
    if (tid < NCLS) cpos[tid] = 0u;
    __syncthreads();

    const int lim = ((int)cnt < MROWS) ? (int)cnt : MROWS;

    // ---- class histogram over first lim candidates ----
    if (tid < lim) atomicAdd(&cpos[cls8[tid]], 1u);
    __syncthreads();
    if (tid == 0) {
        unsigned run = 0;
        for (int c = 0; c < NCLS; c++) { coff[c] = (unsigned short)run; run += cpos[c]; }
        coff[NCLS] = (unsigned short)run;
    }
    __syncthreads();
    if (tid < NCLS) cpos[tid] = coff[tid];
    __syncthreads();
    if (tid < lim) {
        unsigned p = atomicAdd(&cpos[cls8[tid]], 1u);
        clist[p] = (unsigned short)tid;
    }
    __syncthreads();

    // ---- suppression matrix via class lists (one thread per row) ----
    if (tid < lim) {
        const int r = tid;
        const int c = cls8[r];
        float4 br = scand[r];
        float arr = fmaxf(br.z - br.x, 0.f) * fmaxf(br.w - br.y, 0.f);
        const int e0 = coff[c], e1 = coff[c + 1];
        for (int e = e0; e < e1; e++) {
            int j = clist[e];
            if (j == r) continue;
            float4 bj = scand[j];
            float ix1 = fmaxf(br.x, bj.x);
            float iy1 = fmaxf(br.y, bj.y);
            float ix2 = fminf(br.z, bj.z);
            float iy2 = fminf(br.w, bj.w);
            float inter = fmaxf(ix2 - ix1, 0.f) * fmaxf(iy2 - iy1, 0.f);
            float aj = fmaxf(bj.z - bj.x, 0.f) * fmaxf(bj.w - bj.y, 0.f);
            float uni = arr + aj - inter;
            if (inter / fmaxf(uni, 1e-9f) > 0.5f)
                atomicOr(&M[r * MWORDS + (j >> 5)], 1u << (j & 31));
        }
    }
    __syncthreads();

    // ---- warp 0: greedy scan, ffs-driven, uniform-broadcast row word ----
    if (tid < 32) {
        unsigned sup = 0;   // lane l (<MWORDS) holds suppressed bits [32l, 32l+32)
        int nk = 0;
        const int nwords = (lim + 31) >> 5;
        for (int w = 0; w < nwords; w++) {
            int remain = lim - (w << 5);
            unsigned valid = (remain >= 32) ? 0xFFFFFFFFu : ((1u << remain) - 1u);
            unsigned cur = __shfl_sync(0xffffffffu, sup, w);   // suppression from earlier words
            unsigned rem = ~cur & valid;
            while (rem) {
                int t = __ffs(rem) - 1;
                int i = (w << 5) + t;
                unsigned roww = M[i * MWORDS + w];             // uniform broadcast LDS
                if (lane < MWORDS) sup |= M[i * MWORDS + lane];// off critical path
                if (lane == 0) kept_idx[nk] = (short)i;
                nk++;
                if (nk >= MAX_OUT) { rem = 0; break; }
                rem &= ~(roww | (1u << t));
            }
            if (nk >= MAX_OUT) break;
        }
        if (lane == 0) sh_nk = nk;
    }
    __syncthreads();

    const int nk = sh_nk;
    // complete iff: reached MAX_OUT, or we scanned every existing candidate
    bool complete = (nk >= MAX_OUT) || ((int)cnt <= MROWS && cnt >= avail);
    if (complete) {
        float* out5 = out + (size_t)b * MAX_OUT * 5;
        float* ocat = out + (size_t)BATCHES * MAX_OUT * 5 + (size_t)b * MAX_OUT;
        if (tid < MAX_OUT) {
            int k0 = tid;
            float vx1 = 0, vy1 = 0, vx2 = 0, vy2 = 0, vs = 0, vc = 0;
            if (k0 < nk) {
                int i = kept_idx[k0];
                float4 bbv = scand[i];
                vx1 = bbv.x; vy1 = bbv.y; vx2 = bbv.z; vy2 = bbv.w;
                vs  = __uint_as_float((unsigned int)(fcand[i] >> 32));
                vc  = (float)cls8[i];
            }
            out5[k0 * 5 + 0] = vx1;
            out5[k0 * 5 + 1] = vy1;
            out5[k0 * 5 + 2] = vx2;
            out5[k0 * 5 + 3] = vy2;
            out5[k0 * 5 + 4] = vs;
            if (write_cats) ocat[k0] = vc;
        }
        if (tid == 0) g_need_full[b] = 0u;
    } else {
        if (tid == 0) g_need_full[b] = 1u;
    }
}

// ---------------- kernel 5: FULL fallback (flag-guarded) -------------------
// dyn smem: [0,32768) cand u64[4096]; [32768,65536) scand float4[2048];
//           [65536,69632) scls short[2048]
__global__ void __launch_bounds__(1024)
full_sortnms_kernel(const float* __restrict__ boxes, float* __restrict__ out, int write_cats) {
    extern __shared__ unsigned char dyn[];
    unsigned long long* cand  = (unsigned long long*)dyn;
    float4*             scand = (float4*)(dyn + 32768);
    short*              scls  = (short*)(dyn + 65536);

    __shared__ short kept_idx[MAX_OUT];
    __shared__ int   sh_nk;

    const int b = blockIdx.x;
    const int tid  = threadIdx.x;
    const int lane = tid & 31;

    if (!g_need_full[b]) return;

    unsigned int cnt = g_selcnt[b]; if (cnt > CAP) cnt = CAP;
    const unsigned long long* sel = g_sel + (size_t)b * CAP;
    #pragma unroll
    for (int s = 0; s < 4; s++) {
        int i = s * 1024 + tid;
        cand[i] = (i < (int)cnt) ? sel[i] : 0ULL;
    }
    __syncthreads();

    // hybrid bitonic sort (descending), n = 4096
    {
        unsigned long long v[4];
        #pragma unroll
        for (int s = 0; s < 4; s++) v[s] = cand[s * 1024 + tid];
        #pragma unroll
        for (int k = 2; k <= 32; k <<= 1) {
            #pragma unroll
            for (int j = k >> 1; j >= 1; j >>= 1) {
                #pragma unroll
                for (int s = 0; s < 4; s++) {
                    int i = s * 1024 + tid;
                    unsigned long long o = __shfl_xor_sync(0xffffffffu, v[s], j);
                    bool up    = ((i & k) == 0);
                    bool lower = ((i & j) == 0);
                    unsigned long long mx = v[s] > o ? v[s] : o;
                    unsigned long long mn = v[s] > o ? o : v[s];
                    v[s] = (up == lower) ? mx : mn;
                }
            }
        }
        #pragma unroll
        for (int s = 0; s < 4; s++) cand[s * 1024 + tid] = v[s];
    }
    __syncthreads();
    for (int k = 64; k <= CAP; k <<= 1) {
        for (int j = k >> 1; j >= 32; j >>= 1) {
            #pragma unroll
            for (int s0 = 0; s0 < CAP; s0 += 1024) {
                int i = s0 + tid;
                int l = i ^ j;
                if (l > i) {
                    unsigned long long a = cand[i], bb = cand[l];
                    bool up = ((i & k) == 0);
                    if ((a < bb) == up) { cand[i] = bb; cand[l] = a; }
                }
            }
            __syncthreads();
        }
        {
            unsigned long long v[4];
            #pragma unroll
            for (int s = 0; s < 4; s++) v[s] = cand[s * 1024 + tid];
            #pragma unroll
            for (int j = 16; j >= 1; j >>= 1) {
                #pragma unroll
                for (int s = 0; s < 4; s++) {
                    int i = s * 1024 + tid;
                    unsigned long long o = __shfl_xor_sync(0xffffffffu, v[s], j);
                    bool up    = ((i & k) == 0);
                    bool lower = ((i & j) == 0);
                    unsigned long long mx = v[s] > o ? v[s] : o;
                    unsigned long long mn = v[s] > o ? o : v[s];
                    v[s] = (up == lower) ? mx : mn;
                }
            }
            #pragma unroll
            for (int s = 0; s < 4; s++) cand[s * 1024 + tid] = v[s];
        }
        __syncthreads();
    }

    const float*         bxs  = boxes + (size_t)b * NB * 4;
    const unsigned char* cats = g_cat + (size_t)b * NB;
    for (int i = tid; i < PRE_K; i += 1024) {
        unsigned long long k = cand[i];
        if (k == 0ULL) {
            scls[i] = -1;
            scand[i] = make_float4(0.f, 0.f, 0.f, 0.f);
        } else {
            int idx = (NB - 1) - (int)(unsigned int)k;
            scand[i] = *(const float4*)(bxs + (size_t)idx * 4);
            scls[i]  = (short)cats[idx];
        }
    }
    __syncthreads();

    if (tid < 32) {
        int nk = run_nms_warp(scand, scls, kept_idx, PRE_K, lane);
        if (lane == 0) sh_nk = nk;
    }
    __syncthreads();

    const int nk = sh_nk;
    float* out5 = out + (size_t)b * MAX_OUT * 5;
    float* ocat = out + (size_t)BATCHES * MAX_OUT * 5 + (size_t)b * MAX_OUT;
    for (int k0 = tid; k0 < MAX_OUT; k0 += 1024) {
        float vx1 = 0, vy1 = 0, vx2 = 0, vy2 = 0, vs = 0, vc = 0;
        if (k0 < nk) {
            int i = kept_idx[k0];
            float4 bbv = scand[i];
            vx1 = bbv.x; vy1 = bbv.y; vx2 = bbv.z; vy2 = bbv.w;
            vs  = __uint_as_float((unsigned int)(cand[i] >> 32));
            vc  = (float)scls[i];
        }
        out5[k0 * 5 + 0] = vx1;
        out5[k0 * 5 + 1] = vy1;
        out5[k0 * 5 + 2] = vx2;
        out5[k0 * 5 + 3] = vy2;
        out5[k0 * 5 + 4] = vs;
        if (write_cats) ocat[k0] = vc;
    }
}

// ---------------- launch ----------------------------------------------------
extern "C" void kernel_launch(void* const* d_in, const int* in_sizes, int n_in,
                              void* d_out, int out_size) {
    const float* boxes = (const float*)d_in[0];
    const float* confs = (const float*)d_in[1];
    if (n_in >= 2 && in_sizes[0] > in_sizes[1]) {
        boxes = (const float*)d_in[1];
        confs = (const float*)d_in[0];
    }
    float* out = (float*)d_out;

    // out is fully written by the NMS path when out_size matches exactly;
    // otherwise fall back to zero-fill for the unwritten tail.
    if (out_size != BATCHES * MAX_OUT * 6)
        cudaMemsetAsync(d_out, 0, (size_t)out_size * sizeof(float), 0);

    score_kernel<<<(BATCHES * NB) / SB_ANCH, SB_ANCH>>>(confs);

    const int thresh_dyn = (NBINS + NBINS / 16) * 4;   // 69632
    cudaFuncSetAttribute(thresh_kernel,
                         cudaFuncAttributeMaxDynamicSharedMemorySize, thresh_dyn);
    thresh_kernel<<<BATCHES, 1024, thresh_dyn>>>();

    compact_kernel<<<BATCHES * 8, 256>>>();

    int write_cats = (out_size >= BATCHES * MAX_OUT * 6) ? 1 : 0;
    fast_sortnms_kernel<<<BATCHES, 1024>>>(boxes, out, write_cats);

    const int dyn_bytes = 69632;
    cudaFuncSetAttribute(full_sortnms_kernel,
                         cudaFuncAttributeMaxDynamicSharedMemorySize, dyn_bytes);
    full_sortnms_kernel<<<BATCHES, 1024, dyn_bytes>>>(boxes, out, write_cats);
}

// round 11
// speedup vs baseline: 2.8127x; 1.0657x over previous
#include <cuda_runtime.h>
#include <cstdint>

#define BATCHES 8
#define NB      32768
#define NCLS    81
#define PRE_K   2048
#define FKTGT   256
#define FCAP    1024
#define CAP     4096
#define MAX_OUT 200
#define SB_ANCH 128
#define NBINS   16384
#define BINBASE 0x3D4CCu          /* bits(0.05f) >> 12 */
#define PADIDX(i) ((i) + ((i) >> 4))
#define MROWS   384
#define MWORDS  12                /* 384/32 */
#define DYN_BYTES 69632           /* padded bins region; overlaid by fast-path arrays */

// ---------------- scratch (device globals) ---------------------------------
__device__ unsigned long long g_keys[BATCHES * NB];   // (score_bits<<32)|(NB-1-idx), 0 if invalid
__device__ unsigned char      g_cat [BATCHES * NB];   // argmax class
__device__ unsigned int       g_hist[BATCHES * NBINS];// per-batch histogram (self-zeroing)
__device__ unsigned int       g_selcnt[BATCHES];      // full-threshold selected count
__device__ unsigned int       g_need_full[BATCHES];   // 1 => fallback kernel must run
__device__ unsigned long long g_sel[BATCHES * CAP];   // full-threshold keys (unordered)

// ---------------- kernel 1: score/argmax (TMA-staged) + histogram ----------
__global__ void __launch_bounds__(SB_ANCH)
score_kernel(const float* __restrict__ confs) {
    __shared__ alignas(16) float s[SB_ANCH * NCLS];       // 41472 B
    __shared__ alignas(8)  unsigned long long mbar;

    const unsigned bytes  = SB_ANCH * NCLS * 4;
    unsigned mbar_a = (unsigned)__cvta_generic_to_shared(&mbar);
    unsigned smem_a = (unsigned)__cvta_generic_to_shared(s);
    const int a0 = blockIdx.x * SB_ANCH;

    if (threadIdx.x == 0)
        asm volatile("mbarrier.init.shared.b64 [%0], 1;" :: "r"(mbar_a) : "memory");
    __syncthreads();
    if (threadIdx.x == 0) {
        asm volatile("mbarrier.arrive.expect_tx.shared.b64 _, [%0], %1;"
                     :: "r"(mbar_a), "r"(bytes) : "memory");
        asm volatile("cp.async.bulk.shared::cta.global.mbarrier::complete_tx::bytes [%0], [%1], %2, [%3];"
                     :: "r"(smem_a), "l"(confs + (size_t)a0 * NCLS), "r"(bytes), "r"(mbar_a)
                     : "memory");
    }
    unsigned done = 0;
    do {
        asm volatile("{\n\t.reg .pred P;\n\t"
                     "mbarrier.try_wait.parity.acquire.cta.shared::cta.b64 P, [%1], %2, 0x989680;\n\t"
                     "selp.b32 %0, 1, 0, P;\n\t}"
                     : "=r"(done) : "r"(mbar_a), "r"(0u) : "memory");
    } while (!done);

    const float* row = s + threadIdx.x * NCLS;   // stride 81 floats: conflict-free
    float m = -1.0f; int mi = 0;
    #pragma unroll
    for (int j = 0; j < NCLS; j++) {
        float v = row[j];
        if (v > m) { m = v; mi = j; }            // ascending j + '>' keeps first max
    }
    const int a = a0 + threadIdx.x;
    bool valid = (m > 0.05f) && (mi != 0);
    unsigned int n = (unsigned int)a & (NB - 1);
    unsigned long long key = 0ULL;
    if (valid) {
        unsigned int sb = __float_as_uint(m);
        key = (((unsigned long long)sb) << 32) | (unsigned long long)(NB - 1u - n);
        unsigned int bucket = (sb >> 12) - BINBASE;   // monotone, < NBINS
        atomicAdd(&g_hist[(a >> 15) * NBINS + bucket], 1u);
    }
    g_keys[a] = key;
    g_cat[a]  = (unsigned char)mi;
}

// ---------------- shared NMS (slow path only) ------------------------------
__device__ __forceinline__ int run_nms_warp(const float4* scand, const short* scls,
                                            short* kept_idx, int lim, int lane) {
    float kx1[7], ky1[7], kx2[7], ky2[7], kar[7];
    short kcl[7];
    int nk = 0;
    for (int i = 0; i < lim && nk < MAX_OUT; i++) {
        short ci = scls[i];
        if (ci < 0) break;
        float4 bb = scand[i];
        float ar = fmaxf(bb.z - bb.x, 0.f) * fmaxf(bb.w - bb.y, 0.f);
        bool sup = false;
        const int ns = (nk + 31) >> 5;
        #pragma unroll
        for (int s = 0; s < 7; s++) {
            if (s >= ns) break;
            if ((s * 32 + lane) < nk && kcl[s] == ci) {
                float ix1 = fmaxf(bb.x, kx1[s]);
                float iy1 = fmaxf(bb.y, ky1[s]);
                float ix2 = fminf(bb.z, kx2[s]);
                float iy2 = fminf(bb.w, ky2[s]);
                float inter = fmaxf(ix2 - ix1, 0.f) * fmaxf(iy2 - iy1, 0.f);
                float uni   = ar + kar[s] - inter;
                if (inter / fmaxf(uni, 1e-9f) > 0.5f) sup = true;
            }
        }
        sup = __any_sync(0xffffffffu, sup);
        if (!sup) {
            int slot = nk >> 5;
            if ((nk & 31) == lane) {
                #pragma unroll
                for (int s = 0; s < 7; s++) {
                    if (slot == s) {
                        kx1[s] = bb.x; ky1[s] = bb.y;
                        kx2[s] = bb.z; ky2[s] = bb.w;
                        kar[s] = ar;   kcl[s] = ci;
                    }
                }
            }
            if (lane == 0) kept_idx[nk] = (short)i;
            nk++;
        }
    }
    return nk;
}

// ---------------- kernel 2: FUSED thresh + compact + sort + NMS ------------
// dyn smem phase A: bins (padded u32[NBINS + NBINS/16]) = 69632 B
// dyn smem phase B (overlay): [0,8192) fcand u64[1024]; [8192,24576) scand f4[1024];
//                             [24576,25600) cls8 u8[1024]; [25600,44032) M u32[384*12]
__global__ void __launch_bounds__(1024)
fused_kernel(const float* __restrict__ boxes, float* __restrict__ out, int write_cats) {
    extern __shared__ unsigned char dyn[];
    unsigned int*       bins  = (unsigned int*)dyn;
    unsigned long long* fcand = (unsigned long long*)dyn;
    float4*             scand = (float4*)(dyn + 8192);
    unsigned char*      cls8  = (unsigned char*)(dyn + 24576);
    unsigned int*       M     = (unsigned int*)(dyn + 25600);

    __shared__ unsigned int sarr[1024];
    __shared__ unsigned int wsum[32];
    __shared__ unsigned int sh_Tb, sh_Tbf, sh_fcnt;
    __shared__ unsigned int s_fc, s_sc;
    __shared__ unsigned short clist[MROWS];
    __shared__ unsigned short coff[NCLS + 1];
    __shared__ unsigned int   cpos[NCLS];
    __shared__ short  kept_idx[MAX_OUT];
    __shared__ int    sh_nk;

    const int b = blockIdx.x;
    const int tid  = threadIdx.x;
    const int lane = tid & 31;
    const int warp = tid >> 5;

    // ---- A: histogram -> thresholds (also self-zero g_hist) ----
    unsigned int* gh = g_hist + (size_t)b * NBINS;
    for (int i = tid; i < NBINS; i += 1024) {
        bins[PADIDX(i)] = gh[i];
        gh[i] = 0u;
    }
    if (tid == 0) { sh_Tb = 0; sh_Tbf = 0; sh_fcnt = 0; s_fc = 0; s_sc = 0; }
    __syncthreads();

    unsigned int ls = 0;
    #pragma unroll
    for (int j = 0; j < 16; j++) ls += bins[PADIDX(tid * 16 + j)];
    sarr[1023 - tid] = ls;
    __syncthreads();
    {   // inclusive block scan (reversed => suffix sums)
        unsigned int v = sarr[tid], sc = v;
        #pragma unroll
        for (int off = 1; off < 32; off <<= 1) {
            unsigned int t = __shfl_up_sync(0xffffffffu, sc, off);
            if (lane >= off) sc += t;
        }
        if (lane == 31) wsum[warp] = sc;
        __syncthreads();
        if (warp == 0) {
            unsigned int ws = wsum[lane];
            #pragma unroll
            for (int off = 1; off < 32; off <<= 1) {
                unsigned int t = __shfl_up_sync(0xffffffffu, ws, off);
                if (lane >= off) ws += t;
            }
            wsum[lane] = ws;
        }
        __syncthreads();
        sarr[tid] = sc + (warp ? wsum[warp - 1] : 0u);
    }
    __syncthreads();
    {
        unsigned int sincl = sarr[1023 - tid];
        unsigned int run = sincl - ls;
        #pragma unroll
        for (int j = 15; j >= 0; j--) {
            unsigned int c = bins[PADIDX(tid * 16 + j)];
            run += c;
            if (run >= PRE_K && run - c < PRE_K) sh_Tb = (unsigned)(tid * 16 + j);
            if (run >= FKTGT && run - c < FKTGT) { sh_Tbf = (unsigned)(tid * 16 + j); sh_fcnt = run; }
        }
    }
    __syncthreads();
    unsigned total = sarr[1023];
    unsigned fcpred = (total <= FKTGT) ? total : sh_fcnt;
    const unsigned int Tsb = (sh_Tb + BINBASE) << 12;
    const unsigned int Tf  = (((total <= FKTGT) ? 0u : sh_Tbf) + BINBASE) << 12;
    __syncthreads();   // bins dead from here; overlay region reusable

    // ---- B: single sweep of this batch's keys; dual compaction ----
    const unsigned long long* keys = g_keys + (size_t)b * NB;
    unsigned long long* sel = g_sel + (size_t)b * CAP;
    const bool do_fast = (fcpred <= FCAP);
    #pragma unroll
    for (int it = 0; it < 8; it++) {
        unsigned long long kk[4];
        #pragma unroll
        for (int u = 0; u < 4; u++) kk[u] = keys[it * 4096 + u * 1024 + tid];
        #pragma unroll
        for (int u = 0; u < 4; u++) {
            unsigned int sb = (unsigned int)(kk[u] >> 32);
            bool c = (sb >= Tsb);
            unsigned bal = __ballot_sync(0xffffffffu, c);
            if (bal) {
                int leader = __ffs(bal) - 1;
                unsigned int basep = 0;
                if (lane == leader) basep = atomicAdd(&s_sc, (unsigned)__popc(bal));
                basep = __shfl_sync(0xffffffffu, basep, leader);
                if (c) {
                    unsigned int pos = basep + (unsigned)__popc(bal & ((1u << lane) - 1u));
                    if (pos < CAP) sel[pos] = kk[u];
                }
            }
            if (do_fast) {
                bool cf = (sb >= Tf);
                unsigned balf = __ballot_sync(0xffffffffu, cf);
                if (balf) {
                    int leader = __ffs(balf) - 1;
                    unsigned int basep = 0;
                    if (lane == leader) basep = atomicAdd(&s_fc, (unsigned)__popc(balf));
                    basep = __shfl_sync(0xffffffffu, basep, leader);
                    if (cf) {
                        unsigned int pos = basep + (unsigned)__popc(balf & ((1u << lane) - 1u));
                        if (pos < FCAP) fcand[pos] = kk[u];
                    }
                }
            }
        }
    }
    __syncthreads();
    if (tid == 0) g_selcnt[b] = s_sc;
    if (!do_fast || s_fc > FCAP) {
        if (tid == 0) g_need_full[b] = 1u;
        return;
    }
    unsigned int cnt   = s_fc;
    unsigned int avail = s_sc; if (avail > CAP) avail = CAP;

    // ---- C: runtime-sized bitonic sort (descending), nsort = pow2 >= cnt ----
    int nsort = 64;
    while (nsort < (int)cnt) nsort <<= 1;       // <= 1024
    if (tid < nsort && tid >= (int)cnt) fcand[tid] = 0ULL;
    __syncthreads();

    if (tid < nsort) {
        unsigned long long v = fcand[tid];
        #pragma unroll
        for (int k = 2; k <= 32; k <<= 1) {
            #pragma unroll
            for (int j = k >> 1; j >= 1; j >>= 1) {
                unsigned long long o = __shfl_xor_sync(0xffffffffu, v, j);
                bool up    = ((tid & k) == 0);
                bool lower = ((tid & j) == 0);
                unsigned long long mx = v > o ? v : o;
                unsigned long long mn = v > o ? o : v;
                v = (up == lower) ? mx : mn;
            }
        }
        fcand[tid] = v;
    }
    __syncthreads();
    for (int k = 64; k <= nsort; k <<= 1) {
        for (int j = k >> 1; j >= 32; j >>= 1) {
            if (tid < nsort) {
                int l = tid ^ j;
                if (l > tid) {
                    unsigned long long a = fcand[tid], bb = fcand[l];
                    bool up = ((tid & k) == 0);
                    if ((a < bb) == up) { fcand[tid] = bb; fcand[l] = a; }
                }
            }
            __syncthreads();
        }
        if (tid < nsort) {
            unsigned long long v = fcand[tid];
            #pragma unroll
            for (int j = 16; j >= 1; j >>= 1) {
                unsigned long long o = __shfl_xor_sync(0xffffffffu, v, j);
                bool up    = ((tid & k) == 0);
                bool lower = ((tid & j) == 0);
                unsigned long long mx = v > o ? v : o;
                unsigned long long mn = v > o ? o : v;
                v = (up == lower) ? mx : mn;
            }
            fcand[tid] = v;
        }
        __syncthreads();
    }

    // ---- D: stage boxes/classes; zero matrix; class counters ----
    const float*         bxs  = boxes + (size_t)b * NB * 4;
    const unsigned char* cats = g_cat + (size_t)b * NB;
    {
        unsigned long long k = (tid < (int)cnt) ? fcand[tid] : 0ULL;
        if (k == 0ULL) {
            cls8[tid] = 0xFF;
            scand[tid] = make_float4(0.f, 0.f, 0.f, 0.f);
        } else {
            int idx = (NB - 1) - (int)(unsigned int)k;
            scand[tid] = *(const float4*)(bxs + (size_t)idx * 4);
            cls8[tid]  = cats[idx];
        }
    }
    #pragma unroll
    for (int u = tid; u < MROWS * MWORDS; u += 1024) M[u] = 0u;
    if (tid < NCLS) cpos[tid] = 0u;
    __syncthreads();

    const int lim = ((int)cnt < MROWS) ? (int)cnt : MROWS;

    if (tid < lim) atomicAdd(&cpos[cls8[tid]], 1u);
    __syncthreads();
    if (tid == 0) {
        unsigned run = 0;
        for (int c = 0; c < NCLS; c++) { coff[c] = (unsigned short)run; run += cpos[c]; }
        coff[NCLS] = (unsigned short)run;
    }
    __syncthreads();
    if (tid < NCLS) cpos[tid] = coff[tid];
    __syncthreads();
    if (tid < lim) {
        unsigned p = atomicAdd(&cpos[cls8[tid]], 1u);
        clist[p] = (unsigned short)tid;
    }
    __syncthreads();

    // ---- E: suppression matrix via class lists ----
    if (tid < lim) {
        const int r = tid;
        const int c = cls8[r];
        float4 br = scand[r];
        float arr = fmaxf(br.z - br.x, 0.f) * fmaxf(br.w - br.y, 0.f);
        const int e0 = coff[c], e1 = coff[c + 1];
        for (int e = e0; e < e1; e++) {
            int j = clist[e];
            if (j == r) continue;
            float4 bj = scand[j];
            float ix1 = fmaxf(br.x, bj.x);
            float iy1 = fmaxf(br.y, bj.y);
            float ix2 = fminf(br.z, bj.z);
            float iy2 = fminf(br.w, bj.w);
            float inter = fmaxf(ix2 - ix1, 0.f) * fmaxf(iy2 - iy1, 0.f);
            float aj = fmaxf(bj.z - bj.x, 0.f) * fmaxf(bj.w - bj.y, 0.f);
            float uni = arr + aj - inter;
            if (inter / fmaxf(uni, 1e-9f) > 0.5f)
                atomicOr(&M[r * MWORDS + (j >> 5)], 1u << (j & 31));
        }
    }
    __syncthreads();

    // ---- F: warp 0 greedy scan (ffs-driven) ----
    if (tid < 32) {
        unsigned sup = 0;
        int nk = 0;
        const int nwords = (lim + 31) >> 5;
        for (int w = 0; w < nwords; w++) {
            int remain = lim - (w << 5);
            unsigned valid = (remain >= 32) ? 0xFFFFFFFFu : ((1u << remain) - 1u);
            unsigned cur = __shfl_sync(0xffffffffu, sup, w);
            unsigned rem = ~cur & valid;
            while (rem) {
                int t = __ffs(rem) - 1;
                int i = (w << 5) + t;
                unsigned roww = M[i * MWORDS + w];
                if (lane < MWORDS) sup |= M[i * MWORDS + lane];
                if (lane == 0) kept_idx[nk] = (short)i;
                nk++;
                if (nk >= MAX_OUT) { rem = 0; break; }
                rem &= ~(roww | (1u << t));
            }
            if (nk >= MAX_OUT) break;
        }
        if (lane == 0) sh_nk = nk;
    }
    __syncthreads();

    const int nk = sh_nk;
    bool complete = (nk >= MAX_OUT) || ((int)cnt <= MROWS && cnt >= avail);
    if (complete) {
        float* out5 = out + (size_t)b * MAX_OUT * 5;
        float* ocat = out + (size_t)BATCHES * MAX_OUT * 5 + (size_t)b * MAX_OUT;
        if (tid < MAX_OUT) {
            int k0 = tid;
            float vx1 = 0, vy1 = 0, vx2 = 0, vy2 = 0, vs = 0, vc = 0;
            if (k0 < nk) {
                int i = kept_idx[k0];
                float4 bbv = scand[i];
                vx1 = bbv.x; vy1 = bbv.y; vx2 = bbv.z; vy2 = bbv.w;
                vs  = __uint_as_float((unsigned int)(fcand[i] >> 32));
                vc  = (float)cls8[i];
            }
            out5[k0 * 5 + 0] = vx1;
            out5[k0 * 5 + 1] = vy1;
            out5[k0 * 5 + 2] = vx2;
            out5[k0 * 5 + 3] = vy2;
            out5[k0 * 5 + 4] = vs;
            if (write_cats) ocat[k0] = vc;
        }
        if (tid == 0) g_need_full[b] = 0u;
    } else {
        if (tid == 0) g_need_full[b] = 1u;
    }
}

// ---------------- kernel 3: FULL fallback (flag-guarded) -------------------
// dyn smem: [0,32768) cand u64[4096]; [32768,65536) scand float4[2048];
//           [65536,69632) scls short[2048]
__global__ void __launch_bounds__(1024)
full_sortnms_kernel(const float* __restrict__ boxes, float* __restrict__ out, int write_cats) {
    extern __shared__ unsigned char dyn[];
    unsigned long long* cand  = (unsigned long long*)dyn;
    float4*             scand = (float4*)(dyn + 32768);
    short*              scls  = (short*)(dyn + 65536);

    __shared__ short kept_idx[MAX_OUT];
    __shared__ int   sh_nk;

    const int b = blockIdx.x;
    const int tid  = threadIdx.x;
    const int lane = tid & 31;

    if (!g_need_full[b]) return;

    unsigned int cnt = g_selcnt[b]; if (cnt > CAP) cnt = CAP;
    const unsigned long long* sel = g_sel + (size_t)b * CAP;
    #pragma unroll
    for (int s = 0; s < 4; s++) {
        int i = s * 1024 + tid;
        cand[i] = (i < (int)cnt) ? sel[i] : 0ULL;
    }
    __syncthreads();

    {
        unsigned long long v[4];
        #pragma unroll
        for (int s = 0; s < 4; s++) v[s] = cand[s * 1024 + tid];
        #pragma unroll
        for (int k = 2; k <= 32; k <<= 1) {
            #pragma unroll
            for (int j = k >> 1; j >= 1; j >>= 1) {
                #pragma unroll
                for (int s = 0; s < 4; s++) {
                    int i = s * 1024 + tid;
                    unsigned long long o = __shfl_xor_sync(0xffffffffu, v[s], j);
                    bool up    = ((i & k) == 0);
                    bool lower = ((i & j) == 0);
                    unsigned long long mx = v[s] > o ? v[s] : o;
                    unsigned long long mn = v[s] > o ? o : v[s];
                    v[s] = (up == lower) ? mx : mn;
                }
            }
        }
        #pragma unroll
        for (int s = 0; s < 4; s++) cand[s * 1024 + tid] = v[s];
    }
    __syncthreads();
    for (int k = 64; k <= CAP; k <<= 1) {
        for (int j = k >> 1; j >= 32; j >>= 1) {
            #pragma unroll
            for (int s0 = 0; s0 < CAP; s0 += 1024) {
                int i = s0 + tid;
                int l = i ^ j;
                if (l > i) {
                    unsigned long long a = cand[i], bb = cand[l];
                    bool up = ((i & k) == 0);
                    if ((a < bb) == up) { cand[i] = bb; cand[l] = a; }
                }
            }
            __syncthreads();
        }
        {
            unsigned long long v[4];
            #pragma unroll
            for (int s = 0; s < 4; s++) v[s] = cand[s * 1024 + tid];
            #pragma unroll
            for (int j = 16; j >= 1; j >>= 1) {
                #pragma unroll
                for (int s = 0; s < 4; s++) {
                    int i = s * 1024 + tid;
                    unsigned long long o = __shfl_xor_sync(0xffffffffu, v[s], j);
                    bool up    = ((i & k) == 0);
                    bool lower = ((i & j) == 0);
                    unsigned long long mx = v[s] > o ? v[s] : o;
                    unsigned long long mn = v[s] > o ? o : v[s];
                    v[s] = (up == lower) ? mx : mn;
                }
            }
            #pragma unroll
            for (int s = 0; s < 4; s++) cand[s * 1024 + tid] = v[s];
        }
        __syncthreads();
    }

    const float*         bxs  = boxes + (size_t)b * NB * 4;
    const unsigned char* cats = g_cat + (size_t)b * NB;
    for (int i = tid; i < PRE_K; i += 1024) {
        unsigned long long k = cand[i];
        if (k == 0ULL) {
            scls[i] = -1;
            scand[i] = make_float4(0.f, 0.f, 0.f, 0.f);
        } else {
            int idx = (NB - 1) - (int)(unsigned int)k;
            scand[i] = *(const float4*)(bxs + (size_t)idx * 4);
            scls[i]  = (short)cats[idx];
        }
    }
    __syncthreads();

    if (tid < 32) {
        int nk = run_nms_warp(scand, scls, kept_idx, PRE_K, lane);
        if (lane == 0) sh_nk = nk;
    }
    __syncthreads();

    const int nk = sh_nk;
    float* out5 = out + (size_t)b * MAX_OUT * 5;
    float* ocat = out + (size_t)BATCHES * MAX_OUT * 5 + (size_t)b * MAX_OUT;
    for (int k0 = tid; k0 < MAX_OUT; k0 += 1024) {
        float vx1 = 0, vy1 = 0, vx2 = 0, vy2 = 0, vs = 0, vc = 0;
        if (k0 < nk) {
            int i = kept_idx[k0];
            float4 bbv = scand[i];
            vx1 = bbv.x; vy1 = bbv.y; vx2 = bbv.z; vy2 = bbv.w;
            vs  = __uint_as_float((unsigned int)(cand[i] >> 32));
            vc  = (float)scls[i];
        }
        out5[k0 * 5 + 0] = vx1;
        out5[k0 * 5 + 1] = vy1;
        out5[k0 * 5 + 2] = vx2;
        out5[k0 * 5 + 3] = vy2;
        out5[k0 * 5 + 4] = vs;
        if (write_cats) ocat[k0] = vc;
    }
}

// ---------------- launch ----------------------------------------------------
extern "C" void kernel_launch(void* const* d_in, const int* in_sizes, int n_in,
                              void* d_out, int out_size) {
    const float* boxes = (const float*)d_in[0];
    const float* confs = (const float*)d_in[1];
    if (n_in >= 2 && in_sizes[0] > in_sizes[1]) {
        boxes = (const float*)d_in[1];
        confs = (const float*)d_in[0];
    }
    float* out = (float*)d_out;

    if (out_size != BATCHES * MAX_OUT * 6)
        cudaMemsetAsync(d_out, 0, (size_t)out_size * sizeof(float), 0);

    score_kernel<<<(BATCHES * NB) / SB_ANCH, SB_ANCH>>>(confs);

    int write_cats = (out_size >= BATCHES * MAX_OUT * 6) ? 1 : 0;

    cudaFuncSetAttribute(fused_kernel,
                         cudaFuncAttributeMaxDynamicSharedMemorySize, DYN_BYTES);
    fused_kernel<<<BATCHES, 1024, DYN_BYTES>>>(boxes, out, write_cats);

    cudaFuncSetAttribute(full_sortnms_kernel,
                         cudaFuncAttributeMaxDynamicSharedMemorySize, DYN_BYTES);
    full_sortnms_kernel<<<BATCHES, 1024, DYN_BYTES>>>(boxes, out, write_cats);
}

// round 12
// speedup vs baseline: 2.8284x; 1.0056x over previous
#include <cuda_runtime.h>
#include <cstdint>

#define BATCHES 8
#define NB      32768
#define NCLS    81
#define PRE_K   2048
#define FKTGT   256
#define FCAP    1024
#define CAP     4096
#define MAX_OUT 200
#define SB_ANCH 128
#define NTILES  4
#define TILE_ELEMS (SB_ANCH * NCLS)     /* 10368 floats = 41472 B */
#define NBINS   16384
#define BINBASE 0x3D4CCu          /* bits(0.05f) >> 12 */
#define PADIDX(i) ((i) + ((i) >> 4))
#define MROWS   384
#define MWORDS  12                /* 384/32 */
#define DYN_BYTES 69632           /* fused kernel: padded bins region */
#define SCORE_DYN (2 * TILE_ELEMS * 4)  /* 82944 B double buffer */

// ---------------- scratch (device globals) ---------------------------------
__device__ unsigned long long g_keys[BATCHES * NB];   // (score_bits<<32)|(NB-1-idx), 0 if invalid
__device__ unsigned char      g_cat [BATCHES * NB];   // argmax class
__device__ unsigned int       g_hist[BATCHES * NBINS];// per-batch histogram (self-zeroing)
__device__ unsigned int       g_selcnt[BATCHES];      // full-threshold selected count
__device__ unsigned int       g_need_full[BATCHES];   // 1 => fallback kernel must run
__device__ unsigned long long g_sel[BATCHES * CAP];   // full-threshold keys (unordered)

// ---------------- kernel 1: score/argmax, double-buffered TMA pipeline -----
__global__ void __launch_bounds__(SB_ANCH)
score_kernel(const float* __restrict__ confs) {
    extern __shared__ float sbuf[];                  // 2 × TILE_ELEMS
    __shared__ alignas(8) unsigned long long mbar[2];

    const unsigned bytes = TILE_ELEMS * 4;
    unsigned mb0 = (unsigned)__cvta_generic_to_shared(&mbar[0]);
    unsigned mb1 = (unsigned)__cvta_generic_to_shared(&mbar[1]);
    unsigned sb0 = (unsigned)__cvta_generic_to_shared(sbuf);
    unsigned sb1 = (unsigned)__cvta_generic_to_shared(sbuf + TILE_ELEMS);
    const int tile0 = blockIdx.x * NTILES;

    if (threadIdx.x == 0) {
        asm volatile("mbarrier.init.shared.b64 [%0], 1;" :: "r"(mb0) : "memory");
        asm volatile("mbarrier.init.shared.b64 [%0], 1;" :: "r"(mb1) : "memory");
    }
    __syncthreads();
    if (threadIdx.x == 0) {
        // prefetch tiles 0 and 1
        asm volatile("mbarrier.arrive.expect_tx.shared.b64 _, [%0], %1;"
                     :: "r"(mb0), "r"(bytes) : "memory");
        asm volatile("cp.async.bulk.shared::cta.global.mbarrier::complete_tx::bytes [%0], [%1], %2, [%3];"
                     :: "r"(sb0), "l"(confs + (size_t)(tile0 + 0) * TILE_ELEMS),
                        "r"(bytes), "r"(mb0) : "memory");
        asm volatile("mbarrier.arrive.expect_tx.shared.b64 _, [%0], %1;"
                     :: "r"(mb1), "r"(bytes) : "memory");
        asm volatile("cp.async.bulk.shared::cta.global.mbarrier::complete_tx::bytes [%0], [%1], %2, [%3];"
                     :: "r"(sb1), "l"(confs + (size_t)(tile0 + 1) * TILE_ELEMS),
                        "r"(bytes), "r"(mb1) : "memory");
    }

    #pragma unroll
    for (int t = 0; t < NTILES; t++) {
        const unsigned mba = (t & 1) ? mb1 : mb0;
        const unsigned par = (unsigned)((t >> 1) & 1);
        unsigned done = 0;
        do {
            asm volatile("{\n\t.reg .pred P;\n\t"
                         "mbarrier.try_wait.parity.acquire.cta.shared::cta.b64 P, [%1], %2, 0x989680;\n\t"
                         "selp.b32 %0, 1, 0, P;\n\t}"
                         : "=r"(done) : "r"(mba), "r"(par) : "memory");
        } while (!done);

        const float* row = sbuf + (t & 1) * TILE_ELEMS + threadIdx.x * NCLS;
        float m = -1.0f; int mi = 0;
        #pragma unroll
        for (int j = 0; j < NCLS; j++) {
            float v = row[j];
            if (v > m) { m = v; mi = j; }        // ascending j + '>' keeps first max
        }
        const int a = (tile0 + t) * SB_ANCH + threadIdx.x;
        bool valid = (m > 0.05f) && (mi != 0);
        unsigned int n = (unsigned int)a & (NB - 1);
        unsigned long long key = 0ULL;
        if (valid) {
            unsigned int sbv = __float_as_uint(m);
            key = (((unsigned long long)sbv) << 32) | (unsigned long long)(NB - 1u - n);
            unsigned int bucket = (sbv >> 12) - BINBASE;
            atomicAdd(&g_hist[(a >> 15) * NBINS + bucket], 1u);
        }
        g_keys[a] = key;
        g_cat[a]  = (unsigned char)mi;

        __syncthreads();                          // all reads of buf[t&1] done
        if (t + 2 < NTILES && threadIdx.x == 0) { // refill freed buffer
            const unsigned dsb = (t & 1) ? sb1 : sb0;
            asm volatile("mbarrier.arrive.expect_tx.shared.b64 _, [%0], %1;"
                         :: "r"(mba), "r"(bytes) : "memory");
            asm volatile("cp.async.bulk.shared::cta.global.mbarrier::complete_tx::bytes [%0], [%1], %2, [%3];"
                         :: "r"(dsb), "l"(confs + (size_t)(tile0 + t + 2) * TILE_ELEMS),
                            "r"(bytes), "r"(mba) : "memory");
        }
    }
}

// ---------------- shared NMS (slow path only) ------------------------------
__device__ __forceinline__ int run_nms_warp(const float4* scand, const short* scls,
                                            short* kept_idx, int lim, int lane) {
    float kx1[7], ky1[7], kx2[7], ky2[7], kar[7];
    short kcl[7];
    int nk = 0;
    for (int i = 0; i < lim && nk < MAX_OUT; i++) {
        short ci = scls[i];
        if (ci < 0) break;
        float4 bb = scand[i];
        float ar = fmaxf(bb.z - bb.x, 0.f) * fmaxf(bb.w - bb.y, 0.f);
        bool sup = false;
        const int ns = (nk + 31) >> 5;
        #pragma unroll
        for (int s = 0; s < 7; s++) {
            if (s >= ns) break;
            if ((s * 32 + lane) < nk && kcl[s] == ci) {
                float ix1 = fmaxf(bb.x, kx1[s]);
                float iy1 = fmaxf(bb.y, ky1[s]);
                float ix2 = fminf(bb.z, kx2[s]);
                float iy2 = fminf(bb.w, ky2[s]);
                float inter = fmaxf(ix2 - ix1, 0.f) * fmaxf(iy2 - iy1, 0.f);
                float uni   = ar + kar[s] - inter;
                if (inter / fmaxf(uni, 1e-9f) > 0.5f) sup = true;
            }
        }
        sup = __any_sync(0xffffffffu, sup);
        if (!sup) {
            int slot = nk >> 5;
            if ((nk & 31) == lane) {
                #pragma unroll
                for (int s = 0; s < 7; s++) {
                    if (slot == s) {
                        kx1[s] = bb.x; ky1[s] = bb.y;
                        kx2[s] = bb.z; ky2[s] = bb.w;
                        kar[s] = ar;   kcl[s] = ci;
                    }
                }
            }
            if (lane == 0) kept_idx[nk] = (short)i;
            nk++;
        }
    }
    return nk;
}

// ---------------- kernel 2: FUSED thresh + compact + sort + NMS ------------
// dyn smem phase A: bins (padded u32[NBINS + NBINS/16]) = 69632 B
// dyn smem phase B (overlay): [0,8192) fcand u64[1024]; [8192,24576) scand f4[1024];
//                             [24576,25600) cls8 u8[1024]; [25600,44032) M u32[384*12]
__global__ void __launch_bounds__(1024)
fused_kernel(const float* __restrict__ boxes, float* __restrict__ out, int write_cats) {
    extern __shared__ unsigned char dyn[];
    unsigned int*       bins  = (unsigned int*)dyn;
    unsigned long long* fcand = (unsigned long long*)dyn;
    float4*             scand = (float4*)(dyn + 8192);
    unsigned char*      cls8  = (unsigned char*)(dyn + 24576);
    unsigned int*       M     = (unsigned int*)(dyn + 25600);

    __shared__ unsigned int sarr[1024];
    __shared__ unsigned int wsum[32];
    __shared__ unsigned int sh_Tb, sh_Tbf, sh_fcnt;
    __shared__ unsigned int s_fc, s_sc;
    __shared__ unsigned short clist[MROWS];
    __shared__ unsigned short coff[NCLS + 1];
    __shared__ unsigned int   cpos[NCLS];
    __shared__ short  kept_idx[MAX_OUT];
    __shared__ int    sh_nk;

    const int b = blockIdx.x;
    const int tid  = threadIdx.x;
    const int lane = tid & 31;
    const int warp = tid >> 5;

    // ---- A: histogram -> thresholds (also self-zero g_hist) ----
    unsigned int* gh = g_hist + (size_t)b * NBINS;
    for (int i = tid; i < NBINS; i += 1024) {
        bins[PADIDX(i)] = gh[i];
        gh[i] = 0u;
    }
    if (tid == 0) { sh_Tb = 0; sh_Tbf = 0; sh_fcnt = 0; s_fc = 0; s_sc = 0; }
    __syncthreads();

    unsigned int ls = 0;
    #pragma unroll
    for (int j = 0; j < 16; j++) ls += bins[PADIDX(tid * 16 + j)];
    sarr[1023 - tid] = ls;
    __syncthreads();
    {   // inclusive block scan (reversed => suffix sums)
        unsigned int v = sarr[tid], sc = v;
        #pragma unroll
        for (int off = 1; off < 32; off <<= 1) {
            unsigned int t = __shfl_up_sync(0xffffffffu, sc, off);
            if (lane >= off) sc += t;
        }
        if (lane == 31) wsum[warp] = sc;
        __syncthreads();
        if (warp == 0) {
            unsigned int ws = wsum[lane];
            #pragma unroll
            for (int off = 1; off < 32; off <<= 1) {
                unsigned int t = __shfl_up_sync(0xffffffffu, ws, off);
                if (lane >= off) ws += t;
            }
            wsum[lane] = ws;
        }
        __syncthreads();
        sarr[tid] = sc + (warp ? wsum[warp - 1] : 0u);
    }
    __syncthreads();
    {
        unsigned int sincl = sarr[1023 - tid];
        unsigned int run = sincl - ls;
        #pragma unroll
        for (int j = 15; j >= 0; j--) {
            unsigned int c = bins[PADIDX(tid * 16 + j)];
            run += c;
            if (run >= PRE_K && run - c < PRE_K) sh_Tb = (unsigned)(tid * 16 + j);
            if (run >= FKTGT && run - c < FKTGT) { sh_Tbf = (unsigned)(tid * 16 + j); sh_fcnt = run; }
        }
    }
    __syncthreads();
    unsigned total = sarr[1023];
    unsigned fcpred = (total <= FKTGT) ? total : sh_fcnt;
    const unsigned int Tsb = (sh_Tb + BINBASE) << 12;
    const unsigned int Tf  = (((total <= FKTGT) ? 0u : sh_Tbf) + BINBASE) << 12;
    __syncthreads();   // bins dead from here; overlay region reusable

    // ---- B: single sweep of this batch's keys; dual compaction ----
    const unsigned long long* keys = g_keys + (size_t)b * NB;
    unsigned long long* sel = g_sel + (size_t)b * CAP;
    const bool do_fast = (fcpred <= FCAP);
    #pragma unroll
    for (int it = 0; it < 8; it++) {
        unsigned long long kk[4];
        #pragma unroll
        for (int u = 0; u < 4; u++) kk[u] = keys[it * 4096 + u * 1024 + tid];
        #pragma unroll
        for (int u = 0; u < 4; u++) {
            unsigned int sb = (unsigned int)(kk[u] >> 32);
            bool c = (sb >= Tsb);
            unsigned bal = __ballot_sync(0xffffffffu, c);
            if (bal) {
                int leader = __ffs(bal) - 1;
                unsigned int basep = 0;
                if (lane == leader) basep = atomicAdd(&s_sc, (unsigned)__popc(bal));
                basep = __shfl_sync(0xffffffffu, basep, leader);
                if (c) {
                    unsigned int pos = basep + (unsigned)__popc(bal & ((1u << lane) - 1u));
                    if (pos < CAP) sel[pos] = kk[u];
                }
            }
            if (do_fast) {
                bool cf = (sb >= Tf);
                unsigned balf = __ballot_sync(0xffffffffu, cf);
                if (balf) {
                    int leader = __ffs(balf) - 1;
                    unsigned int basep = 0;
                    if (lane == leader) basep = atomicAdd(&s_fc, (unsigned)__popc(balf));
                    basep = __shfl_sync(0xffffffffu, basep, leader);
                    if (cf) {
                        unsigned int pos = basep + (unsigned)__popc(balf & ((1u << lane) - 1u));
                        if (pos < FCAP) fcand[pos] = kk[u];
                    }
                }
            }
        }
    }
    __syncthreads();
    if (tid == 0) g_selcnt[b] = s_sc;
    if (!do_fast || s_fc > FCAP) {
        if (tid == 0) g_need_full[b] = 1u;
        return;
    }
    unsigned int cnt   = s_fc;
    unsigned int avail = s_sc; if (avail > CAP) avail = CAP;

    // ---- C: runtime-sized bitonic sort (descending), nsort = pow2 >= cnt ----
    int nsort = 64;
    while (nsort < (int)cnt) nsort <<= 1;       // <= 1024
    if (tid < nsort && tid >= (int)cnt) fcand[tid] = 0ULL;
    __syncthreads();

    if (tid < nsort) {
        unsigned long long v = fcand[tid];
        #pragma unroll
        for (int k = 2; k <= 32; k <<= 1) {
            #pragma unroll
            for (int j = k >> 1; j >= 1; j >>= 1) {
                unsigned long long o = __shfl_xor_sync(0xffffffffu, v, j);
                bool up    = ((tid & k) == 0);
                bool lower = ((tid & j) == 0);
                unsigned long long mx = v > o ? v : o;
                unsigned long long mn = v > o ? o : v;
                v = (up == lower) ? mx : mn;
            }
        }
        fcand[tid] = v;
    }
    __syncthreads();
    for (int k = 64; k <= nsort; k <<= 1) {
        for (int j = k >> 1; j >= 32; j >>= 1) {
            if (tid < nsort) {
                int l = tid ^ j;
                if (l > tid) {
                    unsigned long long a = fcand[tid], bb = fcand[l];
                    bool up = ((tid & k) == 0);
                    if ((a < bb) == up) { fcand[tid] = bb; fcand[l] = a; }
                }
            }
            __syncthreads();
        }
        if (tid < nsort) {
            unsigned long long v = fcand[tid];
            #pragma unroll
            for (int j = 16; j >= 1; j >>= 1) {
                unsigned long long o = __shfl_xor_sync(0xffffffffu, v, j);
                bool up    = ((tid & k) == 0);
                bool lower = ((tid & j) == 0);
                unsigned long long mx = v > o ? v : o;
                unsigned long long mn = v > o ? o : v;
                v = (up == lower) ? mx : mn;
            }
            fcand[tid] = v;
        }
        __syncthreads();
    }

    // ---- D: stage boxes/classes; zero matrix; class counters ----
    const float*         bxs  = boxes + (size_t)b * NB * 4;
    const unsigned char* cats = g_cat + (size_t)b * NB;
    {
        unsigned long long k = (tid < (int)cnt) ? fcand[tid] : 0ULL;
        if (k == 0ULL) {
            cls8[tid] = 0xFF;
            scand[tid] = make_float4(0.f, 0.f, 0.f, 0.f);
        } else {
            int idx = (NB - 1) - (int)(unsigned int)k;
            scand[tid] = *(const float4*)(bxs + (size_t)idx * 4);
            cls8[tid]  = cats[idx];
        }
    }
    #pragma unroll
    for (int u = tid; u < MROWS * MWORDS; u += 1024) M[u] = 0u;
    if (tid < NCLS) cpos[tid] = 0u;
    __syncthreads();

    const int lim = ((int)cnt < MROWS) ? (int)cnt : MROWS;

    if (tid < lim) atomicAdd(&cpos[cls8[tid]], 1u);
    __syncthreads();
    if (tid == 0) {
        unsigned run = 0;
        for (int c = 0; c < NCLS; c++) { coff[c] = (unsigned short)run; run += cpos[c]; }
        coff[NCLS] = (unsigned short)run;
    }
    __syncthreads();
    if (tid < NCLS) cpos[tid] = coff[tid];
    __syncthreads();
    if (tid < lim) {
        unsigned p = atomicAdd(&cpos[cls8[tid]], 1u);
        clist[p] = (unsigned short)tid;
    }
    __syncthreads();

    // ---- E: suppression matrix via class lists ----
    if (tid < lim) {
        const int r = tid;
        const int c = cls8[r];
        float4 br = scand[r];
        float arr = fmaxf(br.z - br.x, 0.f) * fmaxf(br.w - br.y, 0.f);
        const int e0 = coff[c], e1 = coff[c + 1];
        for (int e = e0; e < e1; e++) {
            int j = clist[e];
            if (j == r) continue;
            float4 bj = scand[j];
            float ix1 = fmaxf(br.x, bj.x);
            float iy1 = fmaxf(br.y, bj.y);
            float ix2 = fminf(br.z, bj.z);
            float iy2 = fminf(br.w, bj.w);
            float inter = fmaxf(ix2 - ix1, 0.f) * fmaxf(iy2 - iy1, 0.f);
            float aj = fmaxf(bj.z - bj.x, 0.f) * fmaxf(bj.w - bj.y, 0.f);
            float uni = arr + aj - inter;
            if (inter / fmaxf(uni, 1e-9f) > 0.5f)
                atomicOr(&M[r * MWORDS + (j >> 5)], 1u << (j & 31));
        }
    }
    __syncthreads();

    // ---- F: warp 0 greedy scan (ffs-driven) ----
    if (tid < 32) {
        unsigned sup = 0;
        int nk = 0;
        const int nwords = (lim + 31) >> 5;
        for (int w = 0; w < nwords; w++) {
            int remain = lim - (w << 5);
            unsigned valid = (remain >= 32) ? 0xFFFFFFFFu : ((1u << remain) - 1u);
            unsigned cur = __shfl_sync(0xffffffffu, sup, w);
            unsigned rem = ~cur & valid;
            while (rem) {
                int t = __ffs(rem) - 1;
                int i = (w << 5) + t;
                unsigned roww = M[i * MWORDS + w];
                if (lane < MWORDS) sup |= M[i * MWORDS + lane];
                if (lane == 0) kept_idx[nk] = (short)i;
                nk++;
                if (nk >= MAX_OUT) { rem = 0; break; }
                rem &= ~(roww | (1u << t));
            }
            if (nk >= MAX_OUT) break;
        }
        if (lane == 0) sh_nk = nk;
    }
    __syncthreads();

    const int nk = sh_nk;
    bool complete = (nk >= MAX_OUT) || ((int)cnt <= MROWS && cnt >= avail);
    if (complete) {
        float* out5 = out + (size_t)b * MAX_OUT * 5;
        float* ocat = out + (size_t)BATCHES * MAX_OUT * 5 + (size_t)b * MAX_OUT;
        if (tid < MAX_OUT) {
            int k0 = tid;
            float vx1 = 0, vy1 = 0, vx2 = 0, vy2 = 0, vs = 0, vc = 0;
            if (k0 < nk) {
                int i = kept_idx[k0];
                float4 bbv = scand[i];
                vx1 = bbv.x; vy1 = bbv.y; vx2 = bbv.z; vy2 = bbv.w;
                vs  = __uint_as_float((unsigned int)(fcand[i] >> 32));
                vc  = (float)cls8[i];
            }
            out5[k0 * 5 + 0] = vx1;
            out5[k0 * 5 + 1] = vy1;
            out5[k0 * 5 + 2] = vx2;
            out5[k0 * 5 + 3] = vy2;
            out5[k0 * 5 + 4] = vs;
            if (write_cats) ocat[k0] = vc;
        }
        if (tid == 0) g_need_full[b] = 0u;
    } else {
        if (tid == 0) g_need_full[b] = 1u;
    }
}

// ---------------- kernel 3: FULL fallback (flag-guarded) -------------------
// dyn smem: [0,32768) cand u64[4096]; [32768,65536) scand float4[2048];
//           [65536,69632) scls short[2048]
__global__ void __launch_bounds__(1024)
full_sortnms_kernel(const float* __restrict__ boxes, float* __restrict__ out, int write_cats) {
    extern __shared__ unsigned char dyn[];
    unsigned long long* cand  = (unsigned long long*)dyn;
    float4*             scand = (float4*)(dyn + 32768);
    short*              scls  = (short*)(dyn + 65536);

    __shared__ short kept_idx[MAX_OUT];
    __shared__ int   sh_nk;

    const int b = blockIdx.x;
    const int tid  = threadIdx.x;
    const int lane = tid & 31;

    if (!g_need_full[b]) return;

    unsigned int cnt = g_selcnt[b]; if (cnt > CAP) cnt = CAP;
    const unsigned long long* sel = g_sel + (size_t)b * CAP;
    #pragma unroll
    for (int s = 0; s < 4; s++) {
        int i = s * 1024 + tid;
        cand[i] = (i < (int)cnt) ? sel[i] : 0ULL;
    }
    __syncthreads();

    {
        unsigned long long v[4];
        #pragma unroll
        for (int s = 0; s < 4; s++) v[s] = cand[s * 1024 + tid];
        #pragma unroll
        for (int k = 2; k <= 32; k <<= 1) {
            #pragma unroll
            for (int j = k >> 1; j >= 1; j >>= 1) {
                #pragma unroll
                for (int s = 0; s < 4; s++) {
                    int i = s * 1024 + tid;
                    unsigned long long o = __shfl_xor_sync(0xffffffffu, v[s], j);
                    bool up    = ((i & k) == 0);
                    bool lower = ((i & j) == 0);
                    unsigned long long mx = v[s] > o ? v[s] : o;
                    unsigned long long mn = v[s] > o ? o : v[s];
                    v[s] = (up == lower) ? mx : mn;
                }
            }
        }
        #pragma unroll
        for (int s = 0; s < 4; s++) cand[s * 1024 + tid] = v[s];
    }
    __syncthreads();
    for (int k = 64; k <= CAP; k <<= 1) {
        for (int j = k >> 1; j >= 32; j >>= 1) {
            #pragma unroll
            for (int s0 = 0; s0 < CAP; s0 += 1024) {
                int i = s0 + tid;
                int l = i ^ j;
                if (l > i) {
                    unsigned long long a = cand[i], bb = cand[l];
                    bool up = ((i & k) == 0);
                    if ((a < bb) == up) { cand[i] = bb; cand[l] = a; }
                }
            }
            __syncthreads();
        }
        {
            unsigned long long v[4];
            #pragma unroll
            for (int s = 0; s < 4; s++) v[s] = cand[s * 1024 + tid];
            #pragma unroll
            for (int j = 16; j >= 1; j >>= 1) {
                #pragma unroll
                for (int s = 0; s < 4; s++) {
                    int i = s * 1024 + tid;
                    unsigned long long o = __shfl_xor_sync(0xffffffffu, v[s], j);
                    bool up    = ((i & k) == 0);
                    bool lower = ((i & j) == 0);
                    unsigned long long mx = v[s] > o ? v[s] : o;
                    unsigned long long mn = v[s] > o ? o : v[s];
                    v[s] = (up == lower) ? mx : mn;
                }
            }
            #pragma unroll
            for (int s = 0; s < 4; s++) cand[s * 1024 + tid] = v[s];
        }
        __syncthreads();
    }

    const float*         bxs  = boxes + (size_t)b * NB * 4;
    const unsigned char* cats = g_cat + (size_t)b * NB;
    for (int i = tid; i < PRE_K; i += 1024) {
        unsigned long long k = cand[i];
        if (k == 0ULL) {
            scls[i] = -1;
            scand[i] = make_float4(0.f, 0.f, 0.f, 0.f);
        } else {
            int idx = (NB - 1) - (int)(unsigned int)k;
            scand[i] = *(const float4*)(bxs + (size_t)idx * 4);
            scls[i]  = (short)cats[idx];
        }
    }
    __syncthreads();

    if (tid < 32) {
        int nk = run_nms_warp(scand, scls, kept_idx, PRE_K, lane);
        if (lane == 0) sh_nk = nk;
    }
    __syncthreads();

    const int nk = sh_nk;
    float* out5 = out + (size_t)b * MAX_OUT * 5;
    float* ocat = out + (size_t)BATCHES * MAX_OUT * 5 + (size_t)b * MAX_OUT;
    for (int k0 = tid; k0 < MAX_OUT; k0 += 1024) {
        float vx1 = 0, vy1 = 0, vx2 = 0, vy2 = 0, vs = 0, vc = 0;
        if (k0 < nk) {
            int i = kept_idx[k0];
            float4 bbv = scand[i];
            vx1 = bbv.x; vy1 = bbv.y; vx2 = bbv.z; vy2 = bbv.w;
            vs  = __uint_as_float((unsigned int)(cand[i] >> 32));
            vc  = (float)scls[i];
        }
        out5[k0 * 5 + 0] = vx1;
        out5[k0 * 5 + 1] = vy1;
        out5[k0 * 5 + 2] = vx2;
        out5[k0 * 5 + 3] = vy2;
        out5[k0 * 5 + 4] = vs;
        if (write_cats) ocat[k0] = vc;
    }
}

// ---------------- launch ----------------------------------------------------
extern "C" void kernel_launch(void* const* d_in, const int* in_sizes, int n_in,
                              void* d_out, int out_size) {
    const float* boxes = (const float*)d_in[0];
    const float* confs = (const float*)d_in[1];
    if (n_in >= 2 && in_sizes[0] > in_sizes[1]) {
        boxes = (const float*)d_in[1];
        confs = (const float*)d_in[0];
    }
    float* out = (float*)d_out;

    if (out_size != BATCHES * MAX_OUT * 6)
        cudaMemsetAsync(d_out, 0, (size_t)out_size * sizeof(float), 0);

    cudaFuncSetAttribute(score_kernel,
                         cudaFuncAttributeMaxDynamicSharedMemorySize, SCORE_DYN);
    score_kernel<<<(BATCHES * NB) / (SB_ANCH * NTILES), SB_ANCH, SCORE_DYN>>>(confs);

    int write_cats = (out_size >= BATCHES * MAX_OUT * 6) ? 1 : 0;

    cudaFuncSetAttribute(fused_kernel,
                         cudaFuncAttributeMaxDynamicSharedMemorySize, DYN_BYTES);
    fused_kernel<<<BATCHES, 1024, DYN_BYTES>>>(boxes, out, write_cats);

    cudaFuncSetAttribute(full_sortnms_kernel,
                         cudaFuncAttributeMaxDynamicSharedMemorySize, DYN_BYTES);
    full_sortnms_kernel<<<BATCHES, 1024, DYN_BYTES>>>(boxes, out, write_cats);
}

// round 13
// speedup vs baseline: 3.2114x; 1.1354x over previous
#include <cuda_runtime.h>
#include <cstdint>

#define BATCHES 8
#define NB      32768
#define NCLS    81
#define PRE_K   2048
#define FKTGT   256
#define FCAP    1024
#define CAP     4096
#define MAX_OUT 200
#define SB_ANCH 128
#define NTILES  4
#define TILE_ELEMS (SB_ANCH * NCLS)     /* 10368 floats = 41472 B */
#define NBINS   9024                    /* covers buckets 0..9012; mult of 32 */
#define WALKCH  (NBINS / 32)            /* 282 chunks */
#define BINBASE 0x3D4CCu                /* bits(0.05f) >> 12 */
#define MROWS   384
#define MWORDS  12                      /* 384/32 */
#define FUSED_DYN 44032                 /* fcand 8K + scand 16K + cls8 1K + M 18K */
#define FULL_DYN  69632                 /* cand 32K + scand 32K + scls 4K */
#define SCORE_DYN (2 * TILE_ELEMS * 4)  /* 82944 B double buffer */

// ---------------- scratch (device globals) ---------------------------------
__device__ unsigned long long g_keys[BATCHES * NB];   // (score_bits<<32)|(NB-1-idx), 0 if invalid
__device__ unsigned char      g_cat [BATCHES * NB];   // argmax class
__device__ unsigned int       g_hist[BATCHES * NBINS];// per-batch histogram (memset per replay)
__device__ unsigned int       g_thresh[BATCHES];      // full threshold bits (for fallback)
__device__ unsigned int       g_need_full[BATCHES];   // 1 => fallback kernel must run

// ---------------- kernel 1: score/argmax, double-buffered TMA pipeline -----
__global__ void __launch_bounds__(SB_ANCH)
score_kernel(const float* __restrict__ confs) {
    extern __shared__ float sbuf[];                  // 2 × TILE_ELEMS
    __shared__ alignas(8) unsigned long long mbar[2];

    const unsigned bytes = TILE_ELEMS * 4;
    unsigned mb0 = (unsigned)__cvta_generic_to_shared(&mbar[0]);
    unsigned mb1 = (unsigned)__cvta_generic_to_shared(&mbar[1]);
    unsigned sb0 = (unsigned)__cvta_generic_to_shared(sbuf);
    unsigned sb1 = (unsigned)__cvta_generic_to_shared(sbuf + TILE_ELEMS);
    const int tile0 = blockIdx.x * NTILES;

    if (threadIdx.x == 0) {
        asm volatile("mbarrier.init.shared.b64 [%0], 1;" :: "r"(mb0) : "memory");
        asm volatile("mbarrier.init.shared.b64 [%0], 1;" :: "r"(mb1) : "memory");
    }
    __syncthreads();
    if (threadIdx.x == 0) {
        asm volatile("mbarrier.arrive.expect_tx.shared.b64 _, [%0], %1;"
                     :: "r"(mb0), "r"(bytes) : "memory");
        asm volatile("cp.async.bulk.shared::cta.global.mbarrier::complete_tx::bytes [%0], [%1], %2, [%3];"
                     :: "r"(sb0), "l"(confs + (size_t)(tile0 + 0) * TILE_ELEMS),
                        "r"(bytes), "r"(mb0) : "memory");
        asm volatile("mbarrier.arrive.expect_tx.shared.b64 _, [%0], %1;"
                     :: "r"(mb1), "r"(bytes) : "memory");
        asm volatile("cp.async.bulk.shared::cta.global.mbarrier::complete_tx::bytes [%0], [%1], %2, [%3];"
                     :: "r"(sb1), "l"(confs + (size_t)(tile0 + 1) * TILE_ELEMS),
                        "r"(bytes), "r"(mb1) : "memory");
    }

    #pragma unroll
    for (int t = 0; t < NTILES; t++) {
        const unsigned mba = (t & 1) ? mb1 : mb0;
        const unsigned par = (unsigned)((t >> 1) & 1);
        unsigned done = 0;
        do {
            asm volatile("{\n\t.reg .pred P;\n\t"
                         "mbarrier.try_wait.parity.acquire.cta.shared::cta.b64 P, [%1], %2, 0x989680;\n\t"
                         "selp.b32 %0, 1, 0, P;\n\t}"
                         : "=r"(done) : "r"(mba), "r"(par) : "memory");
        } while (!done);

        const float* row = sbuf + (t & 1) * TILE_ELEMS + threadIdx.x * NCLS;
        float m = -1.0f; int mi = 0;
        #pragma unroll
        for (int j = 0; j < NCLS; j++) {
            float v = row[j];
            if (v > m) { m = v; mi = j; }        // ascending j + '>' keeps first max
        }
        const int a = (tile0 + t) * SB_ANCH + threadIdx.x;
        bool valid = (m > 0.05f) && (mi != 0);
        unsigned int n = (unsigned int)a & (NB - 1);
        unsigned long long key = 0ULL;
        if (valid) {
            unsigned int sbv = __float_as_uint(m);
            key = (((unsigned long long)sbv) << 32) | (unsigned long long)(NB - 1u - n);
            unsigned int bucket = (sbv >> 12) - BINBASE;   // < 9013
            atomicAdd(&g_hist[(a >> 15) * NBINS + bucket], 1u);
        }
        g_keys[a] = key;
        g_cat[a]  = (unsigned char)mi;

        __syncthreads();
        if (t + 2 < NTILES && threadIdx.x == 0) {
            const unsigned dsb = (t & 1) ? sb1 : sb0;
            asm volatile("mbarrier.arrive.expect_tx.shared.b64 _, [%0], %1;"
                         :: "r"(mba), "r"(bytes) : "memory");
            asm volatile("cp.async.bulk.shared::cta.global.mbarrier::complete_tx::bytes [%0], [%1], %2, [%3];"
                         :: "r"(dsb), "l"(confs + (size_t)(tile0 + t + 2) * TILE_ELEMS),
                            "r"(bytes), "r"(mba) : "memory");
        }
    }
}

// ---------------- shared NMS (slow path only) ------------------------------
__device__ __forceinline__ int run_nms_warp(const float4* scand, const short* scls,
                                            short* kept_idx, int lim, int lane) {
    float kx1[7], ky1[7], kx2[7], ky2[7], kar[7];
    short kcl[7];
    int nk = 0;
    for (int i = 0; i < lim && nk < MAX_OUT; i++) {
        short ci = scls[i];
        if (ci < 0) break;
        float4 bb = scand[i];
        float ar = fmaxf(bb.z - bb.x, 0.f) * fmaxf(bb.w - bb.y, 0.f);
        bool sup = false;
        const int ns = (nk + 31) >> 5;
        #pragma unroll
        for (int s = 0; s < 7; s++) {
            if (s >= ns) break;
            if ((s * 32 + lane) < nk && kcl[s] == ci) {
                float ix1 = fmaxf(bb.x, kx1[s]);
                float iy1 = fmaxf(bb.y, ky1[s]);
                float ix2 = fminf(bb.z, kx2[s]);
                float iy2 = fminf(bb.w, ky2[s]);
                float inter = fmaxf(ix2 - ix1, 0.f) * fmaxf(iy2 - iy1, 0.f);
                float uni   = ar + kar[s] - inter;
                if (inter / fmaxf(uni, 1e-9f) > 0.5f) sup = true;
            }
        }
        sup = __any_sync(0xffffffffu, sup);
        if (!sup) {
            int slot = nk >> 5;
            if ((nk & 31) == lane) {
                #pragma unroll
                for (int s = 0; s < 7; s++) {
                    if (slot == s) {
                        kx1[s] = bb.x; ky1[s] = bb.y;
                        kx2[s] = bb.z; ky2[s] = bb.w;
                        kar[s] = ar;   kcl[s] = ci;
                    }
                }
            }
            if (lane == 0) kept_idx[nk] = (short)i;
            nk++;
        }
    }
    return nk;
}

// ---------------- kernel 2: FUSED walk + compact + sort + NMS --------------
// dyn smem: [0,8192) fcand u64[1024]; [8192,24576) scand f4[1024];
//           [24576,25600) cls8 u8[1024]; [25600,44032) M u32[384*12]
__global__ void __launch_bounds__(1024)
fused_kernel(const float* __restrict__ boxes, float* __restrict__ out, int write_cats) {
    extern __shared__ unsigned char dyn[];
    unsigned long long* fcand = (unsigned long long*)dyn;
    float4*             scand = (float4*)(dyn + 8192);
    unsigned char*      cls8  = (unsigned char*)(dyn + 24576);
    unsigned int*       M     = (unsigned int*)(dyn + 25600);

    __shared__ unsigned int s_Tb, s_Tbf, s_scnt, s_fcnt, s_fc;
    __shared__ unsigned short clist[MROWS];
    __shared__ unsigned short coff[NCLS + 1];
    __shared__ unsigned int   cpos[NCLS];
    __shared__ short  kept_idx[MAX_OUT];
    __shared__ int    sh_nk;

    const int b = blockIdx.x;
    const int tid  = threadIdx.x;
    const int lane = tid & 31;
    const int warp = tid >> 5;

    if (tid == 0) s_fc = 0;

    // ---- A: warp-0 histogram walk from the top (exact thresholds+counts) ----
    if (warp == 0) {
        const unsigned int* gh = g_hist + (size_t)b * NBINS;
        unsigned run = 0;
        int foundf = 0, founds = 0;
        unsigned Tbf = 0, fcnt = 0, Tb = 0, scnt = 0;
        for (int c = 0; c < WALKCH; c++) {
            int bin = NBINS - 1 - c * 32 - lane;   // lane 0 = highest bin of chunk
            unsigned v = gh[bin];
            unsigned p = v;
            #pragma unroll
            for (int off = 1; off < 32; off <<= 1) {
                unsigned t = __shfl_up_sync(0xffffffffu, p, off);
                if (lane >= off) p += t;
            }
            unsigned cum = run + p;                // suffix count down to this bin
            if (!foundf) {
                unsigned cr = __ballot_sync(0xffffffffu, cum >= FKTGT && cum - v < FKTGT);
                if (cr) {
                    int src = __ffs(cr) - 1;
                    Tbf  = __shfl_sync(0xffffffffu, (unsigned)bin, src);
                    fcnt = __shfl_sync(0xffffffffu, cum, src);
                    foundf = 1;
                }
            }
            if (!founds) {
                unsigned cr = __ballot_sync(0xffffffffu, cum >= PRE_K && cum - v < PRE_K);
                if (cr) {
                    int src = __ffs(cr) - 1;
                    Tb   = __shfl_sync(0xffffffffu, (unsigned)bin, src);
                    scnt = __shfl_sync(0xffffffffu, cum, src);
                    founds = 1;
                }
            }
            run = __shfl_sync(0xffffffffu, cum, 31);
            if (founds) break;
        }
        if (!foundf) { Tbf = 0; fcnt = run; }
        if (!founds) { Tb = 0;  scnt = run; }
        if (lane == 0) { s_Tb = Tb; s_Tbf = Tbf; s_scnt = scnt; s_fcnt = fcnt; }
    }
    __syncthreads();

    const unsigned int Tsb = (s_Tb + BINBASE) << 12;
    const unsigned int Tf  = (s_Tbf + BINBASE) << 12;
    const unsigned int fcnt = s_fcnt;
    const unsigned int scnt = s_scnt;
    if (tid == 0) g_thresh[b] = Tsb;
    if (fcnt > FCAP) {
        if (tid == 0) g_need_full[b] = 1u;
        return;
    }

    // ---- B: single sweep, fast-threshold compaction only ----
    const unsigned long long* keys = g_keys + (size_t)b * NB;
    #pragma unroll
    for (int it = 0; it < 8; it++) {
        unsigned long long kk[4];
        #pragma unroll
        for (int u = 0; u < 4; u++) kk[u] = keys[it * 4096 + u * 1024 + tid];
        #pragma unroll
        for (int u = 0; u < 4; u++) {
            unsigned int sb = (unsigned int)(kk[u] >> 32);
            bool cf = (sb >= Tf);
            unsigned balf = __ballot_sync(0xffffffffu, cf);
            if (balf) {
                int leader = __ffs(balf) - 1;
                unsigned int basep = 0;
                if (lane == leader) basep = atomicAdd(&s_fc, (unsigned)__popc(balf));
                basep = __shfl_sync(0xffffffffu, basep, leader);
                if (cf) {
                    unsigned int pos = basep + (unsigned)__popc(balf & ((1u << lane) - 1u));
                    if (pos < FCAP) fcand[pos] = kk[u];
                }
            }
        }
    }
    __syncthreads();
    unsigned int cnt = s_fc; if (cnt > FCAP) cnt = FCAP;

    // ---- C: runtime-sized bitonic sort (descending) ----
    int nsort = 64;
    while (nsort < (int)cnt) nsort <<= 1;       // <= 1024
    if (tid < nsort && tid >= (int)cnt) fcand[tid] = 0ULL;
    __syncthreads();

    if (tid < nsort) {
        unsigned long long v = fcand[tid];
        #pragma unroll
        for (int k = 2; k <= 32; k <<= 1) {
            #pragma unroll
            for (int j = k >> 1; j >= 1; j >>= 1) {
                unsigned long long o = __shfl_xor_sync(0xffffffffu, v, j);
                bool up    = ((tid & k) == 0);
                bool lower = ((tid & j) == 0);
                unsigned long long mx = v > o ? v : o;
                unsigned long long mn = v > o ? o : v;
                v = (up == lower) ? mx : mn;
            }
        }
        fcand[tid] = v;
    }
    __syncthreads();
    for (int k = 64; k <= nsort; k <<= 1) {
        for (int j = k >> 1; j >= 32; j >>= 1) {
            if (tid < nsort) {
                int l = tid ^ j;
                if (l > tid) {
                    unsigned long long a = fcand[tid], bb = fcand[l];
                    bool up = ((tid & k) == 0);
                    if ((a < bb) == up) { fcand[tid] = bb; fcand[l] = a; }
                }
            }
            __syncthreads();
        }
        if (tid < nsort) {
            unsigned long long v = fcand[tid];
            #pragma unroll
            for (int j = 16; j >= 1; j >>= 1) {
                unsigned long long o = __shfl_xor_sync(0xffffffffu, v, j);
                bool up    = ((tid & k) == 0);
                bool lower = ((tid & j) == 0);
                unsigned long long mx = v > o ? v : o;
                unsigned long long mn = v > o ? o : v;
                v = (up == lower) ? mx : mn;
            }
            fcand[tid] = v;
        }
        __syncthreads();
    }

    // ---- D: stage boxes/classes; zero matrix; class counters ----
    const float*         bxs  = boxes + (size_t)b * NB * 4;
    const unsigned char* cats = g_cat + (size_t)b * NB;
    {
        unsigned long long k = (tid < (int)cnt) ? fcand[tid] : 0ULL;
        if (k == 0ULL) {
            cls8[tid] = 0xFF;
            scand[tid] = make_float4(0.f, 0.f, 0.f, 0.f);
        } else {
            int idx = (NB - 1) - (int)(unsigned int)k;
            scand[tid] = *(const float4*)(bxs + (size_t)idx * 4);
            cls8[tid]  = cats[idx];
        }
    }
    #pragma unroll
    for (int u = tid; u < MROWS * MWORDS; u += 1024) M[u] = 0u;
    if (tid < NCLS) cpos[tid] = 0u;
    __syncthreads();

    const int lim = ((int)cnt < MROWS) ? (int)cnt : MROWS;

    if (tid < lim) atomicAdd(&cpos[cls8[tid]], 1u);
    __syncthreads();
    if (tid == 0) {
        unsigned run = 0;
        for (int c = 0; c < NCLS; c++) { coff[c] = (unsigned short)run; run += cpos[c]; }
        coff[NCLS] = (unsigned short)run;
    }
    __syncthreads();
    if (tid < NCLS) cpos[tid] = coff[tid];
    __syncthreads();
    if (tid < lim) {
        unsigned p = atomicAdd(&cpos[cls8[tid]], 1u);
        clist[p] = (unsigned short)tid;
    }
    __syncthreads();

    // ---- E: suppression matrix via class lists ----
    if (tid < lim) {
        const int r = tid;
        const int c = cls8[r];
        float4 br = scand[r];
        float arr = fmaxf(br.z - br.x, 0.f) * fmaxf(br.w - br.y, 0.f);
        const int e0 = coff[c], e1 = coff[c + 1];
        for (int e = e0; e < e1; e++) {
            int j = clist[e];
            if (j == r) continue;
            float4 bj = scand[j];
            float ix1 = fmaxf(br.x, bj.x);
            float iy1 = fmaxf(br.y, bj.y);
            float ix2 = fminf(br.z, bj.z);
            float iy2 = fminf(br.w, bj.w);
            float inter = fmaxf(ix2 - ix1, 0.f) * fmaxf(iy2 - iy1, 0.f);
            float aj = fmaxf(bj.z - bj.x, 0.f) * fmaxf(bj.w - bj.y, 0.f);
            float uni = arr + aj - inter;
            if (inter / fmaxf(uni, 1e-9f) > 0.5f)
                atomicOr(&M[r * MWORDS + (j >> 5)], 1u << (j & 31));
        }
    }
    __syncthreads();

    // ---- F: warp 0 greedy scan (ffs-driven) ----
    if (tid < 32) {
        unsigned sup = 0;
        int nk = 0;
        const int nwords = (lim + 31) >> 5;
        for (int w = 0; w < nwords; w++) {
            int remain = lim - (w << 5);
            unsigned valid = (remain >= 32) ? 0xFFFFFFFFu : ((1u << remain) - 1u);
            unsigned cur = __shfl_sync(0xffffffffu, sup, w);
            unsigned rem = ~cur & valid;
            while (rem) {
                int t = __ffs(rem) - 1;
                int i = (w << 5) + t;
                unsigned roww = M[i * MWORDS + w];
                if (lane < MWORDS) sup |= M[i * MWORDS + lane];
                if (lane == 0) kept_idx[nk] = (short)i;
                nk++;
                if (nk >= MAX_OUT) { rem = 0; break; }
                rem &= ~(roww | (1u << t));
            }
            if (nk >= MAX_OUT) break;
        }
        if (lane == 0) sh_nk = nk;
    }
    __syncthreads();

    const int nk = sh_nk;
    bool complete = (nk >= MAX_OUT) || ((int)cnt <= MROWS && cnt >= scnt);
    if (complete) {
        float* out5 = out + (size_t)b * MAX_OUT * 5;
        float* ocat = out + (size_t)BATCHES * MAX_OUT * 5 + (size_t)b * MAX_OUT;
        if (tid < MAX_OUT) {
            int k0 = tid;
            float vx1 = 0, vy1 = 0, vx2 = 0, vy2 = 0, vs = 0, vc = 0;
            if (k0 < nk) {
                int i = kept_idx[k0];
                float4 bbv = scand[i];
                vx1 = bbv.x; vy1 = bbv.y; vx2 = bbv.z; vy2 = bbv.w;
                vs  = __uint_as_float((unsigned int)(fcand[i] >> 32));
                vc  = (float)cls8[i];
            }
            out5[k0 * 5 + 0] = vx1;
            out5[k0 * 5 + 1] = vy1;
            out5[k0 * 5 + 2] = vx2;
            out5[k0 * 5 + 3] = vy2;
            out5[k0 * 5 + 4] = vs;
            if (write_cats) ocat[k0] = vc;
        }
        if (tid == 0) g_need_full[b] = 0u;
    } else {
        if (tid == 0) g_need_full[b] = 1u;
    }
}

// ---------------- kernel 3: FULL fallback (flag-guarded, sweeps keys) ------
// dyn smem: [0,32768) cand u64[4096]; [32768,65536) scand float4[2048];
//           [65536,69632) scls short[2048]
__global__ void __launch_bounds__(1024)
full_sortnms_kernel(const float* __restrict__ boxes, float* __restrict__ out, int write_cats) {
    extern __shared__ unsigned char dyn[];
    unsigned long long* cand  = (unsigned long long*)dyn;
    float4*             scand = (float4*)(dyn + 32768);
    short*              scls  = (short*)(dyn + 65536);

    __shared__ short kept_idx[MAX_OUT];
    __shared__ int   sh_nk;
    __shared__ unsigned int s_cnt;

    const int b = blockIdx.x;
    const int tid  = threadIdx.x;
    const int lane = tid & 31;

    if (!g_need_full[b]) return;

    const unsigned int Tsb = g_thresh[b];
    const unsigned long long* keys = g_keys + (size_t)b * NB;
    if (tid == 0) s_cnt = 0;
    __syncthreads();

    // compaction sweep (full threshold) into smem
    #pragma unroll
    for (int it = 0; it < 8; it++) {
        unsigned long long kk[4];
        #pragma unroll
        for (int u = 0; u < 4; u++) kk[u] = keys[it * 4096 + u * 1024 + tid];
        #pragma unroll
        for (int u = 0; u < 4; u++) {
            unsigned int sb = (unsigned int)(kk[u] >> 32);
            bool c = (sb >= Tsb);
            unsigned bal = __ballot_sync(0xffffffffu, c);
            if (bal) {
                int leader = __ffs(bal) - 1;
                unsigned int basep = 0;
                if (lane == leader) basep = atomicAdd(&s_cnt, (unsigned)__popc(bal));
                basep = __shfl_sync(0xffffffffu, basep, leader);
                if (c) {
                    unsigned int pos = basep + (unsigned)__popc(bal & ((1u << lane) - 1u));
                    if (pos < CAP) cand[pos] = kk[u];
                }
            }
        }
    }
    __syncthreads();
    unsigned int cnt = s_cnt; if (cnt > CAP) cnt = CAP;
    #pragma unroll
    for (int s = 0; s < 4; s++) {
        int i = s * 1024 + tid;
        if (i >= (int)cnt) cand[i] = 0ULL;
    }
    __syncthreads();

    // hybrid bitonic sort (descending), n = 4096
    {
        unsigned long long v[4];
        #pragma unroll
        for (int s = 0; s < 4; s++) v[s] = cand[s * 1024 + tid];
        #pragma unroll
        for (int k = 2; k <= 32; k <<= 1) {
            #pragma unroll
            for (int j = k >> 1; j >= 1; j >>= 1) {
                #pragma unroll
                for (int s = 0; s < 4; s++) {
                    int i = s * 1024 + tid;
                    unsigned long long o = __shfl_xor_sync(0xffffffffu, v[s], j);
                    bool up    = ((i & k) == 0);
                    bool lower = ((i & j) == 0);
                    unsigned long long mx = v[s] > o ? v[s] : o;
                    unsigned long long mn = v[s] > o ? o : v[s];
                    v[s] = (up == lower) ? mx : mn;
                }
            }
        }
        #pragma unroll
        for (int s = 0; s < 4; s++) cand[s * 1024 + tid] = v[s];
    }
    __syncthreads();
    for (int k = 64; k <= CAP; k <<= 1) {
        for (int j = k >> 1; j >= 32; j >>= 1) {
            #pragma unroll
            for (int s0 = 0; s0 < CAP; s0 += 1024) {
                int i = s0 + tid;
                int l = i ^ j;
                if (l > i) {
                    unsigned long long a = cand[i], bb = cand[l];
                    bool up = ((i & k) == 0);
                    if ((a < bb) == up) { cand[i] = bb; cand[l] = a; }
                }
            }
            __syncthreads();
        }
        {
            unsigned long long v[4];
            #pragma unroll
            for (int s = 0; s < 4; s++) v[s] = cand[s * 1024 + tid];
            #pragma unroll
            for (int j = 16; j >= 1; j >>= 1) {
                #pragma unroll
                for (int s = 0; s < 4; s++) {
                    int i = s * 1024 + tid;
                    unsigned long long o = __shfl_xor_sync(0xffffffffu, v[s], j);
                    bool up    = ((i & k) == 0);
                    bool lower = ((i & j) == 0);
                    unsigned long long mx = v[s] > o ? v[s] : o;
                    unsigned long long mn = v[s] > o ? o : v[s];
                    v[s] = (up == lower) ? mx : mn;
                }
            }
            #pragma unroll
            for (int s = 0; s < 4; s++) cand[s * 1024 + tid] = v[s];
        }
        __syncthreads();
    }

    const float*         bxs  = boxes + (size_t)b * NB * 4;
    const unsigned char* cats = g_cat + (size_t)b * NB;
    for (int i = tid; i < PRE_K; i += 1024) {
        unsigned long long k = cand[i];
        if (k == 0ULL) {
            scls[i] = -1;
            scand[i] = make_float4(0.f, 0.f, 0.f, 0.f);
        } else {
            int idx = (NB - 1) - (int)(unsigned int)k;
            scand[i] = *(const float4*)(bxs + (size_t)idx * 4);
            scls[i]  = (short)cats[idx];
        }
    }
    __syncthreads();

    if (tid < 32) {
        int nk = run_nms_warp(scand, scls, kept_idx, PRE_K, lane);
        if (lane == 0) sh_nk = nk;
    }
    __syncthreads();

    const int nk = sh_nk;
    float* out5 = out + (size_t)b * MAX_OUT * 5;
    float* ocat = out + (size_t)BATCHES * MAX_OUT * 5 + (size_t)b * MAX_OUT;
    for (int k0 = tid; k0 < MAX_OUT; k0 += 1024) {
        float vx1 = 0, vy1 = 0, vx2 = 0, vy2 = 0, vs = 0, vc = 0;
        if (k0 < nk) {
            int i = kept_idx[k0];
            float4 bbv = scand[i];
            vx1 = bbv.x; vy1 = bbv.y; vx2 = bbv.z; vy2 = bbv.w;
            vs  = __uint_as_float((unsigned int)(cand[i] >> 32));
            vc  = (float)scls[i];
        }
        out5[k0 * 5 + 0] = vx1;
        out5[k0 * 5 + 1] = vy1;
        out5[k0 * 5 + 2] = vx2;
        out5[k0 * 5 + 3] = vy2;
        out5[k0 * 5 + 4] = vs;
        if (write_cats) ocat[k0] = vc;
    }
}

// ---------------- launch ----------------------------------------------------
extern "C" void kernel_launch(void* const* d_in, const int* in_sizes, int n_in,
                              void* d_out, int out_size) {
    const float* boxes = (const float*)d_in[0];
    const float* confs = (const float*)d_in[1];
    if (n_in >= 2 && in_sizes[0] > in_sizes[1]) {
        boxes = (const float*)d_in[1];
        confs = (const float*)d_in[0];
    }
    float* out = (float*)d_out;

    if (out_size != BATCHES * MAX_OUT * 6)
        cudaMemsetAsync(d_out, 0, (size_t)out_size * sizeof(float), 0);

    void* hp = nullptr;
    cudaGetSymbolAddress(&hp, g_hist);
    cudaMemsetAsync(hp, 0, sizeof(unsigned int) * BATCHES * NBINS, 0);

    cudaFuncSetAttribute(score_kernel,
                         cudaFuncAttributeMaxDynamicSharedMemorySize, SCORE_DYN);
    score_kernel<<<(BATCHES * NB) / (SB_ANCH * NTILES), SB_ANCH, SCORE_DYN>>>(confs);

    int write_cats = (out_size >= BATCHES * MAX_OUT * 6) ? 1 : 0;

    cudaFuncSetAttribute(fused_kernel,
                         cudaFuncAttributeMaxDynamicSharedMemorySize, FUSED_DYN);
    fused_kernel<<<BATCHES, 1024, FUSED_DYN>>>(boxes, out, write_cats);

    cudaFuncSetAttribute(full_sortnms_kernel,
                         cudaFuncAttributeMaxDynamicSharedMemorySize, FULL_DYN);
    full_sortnms_kernel<<<BATCHES, 1024, FULL_DYN>>>(boxes, out, write_cats);
}

// round 14
// speedup vs baseline: 3.3214x; 1.0343x over previous
#include <cuda_runtime.h>
#include <cstdint>

#define BATCHES 8
#define NB      32768
#define NCLS    81
#define PRE_K   2048
#define FKTGT   256
#define FCAP    1024
#define CAP     4096
#define MAX_OUT 200
#define SB_ANCH 128
#define NTILES  4
#define TILE_ELEMS (SB_ANCH * NCLS)     /* 10368 floats = 41472 B */
#define NBINS   9024                    /* covers buckets 0..9012; mult of 32 */
#define WALKCH  (NBINS / 32)            /* 282 chunks */
#define BINBASE 0x3D4CCu                /* bits(0.05f) >> 12 */
#define MROWS   384
#define MWORDS  12                      /* 384/32 */
#define FUSED_DYN 69632                 /* max(fast 44032, full 69632) */
#define SCORE_DYN (2 * TILE_ELEMS * 4)  /* 82944 B double buffer */

// ---------------- scratch (device globals) ---------------------------------
__device__ unsigned long long g_keys[BATCHES * NB];   // (score_bits<<32)|(NB-1-idx), 0 if invalid
__device__ unsigned char      g_cat [BATCHES * NB];   // argmax class
__device__ unsigned int      g_hist[BATCHES * NBINS]; // per-batch histogram (zeroed by fused)

// ---------------- kernel 1: score/argmax, double-buffered TMA pipeline -----
__global__ void __launch_bounds__(SB_ANCH)
score_kernel(const float* __restrict__ confs) {
    extern __shared__ float sbuf[];                  // 2 × TILE_ELEMS
    __shared__ alignas(8) unsigned long long mbar[2];

    const unsigned bytes = TILE_ELEMS * 4;
    unsigned mb0 = (unsigned)__cvta_generic_to_shared(&mbar[0]);
    unsigned mb1 = (unsigned)__cvta_generic_to_shared(&mbar[1]);
    unsigned sb0 = (unsigned)__cvta_generic_to_shared(sbuf);
    unsigned sb1 = (unsigned)__cvta_generic_to_shared(sbuf + TILE_ELEMS);
    const int tile0 = blockIdx.x * NTILES;

    if (threadIdx.x == 0) {
        asm volatile("mbarrier.init.shared.b64 [%0], 1;" :: "r"(mb0) : "memory");
        asm volatile("mbarrier.init.shared.b64 [%0], 1;" :: "r"(mb1) : "memory");
    }
    __syncthreads();
    if (threadIdx.x == 0) {
        asm volatile("mbarrier.arrive.expect_tx.shared.b64 _, [%0], %1;"
                     :: "r"(mb0), "r"(bytes) : "memory");
        asm volatile("cp.async.bulk.shared::cta.global.mbarrier::complete_tx::bytes [%0], [%1], %2, [%3];"
                     :: "r"(sb0), "l"(confs + (size_t)(tile0 + 0) * TILE_ELEMS),
                        "r"(bytes), "r"(mb0) : "memory");
        asm volatile("mbarrier.arrive.expect_tx.shared.b64 _, [%0], %1;"
                     :: "r"(mb1), "r"(bytes) : "memory");
        asm volatile("cp.async.bulk.shared::cta.global.mbarrier::complete_tx::bytes [%0], [%1], %2, [%3];"
                     :: "r"(sb1), "l"(confs + (size_t)(tile0 + 1) * TILE_ELEMS),
                        "r"(bytes), "r"(mb1) : "memory");
    }

    #pragma unroll
    for (int t = 0; t < NTILES; t++) {
        const unsigned mba = (t & 1) ? mb1 : mb0;
        const unsigned par = (unsigned)((t >> 1) & 1);
        unsigned done = 0;
        do {
            asm volatile("{\n\t.reg .pred P;\n\t"
                         "mbarrier.try_wait.parity.acquire.cta.shared::cta.b64 P, [%1], %2, 0x989680;\n\t"
                         "selp.b32 %0, 1, 0, P;\n\t}"
                         : "=r"(done) : "r"(mba), "r"(par) : "memory");
        } while (!done);

        const float* row = sbuf + (t & 1) * TILE_ELEMS + threadIdx.x * NCLS;
        float m = -1.0f; int mi = 0;
        #pragma unroll
        for (int j = 0; j < NCLS; j++) {
            float v = row[j];
            if (v > m) { m = v; mi = j; }        // ascending j + '>' keeps first max
        }
        const int a = (tile0 + t) * SB_ANCH + threadIdx.x;
        bool valid = (m > 0.05f) && (mi != 0);
        unsigned int n = (unsigned int)a & (NB - 1);
        unsigned long long key = 0ULL;
        if (valid) {
            unsigned int sbv = __float_as_uint(m);
            key = (((unsigned long long)sbv) << 32) | (unsigned long long)(NB - 1u - n);
            unsigned int bucket = (sbv >> 12) - BINBASE;   // < 9013
            atomicAdd(&g_hist[(a >> 15) * NBINS + bucket], 1u);
        }
        g_keys[a] = key;
        g_cat[a]  = (unsigned char)mi;

        __syncthreads();
        if (t + 2 < NTILES && threadIdx.x == 0) {
            const unsigned dsb = (t & 1) ? sb1 : sb0;
            asm volatile("mbarrier.arrive.expect_tx.shared.b64 _, [%0], %1;"
                         :: "r"(mba), "r"(bytes) : "memory");
            asm volatile("cp.async.bulk.shared::cta.global.mbarrier::complete_tx::bytes [%0], [%1], %2, [%3];"
                         :: "r"(dsb), "l"(confs + (size_t)(tile0 + t + 2) * TILE_ELEMS),
                            "r"(bytes), "r"(mba) : "memory");
        }
    }
}

// ---------------- full-path NMS (warp-serial; slow path only) --------------
__device__ __forceinline__ int run_nms_warp(const float4* scand, const short* scls,
                                            short* kept_idx, int lim, int lane) {
    float kx1[7], ky1[7], kx2[7], ky2[7], kar[7];
    short kcl[7];
    int nk = 0;
    for (int i = 0; i < lim && nk < MAX_OUT; i++) {
        short ci = scls[i];
        if (ci < 0) break;
        float4 bb = scand[i];
        float ar = fmaxf(bb.z - bb.x, 0.f) * fmaxf(bb.w - bb.y, 0.f);
        bool sup = false;
        const int ns = (nk + 31) >> 5;
        #pragma unroll
        for (int s = 0; s < 7; s++) {
            if (s >= ns) break;
            if ((s * 32 + lane) < nk && kcl[s] == ci) {
                float ix1 = fmaxf(bb.x, kx1[s]);
                float iy1 = fmaxf(bb.y, ky1[s]);
                float ix2 = fminf(bb.z, kx2[s]);
                float iy2 = fminf(bb.w, ky2[s]);
                float inter = fmaxf(ix2 - ix1, 0.f) * fmaxf(iy2 - iy1, 0.f);
                float uni   = ar + kar[s] - inter;
                if (inter / fmaxf(uni, 1e-9f) > 0.5f) sup = true;
            }
        }
        sup = __any_sync(0xffffffffu, sup);
        if (!sup) {
            int slot = nk >> 5;
            if ((nk & 31) == lane) {
                #pragma unroll
                for (int s = 0; s < 7; s++) {
                    if (slot == s) {
                        kx1[s] = bb.x; ky1[s] = bb.y;
                        kx2[s] = bb.z; ky2[s] = bb.w;
                        kar[s] = ar;   kcl[s] = ci;
                    }
                }
            }
            if (lane == 0) kept_idx[nk] = (short)i;
            nk++;
        }
    }
    return nk;
}

// ---------------- kernel 2: FUSED everything (fast path + inline fallback) -
// fast layout:  [0,8192) fcand u64[1024]; [8192,24576) scand f4[1024];
//               [24576,25600) cls8 u8[1024]; [25600,44032) M u32[384*12]
// full layout:  [0,32768) cand u64[4096]; [32768,65536) scand2 f4[2048];
//               [65536,69632) scls2 short[2048]
__global__ void __launch_bounds__(1024)
fused_kernel(const float* __restrict__ boxes, float* __restrict__ out, int write_cats) {
    extern __shared__ unsigned char dyn[];
    unsigned long long* fcand = (unsigned long long*)dyn;
    float4*             scand = (float4*)(dyn + 8192);
    unsigned char*      cls8  = (unsigned char*)(dyn + 24576);
    unsigned int*       M     = (unsigned int*)(dyn + 25600);
    unsigned long long* cand   = (unsigned long long*)dyn;
    float4*             scand2 = (float4*)(dyn + 32768);
    short*              scls2  = (short*)(dyn + 65536);

    __shared__ unsigned int s_Tb, s_Tbf, s_scnt, s_fcnt, s_fc, s_cnt2;
    __shared__ int s_fullpath;
    __shared__ unsigned short clist[MROWS];
    __shared__ unsigned short coff[NCLS + 1];
    __shared__ unsigned int   cpos[NCLS];
    __shared__ short  kept_idx[MAX_OUT];
    __shared__ int    sh_nk;

    const int b = blockIdx.x;
    const int tid  = threadIdx.x;
    const int lane = tid & 31;
    const int warp = tid >> 5;

    if (tid == 0) { s_fc = 0; s_fullpath = 0; }

    // ---- A: warp-0 histogram walk from the top (exact thresholds+counts) ----
    unsigned int* gh = g_hist + (size_t)b * NBINS;
    if (warp == 0) {
        unsigned run = 0;
        int foundf = 0, founds = 0;
        unsigned Tbf = 0, fcv = 0, Tb = 0, scv = 0;
        for (int c = 0; c < WALKCH; c++) {
            int bin = NBINS - 1 - c * 32 - lane;
            unsigned v = gh[bin];
            unsigned p = v;
            #pragma unroll
            for (int off = 1; off < 32; off <<= 1) {
                unsigned t = __shfl_up_sync(0xffffffffu, p, off);
                if (lane >= off) p += t;
            }
            unsigned cum = run + p;
            if (!foundf) {
                unsigned cr = __ballot_sync(0xffffffffu, cum >= FKTGT && cum - v < FKTGT);
                if (cr) {
                    int src = __ffs(cr) - 1;
                    Tbf = __shfl_sync(0xffffffffu, (unsigned)bin, src);
                    fcv = __shfl_sync(0xffffffffu, cum, src);
                    foundf = 1;
                }
            }
            if (!founds) {
                unsigned cr = __ballot_sync(0xffffffffu, cum >= PRE_K && cum - v < PRE_K);
                if (cr) {
                    int src = __ffs(cr) - 1;
                    Tb  = __shfl_sync(0xffffffffu, (unsigned)bin, src);
                    scv = __shfl_sync(0xffffffffu, cum, src);
                    founds = 1;
                }
            }
            run = __shfl_sync(0xffffffffu, cum, 31);
            if (founds) break;
        }
        if (!foundf) { Tbf = 0; fcv = run; }
        if (!founds) { Tb = 0;  scv = run; }
        if (lane == 0) { s_Tb = Tb; s_Tbf = Tbf; s_scnt = scv; s_fcnt = fcv; }
    }
    __syncthreads();

    // zero this batch's histogram for the next graph replay (after all reads)
    for (int i = tid; i < NBINS; i += 1024) gh[i] = 0u;

    const unsigned int Tsb = (s_Tb + BINBASE) << 12;
    const unsigned int Tf  = (s_Tbf + BINBASE) << 12;
    const unsigned int fcnt = s_fcnt;
    const unsigned int scnt = s_scnt;
    const unsigned long long* keys = g_keys + (size_t)b * NB;
    const float*         bxs  = boxes + (size_t)b * NB * 4;
    const unsigned char* cats = g_cat + (size_t)b * NB;
    float* out5 = out + (size_t)b * MAX_OUT * 5;
    float* ocat = out + (size_t)BATCHES * MAX_OUT * 5 + (size_t)b * MAX_OUT;

    if (fcnt <= FCAP) {
        // ================= FAST PATH =================
        // ---- B: single sweep, fast-threshold compaction into smem ----
        #pragma unroll
        for (int it = 0; it < 8; it++) {
            unsigned long long kk[4];
            #pragma unroll
            for (int u = 0; u < 4; u++) kk[u] = keys[it * 4096 + u * 1024 + tid];
            #pragma unroll
            for (int u = 0; u < 4; u++) {
                unsigned int sb = (unsigned int)(kk[u] >> 32);
                bool cf = (sb >= Tf);
                unsigned balf = __ballot_sync(0xffffffffu, cf);
                if (balf) {
                    int leader = __ffs(balf) - 1;
                    unsigned int basep = 0;
                    if (lane == leader) basep = atomicAdd(&s_fc, (unsigned)__popc(balf));
                    basep = __shfl_sync(0xffffffffu, basep, leader);
                    if (cf) {
                        unsigned int pos = basep + (unsigned)__popc(balf & ((1u << lane) - 1u));
                        if (pos < FCAP) fcand[pos] = kk[u];
                    }
                }
            }
        }
        __syncthreads();
        unsigned int cnt = s_fc; if (cnt > FCAP) cnt = FCAP;

        // ---- C: runtime-sized bitonic sort (descending) ----
        int nsort = 64;
        while (nsort < (int)cnt) nsort <<= 1;       // <= 1024
        if (tid < nsort && tid >= (int)cnt) fcand[tid] = 0ULL;
        __syncthreads();

        if (tid < nsort) {
            unsigned long long v = fcand[tid];
            #pragma unroll
            for (int k = 2; k <= 32; k <<= 1) {
                #pragma unroll
                for (int j = k >> 1; j >= 1; j >>= 1) {
                    unsigned long long o = __shfl_xor_sync(0xffffffffu, v, j);
                    bool up    = ((tid & k) == 0);
                    bool lower = ((tid & j) == 0);
                    unsigned long long mx = v > o ? v : o;
                    unsigned long long mn = v > o ? o : v;
                    v = (up == lower) ? mx : mn;
                }
            }
            fcand[tid] = v;
        }
        __syncthreads();
        for (int k = 64; k <= nsort; k <<= 1) {
            for (int j = k >> 1; j >= 32; j >>= 1) {
                if (tid < nsort) {
                    int l = tid ^ j;
                    if (l > tid) {
                        unsigned long long a = fcand[tid], bb = fcand[l];
                        bool up = ((tid & k) == 0);
                        if ((a < bb) == up) { fcand[tid] = bb; fcand[l] = a; }
                    }
                }
                __syncthreads();
            }
            if (tid < nsort) {
                unsigned long long v = fcand[tid];
                #pragma unroll
                for (int j = 16; j >= 1; j >>= 1) {
                    unsigned long long o = __shfl_xor_sync(0xffffffffu, v, j);
                    bool up    = ((tid & k) == 0);
                    bool lower = ((tid & j) == 0);
                    unsigned long long mx = v > o ? v : o;
                    unsigned long long mn = v > o ? o : v;
                    v = (up == lower) ? mx : mn;
                }
                fcand[tid] = v;
            }
            __syncthreads();
        }

        // ---- D: stage boxes/classes; zero matrix; class counters ----
        {
            unsigned long long k = (tid < (int)cnt) ? fcand[tid] : 0ULL;
            if (k == 0ULL) {
                cls8[tid] = 0xFF;
                scand[tid] = make_float4(0.f, 0.f, 0.f, 0.f);
            } else {
                int idx = (NB - 1) - (int)(unsigned int)k;
                scand[tid] = *(const float4*)(bxs + (size_t)idx * 4);
                cls8[tid]  = cats[idx];
            }
        }
        #pragma unroll
        for (int u = tid; u < MROWS * MWORDS; u += 1024) M[u] = 0u;
        if (tid < NCLS) cpos[tid] = 0u;
        __syncthreads();

        const int lim = ((int)cnt < MROWS) ? (int)cnt : MROWS;

        if (tid < lim) atomicAdd(&cpos[cls8[tid]], 1u);
        __syncthreads();
        if (tid == 0) {
            unsigned run = 0;
            for (int c = 0; c < NCLS; c++) { coff[c] = (unsigned short)run; run += cpos[c]; }
            coff[NCLS] = (unsigned short)run;
        }
        __syncthreads();
        if (tid < NCLS) cpos[tid] = coff[tid];
        __syncthreads();
        if (tid < lim) {
            unsigned p = atomicAdd(&cpos[cls8[tid]], 1u);
            clist[p] = (unsigned short)tid;
        }
        __syncthreads();

        // ---- E: suppression matrix via class lists ----
        if (tid < lim) {
            const int r = tid;
            const int c = cls8[r];
            float4 br = scand[r];
            float arr = fmaxf(br.z - br.x, 0.f) * fmaxf(br.w - br.y, 0.f);
            const int e0 = coff[c], e1 = coff[c + 1];
            for (int e = e0; e < e1; e++) {
                int j = clist[e];
                if (j == r) continue;
                float4 bj = scand[j];
                float ix1 = fmaxf(br.x, bj.x);
                float iy1 = fmaxf(br.y, bj.y);
                float ix2 = fminf(br.z, bj.z);
                float iy2 = fminf(br.w, bj.w);
                float inter = fmaxf(ix2 - ix1, 0.f) * fmaxf(iy2 - iy1, 0.f);
                float aj = fmaxf(bj.z - bj.x, 0.f) * fmaxf(bj.w - bj.y, 0.f);
                float uni = arr + aj - inter;
                if (inter / fmaxf(uni, 1e-9f) > 0.5f)
                    atomicOr(&M[r * MWORDS + (j >> 5)], 1u << (j & 31));
            }
        }
        __syncthreads();

        // ---- F: warp 0 greedy scan (ffs-driven, shfl-preloaded row word) ----
        if (tid < 32) {
            unsigned sup = 0;
            int nk = 0;
            const int nwords = (lim + 31) >> 5;
            for (int w = 0; w < nwords; w++) {
                int remain = lim - (w << 5);
                unsigned valid = (remain >= 32) ? 0xFFFFFFFFu : ((1u << remain) - 1u);
                unsigned rw = M[((w << 5) + lane) * MWORDS + w];  // row (32w+lane), word w
                unsigned cur = __shfl_sync(0xffffffffu, sup, w);
                unsigned rem = ~cur & valid;
                while (rem) {
                    int t = __ffs(rem) - 1;
                    int i = (w << 5) + t;
                    unsigned roww = __shfl_sync(0xffffffffu, rw, t); // critical path: shfl
                    if (lane < MWORDS) sup |= M[i * MWORDS + lane]; // off critical path
                    if (lane == 0) kept_idx[nk] = (short)i;
                    nk++;
                    if (nk >= MAX_OUT) { rem = 0; break; }
                    rem &= ~(roww | (1u << t));
                }
                if (nk >= MAX_OUT) break;
            }
            if (lane == 0) sh_nk = nk;
        }
        __syncthreads();

        const int nk = sh_nk;
        bool complete = (nk >= MAX_OUT) || ((int)cnt <= MROWS && cnt >= scnt);
        if (complete) {
            if (tid < MAX_OUT) {
                int k0 = tid;
                float vx1 = 0, vy1 = 0, vx2 = 0, vy2 = 0, vs = 0, vc = 0;
                if (k0 < nk) {
                    int i = kept_idx[k0];
                    float4 bbv = scand[i];
                    vx1 = bbv.x; vy1 = bbv.y; vx2 = bbv.z; vy2 = bbv.w;
                    vs  = __uint_as_float((unsigned int)(fcand[i] >> 32));
                    vc  = (float)cls8[i];
                }
                out5[k0 * 5 + 0] = vx1;
                out5[k0 * 5 + 1] = vy1;
                out5[k0 * 5 + 2] = vx2;
                out5[k0 * 5 + 3] = vy2;
                out5[k0 * 5 + 4] = vs;
                if (write_cats) ocat[k0] = vc;
            }
            return;
        }
        if (tid == 0) s_fullpath = 1;
    }
    __syncthreads();
    if (!s_fullpath && fcnt <= FCAP) return;   // (unreachable; uniform guard)

    // ================= FULL PATH (inline fallback) =================
    if (tid == 0) s_cnt2 = 0;
    __syncthreads();

    #pragma unroll
    for (int it = 0; it < 8; it++) {
        unsigned long long kk[4];
        #pragma unroll
        for (int u = 0; u < 4; u++) kk[u] = keys[it * 4096 + u * 1024 + tid];
        #pragma unroll
        for (int u = 0; u < 4; u++) {
            unsigned int sb = (unsigned int)(kk[u] >> 32);
            bool c = (sb >= Tsb);
            unsigned bal = __ballot_sync(0xffffffffu, c);
            if (bal) {
                int leader = __ffs(bal) - 1;
                unsigned int basep = 0;
                if (lane == leader) basep = atomicAdd(&s_cnt2, (unsigned)__popc(bal));
                basep = __shfl_sync(0xffffffffu, basep, leader);
                if (c) {
                    unsigned int pos = basep + (unsigned)__popc(bal & ((1u << lane) - 1u));
                    if (pos < CAP) cand[pos] = kk[u];
                }
            }
        }
    }
    __syncthreads();
    unsigned int cnt2 = s_cnt2; if (cnt2 > CAP) cnt2 = CAP;
    #pragma unroll
    for (int s = 0; s < 4; s++) {
        int i = s * 1024 + tid;
        if (i >= (int)cnt2) cand[i] = 0ULL;
    }
    __syncthreads();

    // hybrid bitonic sort (descending), n = 4096
    {
        unsigned long long v[4];
        #pragma unroll
        for (int s = 0; s < 4; s++) v[s] = cand[s * 1024 + tid];
        #pragma unroll
        for (int k = 2; k <= 32; k <<= 1) {
            #pragma unroll
            for (int j = k >> 1; j >= 1; j >>= 1) {
                #pragma unroll
                for (int s = 0; s < 4; s++) {
                    int i = s * 1024 + tid;
                    unsigned long long o = __shfl_xor_sync(0xffffffffu, v[s], j);
                    bool up    = ((i & k) == 0);
                    bool lower = ((i & j) == 0);
                    unsigned long long mx = v[s] > o ? v[s] : o;
                    unsigned long long mn = v[s] > o ? o : v[s];
                    v[s] = (up == lower) ? mx : mn;
                }
            }
        }
        #pragma unroll
        for (int s = 0; s < 4; s++) cand[s * 1024 + tid] = v[s];
    }
    __syncthreads();
    for (int k = 64; k <= CAP; k <<= 1) {
        for (int j = k >> 1; j >= 32; j >>= 1) {
            #pragma unroll
            for (int s0 = 0; s0 < CAP; s0 += 1024) {
                int i = s0 + tid;
                int l = i ^ j;
                if (l > i) {
                    unsigned long long a = cand[i], bb = cand[l];
                    bool up = ((i & k) == 0);
                    if ((a < bb) == up) { cand[i] = bb; cand[l] = a; }
                }
            }
            __syncthreads();
        }
        {
            unsigned long long v[4];
            #pragma unroll
            for (int s = 0; s < 4; s++) v[s] = cand[s * 1024 + tid];
            #pragma unroll
            for (int j = 16; j >= 1; j >>= 1) {
                #pragma unroll
                for (int s = 0; s < 4; s++) {
                    int i = s * 1024 + tid;
                    unsigned long long o = __shfl_xor_sync(0xffffffffu, v[s], j);
                    bool up    = ((i & k) == 0);
                    bool lower = ((i & j) == 0);
                    unsigned long long mx = v[s] > o ? v[s] : o;
                    unsigned long long mn = v[s] > o ? o : v[s];
                    v[s] = (up == lower) ? mx : mn;
                }
            }
            #pragma unroll
            for (int s = 0; s < 4; s++) cand[s * 1024 + tid] = v[s];
        }
        __syncthreads();
    }

    for (int i = tid; i < PRE_K; i += 1024) {
        unsigned long long k = cand[i];
        if (k == 0ULL) {
            scls2[i] = -1;
            scand2[i] = make_float4(0.f, 0.f, 0.f, 0.f);
        } else {
            int idx = (NB - 1) - (int)(unsigned int)k;
            scand2[i] = *(const float4*)(bxs + (size_t)idx * 4);
            scls2[i]  = (short)cats[idx];
        }
    }
    __syncthreads();

    if (tid < 32) {
        int nk = run_nms_warp(scand2, scls2, kept_idx, PRE_K, lane);
        if (lane == 0) sh_nk = nk;
    }
    __syncthreads();

    const int nk = sh_nk;
    for (int k0 = tid; k0 < MAX_OUT; k0 += 1024) {
        float vx1 = 0, vy1 = 0, vx2 = 0, vy2 = 0, vs = 0, vc = 0;
        if (k0 < nk) {
            int i = kept_idx[k0];
            float4 bbv = scand2[i];
            vx1 = bbv.x; vy1 = bbv.y; vx2 = bbv.z; vy2 = bbv.w;
            vs  = __uint_as_float((unsigned int)(cand[i] >> 32));
            vc  = (float)scls2[i];
        }
        out5[k0 * 5 + 0] = vx1;
        out5[k0 * 5 + 1] = vy1;
        out5[k0 * 5 + 2] = vx2;
        out5[k0 * 5 + 3] = vy2;
        out5[k0 * 5 + 4] = vs;
        if (write_cats) ocat[k0] = vc;
    }
}

// ---------------- launch ----------------------------------------------------
extern "C" void kernel_launch(void* const* d_in, const int* in_sizes, int n_in,
                              void* d_out, int out_size) {
    const float* boxes = (const float*)d_in[0];
    const float* confs = (const float*)d_in[1];
    if (n_in >= 2 && in_sizes[0] > in_sizes[1]) {
        boxes = (const float*)d_in[1];
        confs = (const float*)d_in[0];
    }
    float* out = (float*)d_out;

    if (out_size != BATCHES * MAX_OUT * 6)
        cudaMemsetAsync(d_out, 0, (size_t)out_size * sizeof(float), 0);

    cudaFuncSetAttribute(score_kernel,
                         cudaFuncAttributeMaxDynamicSharedMemorySize, SCORE_DYN);
    score_kernel<<<(BATCHES * NB) / (SB_ANCH * NTILES), SB_ANCH, SCORE_DYN>>>(confs);

    int write_cats = (out_size >= BATCHES * MAX_OUT * 6) ? 1 : 0;
    cudaFuncSetAttribute(fused_kernel,
                         cudaFuncAttributeMaxDynamicSharedMemorySize, FUSED_DYN);
    fused_kernel<<<BATCHES, 1024, FUSED_DYN>>>(boxes, out, write_cats);
}

// round 15
// speedup vs baseline: 3.5504x; 1.0689x over previous
#include <cuda_runtime.h>
#include <cstdint>

#define BATCHES 8
#define NB      32768
#define NCLS    81
#define PRE_K   2048
#define FKTGT   256
#define FCAP    1024
#define FLCAP   4096
#define CAP     4096
#define MAX_OUT 200
#define SB_ANCH 128
#define NTILES  4
#define TILE_ELEMS (SB_ANCH * NCLS)     /* 10368 floats = 41472 B */
#define NBINS   9024                    /* covers buckets 0..9012; mult of 32 */
#define WALKCH  (NBINS / 32)            /* 282 chunks */
#define BINBASE 0x3D4CCu                /* bits(0.05f) >> 12 */
#define MROWS   384
#define MWORDS  12                      /* 384/32 */
#define FUSED_DYN 69632                 /* max(fast 44032, full 69632) */
#define SCORE_DYN (2 * TILE_ELEMS * 4)  /* 82944 B double buffer */

// ---------------- scratch (device globals) ---------------------------------
__device__ unsigned long long g_keys[BATCHES * NB];    // (score_bits<<32)|(NB-1-idx), 0 if invalid
__device__ unsigned char      g_cat [BATCHES * NB];    // argmax class
__device__ unsigned int      g_hist[BATCHES * NBINS];  // per-batch histogram (zeroed by fused)
__device__ unsigned int      g_flcnt[BATCHES];         // bootstrap fastlist count (zeroed by fused)
__device__ unsigned long long g_flist[BATCHES * FLCAP];// keys with score > T0 (unordered)

// ---------------- kernel 1: score/argmax + histogram + bootstrap fastlist --
__global__ void __launch_bounds__(SB_ANCH)
score_kernel(const float* __restrict__ confs) {
    extern __shared__ float sbuf[];                  // 2 × TILE_ELEMS
    __shared__ alignas(8) unsigned long long mbar[2];

    const unsigned bytes = TILE_ELEMS * 4;
    unsigned mb0 = (unsigned)__cvta_generic_to_shared(&mbar[0]);
    unsigned mb1 = (unsigned)__cvta_generic_to_shared(&mbar[1]);
    unsigned sb0 = (unsigned)__cvta_generic_to_shared(sbuf);
    unsigned sb1 = (unsigned)__cvta_generic_to_shared(sbuf + TILE_ELEMS);
    const int tile0 = blockIdx.x * NTILES;
    const unsigned T0b = __float_as_uint(0.999f);
    const int lane = threadIdx.x & 31;

    if (threadIdx.x == 0) {
        asm volatile("mbarrier.init.shared.b64 [%0], 1;" :: "r"(mb0) : "memory");
        asm volatile("mbarrier.init.shared.b64 [%0], 1;" :: "r"(mb1) : "memory");
    }
    __syncthreads();
    if (threadIdx.x == 0) {
        asm volatile("mbarrier.arrive.expect_tx.shared.b64 _, [%0], %1;"
                     :: "r"(mb0), "r"(bytes) : "memory");
        asm volatile("cp.async.bulk.shared::cta.global.mbarrier::complete_tx::bytes [%0], [%1], %2, [%3];"
                     :: "r"(sb0), "l"(confs + (size_t)(tile0 + 0) * TILE_ELEMS),
                        "r"(bytes), "r"(mb0) : "memory");
        asm volatile("mbarrier.arrive.expect_tx.shared.b64 _, [%0], %1;"
                     :: "r"(mb1), "r"(bytes) : "memory");
        asm volatile("cp.async.bulk.shared::cta.global.mbarrier::complete_tx::bytes [%0], [%1], %2, [%3];"
                     :: "r"(sb1), "l"(confs + (size_t)(tile0 + 1) * TILE_ELEMS),
                        "r"(bytes), "r"(mb1) : "memory");
    }

    #pragma unroll
    for (int t = 0; t < NTILES; t++) {
        const unsigned mba = (t & 1) ? mb1 : mb0;
        const unsigned par = (unsigned)((t >> 1) & 1);
        unsigned done = 0;
        do {
            asm volatile("{\n\t.reg .pred P;\n\t"
                         "mbarrier.try_wait.parity.acquire.cta.shared::cta.b64 P, [%1], %2, 0x989680;\n\t"
                         "selp.b32 %0, 1, 0, P;\n\t}"
                         : "=r"(done) : "r"(mba), "r"(par) : "memory");
        } while (!done);

        const float* row = sbuf + (t & 1) * TILE_ELEMS + threadIdx.x * NCLS;
        float m = -1.0f; int mi = 0;
        #pragma unroll
        for (int j = 0; j < NCLS; j++) {
            float v = row[j];
            if (v > m) { m = v; mi = j; }        // ascending j + '>' keeps first max
        }
        const int a = (tile0 + t) * SB_ANCH + threadIdx.x;
        const int b = a >> 15;
        bool valid = (m > 0.05f) && (mi != 0);
        unsigned int n = (unsigned int)a & (NB - 1);
        unsigned long long key = 0ULL;
        unsigned int sbv = 0;
        if (valid) {
            sbv = __float_as_uint(m);
            key = (((unsigned long long)sbv) << 32) | (unsigned long long)(NB - 1u - n);
            unsigned int bucket = (sbv >> 12) - BINBASE;   // < 9013
            atomicAdd(&g_hist[b * NBINS + bucket], 1u);
        }
        g_keys[a] = key;
        g_cat[a]  = (unsigned char)mi;

        // bootstrap fastlist: keys with score bits >= T0b (warp-aggregated)
        bool hot = valid && (sbv >= T0b);
        unsigned bal = __ballot_sync(0xffffffffu, hot);
        if (bal) {
            int leader = __ffs(bal) - 1;
            unsigned basep = 0;
            if (lane == leader) basep = atomicAdd(&g_flcnt[b], (unsigned)__popc(bal));
            basep = __shfl_sync(0xffffffffu, basep, leader);
            if (hot) {
                unsigned pos = basep + (unsigned)__popc(bal & ((1u << lane) - 1u));
                if (pos < FLCAP) g_flist[(size_t)b * FLCAP + pos] = key;
            }
        }

        __syncthreads();
        if (t + 2 < NTILES && threadIdx.x == 0) {
            const unsigned dsb = (t & 1) ? sb1 : sb0;
            asm volatile("mbarrier.arrive.expect_tx.shared.b64 _, [%0], %1;"
                         :: "r"(mba), "r"(bytes) : "memory");
            asm volatile("cp.async.bulk.shared::cta.global.mbarrier::complete_tx::bytes [%0], [%1], %2, [%3];"
                         :: "r"(dsb), "l"(confs + (size_t)(tile0 + t + 2) * TILE_ELEMS),
                            "r"(bytes), "r"(mba) : "memory");
        }
    }
}

// ---------------- full-path NMS (warp-serial; slow path only) --------------
__device__ __forceinline__ int run_nms_warp(const float4* scand, const short* scls,
                                            short* kept_idx, int lim, int lane) {
    float kx1[7], ky1[7], kx2[7], ky2[7], kar[7];
    short kcl[7];
    int nk = 0;
    for (int i = 0; i < lim && nk < MAX_OUT; i++) {
        short ci = scls[i];
        if (ci < 0) break;
        float4 bb = scand[i];
        float ar = fmaxf(bb.z - bb.x, 0.f) * fmaxf(bb.w - bb.y, 0.f);
        bool sup = false;
        const int ns = (nk + 31) >> 5;
        #pragma unroll
        for (int s = 0; s < 7; s++) {
            if (s >= ns) break;
            if ((s * 32 + lane) < nk && kcl[s] == ci) {
                float ix1 = fmaxf(bb.x, kx1[s]);
                float iy1 = fmaxf(bb.y, ky1[s]);
                float ix2 = fminf(bb.z, kx2[s]);
                float iy2 = fminf(bb.w, ky2[s]);
                float inter = fmaxf(ix2 - ix1, 0.f) * fmaxf(iy2 - iy1, 0.f);
                float uni   = ar + kar[s] - inter;
                if (inter / fmaxf(uni, 1e-9f) > 0.5f) sup = true;
            }
        }
        sup = __any_sync(0xffffffffu, sup);
        if (!sup) {
            int slot = nk >> 5;
            if ((nk & 31) == lane) {
                #pragma unroll
                for (int s = 0; s < 7; s++) {
                    if (slot == s) {
                        kx1[s] = bb.x; ky1[s] = bb.y;
                        kx2[s] = bb.z; ky2[s] = bb.w;
                        kar[s] = ar;   kcl[s] = ci;
                    }
                }
            }
            if (lane == 0) kept_idx[nk] = (short)i;
            nk++;
        }
    }
    return nk;
}

// ---------------- kernel 2: FUSED everything (fast path + inline fallback) -
__global__ void __launch_bounds__(1024)
fused_kernel(const float* __restrict__ boxes, float* __restrict__ out, int write_cats) {
    extern __shared__ unsigned char dyn[];
    unsigned long long* fcand = (unsigned long long*)dyn;
    float4*             scand = (float4*)(dyn + 8192);
    unsigned char*      cls8  = (unsigned char*)(dyn + 24576);
    unsigned int*       M     = (unsigned int*)(dyn + 25600);
    unsigned long long* cand   = (unsigned long long*)dyn;
    float4*             scand2 = (float4*)(dyn + 32768);
    short*              scls2  = (short*)(dyn + 65536);

    __shared__ unsigned int s_Tb, s_Tbf, s_scnt, s_fcnt, s_fc, s_cnt2, s_flcnt;
    __shared__ int s_fullpath;
    __shared__ unsigned short clist[MROWS];
    __shared__ unsigned short coff[NCLS + 1];
    __shared__ unsigned int   cpos[NCLS];
    __shared__ short  kept_idx[MAX_OUT];
    __shared__ int    sh_nk;

    const int b = blockIdx.x;
    const int tid  = threadIdx.x;
    const int lane = tid & 31;
    const int warp = tid >> 5;
    const unsigned T0b = __float_as_uint(0.999f);

    if (tid == 0) {
        s_fc = 0; s_fullpath = 0;
        s_flcnt = g_flcnt[b];
        g_flcnt[b] = 0;                  // self-zero for next replay
    }

    // ---- A: warp-0 histogram walk from the top (exact thresholds+counts) ----
    unsigned int* gh = g_hist + (size_t)b * NBINS;
    if (warp == 0) {
        unsigned run = 0;
        int foundf = 0, founds = 0;
        unsigned Tbf = 0, fcv = 0, Tb = 0, scv = 0;
        for (int c = 0; c < WALKCH; c++) {
            int bin = NBINS - 1 - c * 32 - lane;
            unsigned v = gh[bin];
            unsigned p = v;
            #pragma unroll
            for (int off = 1; off < 32; off <<= 1) {
                unsigned t = __shfl_up_sync(0xffffffffu, p, off);
                if (lane >= off) p += t;
            }
            unsigned cum = run + p;
            if (!foundf) {
                unsigned cr = __ballot_sync(0xffffffffu, cum >= FKTGT && cum - v < FKTGT);
                if (cr) {
                    int src = __ffs(cr) - 1;
                    Tbf = __shfl_sync(0xffffffffu, (unsigned)bin, src);
                    fcv = __shfl_sync(0xffffffffu, cum, src);
                    foundf = 1;
                }
            }
            if (!founds) {
                unsigned cr = __ballot_sync(0xffffffffu, cum >= PRE_K && cum - v < PRE_K);
                if (cr) {
                    int src = __ffs(cr) - 1;
                    Tb  = __shfl_sync(0xffffffffu, (unsigned)bin, src);
                    scv = __shfl_sync(0xffffffffu, cum, src);
                    founds = 1;
                }
            }
            run = __shfl_sync(0xffffffffu, cum, 31);
            if (founds) break;
        }
        if (!foundf) { Tbf = 0; fcv = run; }
        if (!founds) { Tb = 0;  scv = run; }
        if (lane == 0) { s_Tb = Tb; s_Tbf = Tbf; s_scnt = scv; s_fcnt = fcv; }
    }
    __syncthreads();

    // zero this batch's histogram for the next graph replay (after all reads)
    for (int i = tid; i < NBINS; i += 1024) gh[i] = 0u;

    const unsigned int Tsb = (s_Tb + BINBASE) << 12;
    const unsigned int Tf  = (s_Tbf + BINBASE) << 12;
    const unsigned int fcnt = s_fcnt;
    const unsigned int scnt = s_scnt;
    const unsigned int flcnt = s_flcnt;
    const unsigned long long* keys = g_keys + (size_t)b * NB;
    const float*         bxs  = boxes + (size_t)b * NB * 4;
    const unsigned char* cats = g_cat + (size_t)b * NB;
    float* out5 = out + (size_t)b * MAX_OUT * 5;
    float* ocat = out + (size_t)BATCHES * MAX_OUT * 5 + (size_t)b * MAX_OUT;

    if (fcnt <= FCAP) {
        // ================= FAST PATH =================
        const bool use_flist = (Tf >= T0b) && (flcnt <= FLCAP);
        if (use_flist) {
            // ---- B': compact from bootstrap fastlist (<=4096 keys) ----
            const unsigned long long* fl = g_flist + (size_t)b * FLCAP;
            #pragma unroll
            for (int it = 0; it < 4; it++) {
                int i = it * 1024 + tid;
                unsigned long long k = (i < (int)flcnt) ? fl[i] : 0ULL;
                bool cf = ((unsigned int)(k >> 32) >= Tf) && (k != 0ULL);
                unsigned balf = __ballot_sync(0xffffffffu, cf);
                if (balf) {
                    int leader = __ffs(balf) - 1;
                    unsigned int basep = 0;
                    if (lane == leader) basep = atomicAdd(&s_fc, (unsigned)__popc(balf));
                    basep = __shfl_sync(0xffffffffu, basep, leader);
                    if (cf) {
                        unsigned int pos = basep + (unsigned)__popc(balf & ((1u << lane) - 1u));
                        if (pos < FCAP) fcand[pos] = k;
                    }
                }
            }
        } else {
            // ---- B: full sweep of g_keys, fast-threshold compaction ----
            #pragma unroll
            for (int it = 0; it < 8; it++) {
                unsigned long long kk[4];
                #pragma unroll
                for (int u = 0; u < 4; u++) kk[u] = keys[it * 4096 + u * 1024 + tid];
                #pragma unroll
                for (int u = 0; u < 4; u++) {
                    unsigned int sb = (unsigned int)(kk[u] >> 32);
                    bool cf = (sb >= Tf);
                    unsigned balf = __ballot_sync(0xffffffffu, cf);
                    if (balf) {
                        int leader = __ffs(balf) - 1;
                        unsigned int basep = 0;
                        if (lane == leader) basep = atomicAdd(&s_fc, (unsigned)__popc(balf));
                        basep = __shfl_sync(0xffffffffu, basep, leader);
                        if (cf) {
                            unsigned int pos = basep + (unsigned)__popc(balf & ((1u << lane) - 1u));
                            if (pos < FCAP) fcand[pos] = kk[u];
                        }
                    }
                }
            }
        }
        __syncthreads();
        unsigned int cnt = s_fc; if (cnt > FCAP) cnt = FCAP;

        // ---- C: runtime-sized bitonic sort (descending) ----
        int nsort = 64;
        while (nsort < (int)cnt) nsort <<= 1;       // <= 1024
        if (tid < nsort && tid >= (int)cnt) fcand[tid] = 0ULL;
        __syncthreads();

        if (tid < nsort) {
            unsigned long long v = fcand[tid];
            #pragma unroll
            for (int k = 2; k <= 32; k <<= 1) {
                #pragma unroll
                for (int j = k >> 1; j >= 1; j >>= 1) {
                    unsigned long long o = __shfl_xor_sync(0xffffffffu, v, j);
                    bool up    = ((tid & k) == 0);
                    bool lower = ((tid & j) == 0);
                    unsigned long long mx = v > o ? v : o;
                    unsigned long long mn = v > o ? o : v;
                    v = (up == lower) ? mx : mn;
                }
            }
            fcand[tid] = v;
        }
        __syncthreads();
        for (int k = 64; k <= nsort; k <<= 1) {
            for (int j = k >> 1; j >= 32; j >>= 1) {
                if (tid < nsort) {
                    int l = tid ^ j;
                    if (l > tid) {
                        unsigned long long a = fcand[tid], bb = fcand[l];
                        bool up = ((tid & k) == 0);
                        if ((a < bb) == up) { fcand[tid] = bb; fcand[l] = a; }
                    }
                }
                __syncthreads();
            }
            if (tid < nsort) {
                unsigned long long v = fcand[tid];
                #pragma unroll
                for (int j = 16; j >= 1; j >>= 1) {
                    unsigned long long o = __shfl_xor_sync(0xffffffffu, v, j);
                    bool up    = ((tid & k) == 0);
                    bool lower = ((tid & j) == 0);
                    unsigned long long mx = v > o ? v : o;
                    unsigned long long mn = v > o ? o : v;
                    v = (up == lower) ? mx : mn;
                }
                fcand[tid] = v;
            }
            __syncthreads();
        }

        // ---- D: stage boxes/classes; zero matrix; class counters ----
        {
            unsigned long long k = (tid < (int)cnt) ? fcand[tid] : 0ULL;
            if (k == 0ULL) {
                cls8[tid] = 0xFF;
                scand[tid] = make_float4(0.f, 0.f, 0.f, 0.f);
            } else {
                int idx = (NB - 1) - (int)(unsigned int)k;
                scand[tid] = *(const float4*)(bxs + (size_t)idx * 4);
                cls8[tid]  = cats[idx];
            }
        }
        #pragma unroll
        for (int u = tid; u < MROWS * MWORDS; u += 1024) M[u] = 0u;
        if (tid < NCLS) cpos[tid] = 0u;
        __syncthreads();

        const int lim = ((int)cnt < MROWS) ? (int)cnt : MROWS;

        if (tid < lim) atomicAdd(&cpos[cls8[tid]], 1u);
        __syncthreads();
        if (tid == 0) {
            unsigned run = 0;
            for (int c = 0; c < NCLS; c++) { coff[c] = (unsigned short)run; run += cpos[c]; }
            coff[NCLS] = (unsigned short)run;
        }
        __syncthreads();
        if (tid < NCLS) cpos[tid] = coff[tid];
        __syncthreads();
        if (tid < lim) {
            unsigned p = atomicAdd(&cpos[cls8[tid]], 1u);
            clist[p] = (unsigned short)tid;
        }
        __syncthreads();

        // ---- E: suppression matrix via class lists ----
        if (tid < lim) {
            const int r = tid;
            const int c = cls8[r];
            float4 br = scand[r];
            float arr = fmaxf(br.z - br.x, 0.f) * fmaxf(br.w - br.y, 0.f);
            const int e0 = coff[c], e1 = coff[c + 1];
            for (int e = e0; e < e1; e++) {
                int j = clist[e];
                if (j == r) continue;
                float4 bj = scand[j];
                float ix1 = fmaxf(br.x, bj.x);
                float iy1 = fmaxf(br.y, bj.y);
                float ix2 = fminf(br.z, bj.z);
                float iy2 = fminf(br.w, bj.w);
                float inter = fmaxf(ix2 - ix1, 0.f) * fmaxf(iy2 - iy1, 0.f);
                float aj = fmaxf(bj.z - bj.x, 0.f) * fmaxf(bj.w - bj.y, 0.f);
                float uni = arr + aj - inter;
                if (inter / fmaxf(uni, 1e-9f) > 0.5f)
                    atomicOr(&M[r * MWORDS + (j >> 5)], 1u << (j & 31));
            }
        }
        __syncthreads();

        // ---- F: warp 0 greedy scan (ffs-driven, shfl-preloaded row word) ----
        if (tid < 32) {
            unsigned sup = 0;
            int nk = 0;
            const int nwords = (lim + 31) >> 5;
            for (int w = 0; w < nwords; w++) {
                int remain = lim - (w << 5);
                unsigned valid = (remain >= 32) ? 0xFFFFFFFFu : ((1u << remain) - 1u);
                unsigned rw = M[((w << 5) + lane) * MWORDS + w];  // row (32w+lane), word w
                unsigned cur = __shfl_sync(0xffffffffu, sup, w);
                unsigned rem = ~cur & valid;
                while (rem) {
                    int t = __ffs(rem) - 1;
                    int i = (w << 5) + t;
                    unsigned roww = __shfl_sync(0xffffffffu, rw, t);
                    if (lane < MWORDS) sup |= M[i * MWORDS + lane];
                    if (lane == 0) kept_idx[nk] = (short)i;
                    nk++;
                    if (nk >= MAX_OUT) { rem = 0; break; }
                    rem &= ~(roww | (1u << t));
                }
                if (nk >= MAX_OUT) break;
            }
            if (lane == 0) sh_nk = nk;
        }
        __syncthreads();

        const int nk = sh_nk;
        bool complete = (nk >= MAX_OUT) || ((int)cnt <= MROWS && cnt >= scnt);
        if (complete) {
            if (tid < MAX_OUT) {
                int k0 = tid;
                float vx1 = 0, vy1 = 0, vx2 = 0, vy2 = 0, vs = 0, vc = 0;
                if (k0 < nk) {
                    int i = kept_idx[k0];
                    float4 bbv = scand[i];
                    vx1 = bbv.x; vy1 = bbv.y; vx2 = bbv.z; vy2 = bbv.w;
                    vs  = __uint_as_float((unsigned int)(fcand[i] >> 32));
                    vc  = (float)cls8[i];
                }
                out5[k0 * 5 + 0] = vx1;
                out5[k0 * 5 + 1] = vy1;
                out5[k0 * 5 + 2] = vx2;
                out5[k0 * 5 + 3] = vy2;
                out5[k0 * 5 + 4] = vs;
                if (write_cats) ocat[k0] = vc;
            }
            return;
        }
        if (tid == 0) s_fullpath = 1;
    }
    __syncthreads();
    if (!s_fullpath && fcnt <= FCAP) return;

    // ================= FULL PATH (inline fallback) =================
    if (tid == 0) s_cnt2 = 0;
    __syncthreads();

    #pragma unroll
    for (int it = 0; it < 8; it++) {
        unsigned long long kk[4];
        #pragma unroll
        for (int u = 0; u < 4; u++) kk[u] = keys[it * 4096 + u * 1024 + tid];
        #pragma unroll
        for (int u = 0; u < 4; u++) {
            unsigned int sb = (unsigned int)(kk[u] >> 32);
            bool c = (sb >= Tsb);
            unsigned bal = __ballot_sync(0xffffffffu, c);
            if (bal) {
                int leader = __ffs(bal) - 1;
                unsigned int basep = 0;
                if (lane == leader) basep = atomicAdd(&s_cnt2, (unsigned)__popc(bal));
                basep = __shfl_sync(0xffffffffu, basep, leader);
                if (c) {
                    unsigned int pos = basep + (unsigned)__popc(bal & ((1u << lane) - 1u));
                    if (pos < CAP) cand[pos] = kk[u];
                }
            }
        }
    }
    __syncthreads();
    unsigned int cnt2 = s_cnt2; if (cnt2 > CAP) cnt2 = CAP;
    #pragma unroll
    for (int s = 0; s < 4; s++) {
        int i = s * 1024 + tid;
        if (i >= (int)cnt2) cand[i] = 0ULL;
    }
    __syncthreads();

    {
        unsigned long long v[4];
        #pragma unroll
        for (int s = 0; s < 4; s++) v[s] = cand[s * 1024 + tid];
        #pragma unroll
        for (int k = 2; k <= 32; k <<= 1) {
            #pragma unroll
            for (int j = k >> 1; j >= 1; j >>= 1) {
                #pragma unroll
                for (int s = 0; s < 4; s++) {
                    int i = s * 1024 + tid;
                    unsigned long long o = __shfl_xor_sync(0xffffffffu, v[s], j);
                    bool up    = ((i & k) == 0);
                    bool lower = ((i & j) == 0);
                    unsigned long long mx = v[s] > o ? v[s] : o;
                    unsigned long long mn = v[s] > o ? o : v[s];
                    v[s] = (up == lower) ? mx : mn;
                }
            }
        }
        #pragma unroll
        for (int s = 0; s < 4; s++) cand[s * 1024 + tid] = v[s];
    }
    __syncthreads();
    for (int k = 64; k <= CAP; k <<= 1) {
        for (int j = k >> 1; j >= 32; j >>= 1) {
            #pragma unroll
            for (int s0 = 0; s0 < CAP; s0 += 1024) {
                int i = s0 + tid;
                int l = i ^ j;
                if (l > i) {
                    unsigned long long a = cand[i], bb = cand[l];
                    bool up = ((i & k) == 0);
                    if ((a < bb) == up) { cand[i] = bb; cand[l] = a; }
                }
            }
            __syncthreads();
        }
        {
            unsigned long long v[4];
            #pragma unroll
            for (int s = 0; s < 4; s++) v[s] = cand[s * 1024 + tid];
            #pragma unroll
            for (int j = 16; j >= 1; j >>= 1) {
                #pragma unroll
                for (int s = 0; s < 4; s++) {
                    int i = s * 1024 + tid;
                    unsigned long long o = __shfl_xor_sync(0xffffffffu, v[s], j);
                    bool up    = ((i & k) == 0);
                    bool lower = ((i & j) == 0);
                    unsigned long long mx = v[s] > o ? v[s] : o;
                    unsigned long long mn = v[s] > o ? o : v[s];
                    v[s] = (up == lower) ? mx : mn;
                }
            }
            #pragma unroll
            for (int s = 0; s < 4; s++) cand[s * 1024 + tid] = v[s];
        }
        __syncthreads();
    }

    for (int i = tid; i < PRE_K; i += 1024) {
        unsigned long long k = cand[i];
        if (k == 0ULL) {
            scls2[i] = -1;
            scand2[i] = make_float4(0.f, 0.f, 0.f, 0.f);
        } else {
            int idx = (NB - 1) - (int)(unsigned int)k;
            scand2[i] = *(const float4*)(bxs + (size_t)idx * 4);
            scls2[i]  = (short)cats[idx];
        }
    }
    __syncthreads();

    if (tid < 32) {
        int nk = run_nms_warp(scand2, scls2, kept_idx, PRE_K, lane);
        if (lane == 0) sh_nk = nk;
    }
    __syncthreads();

    const int nk = sh_nk;
    for (int k0 = tid; k0 < MAX_OUT; k0 += 1024) {
        float vx1 = 0, vy1 = 0, vx2 = 0, vy2 = 0, vs = 0, vc = 0;
        if (k0 < nk) {
            int i = kept_idx[k0];
            float4 bbv = scand2[i];
            vx1 = bbv.x; vy1 = bbv.y; vx2 = bbv.z; vy2 = bbv.w;
            vs  = __uint_as_float((unsigned int)(cand[i] >> 32));
            vc  = (float)scls2[i];
        }
        out5[k0 * 5 + 0] = vx1;
        out5[k0 * 5 + 1] = vy1;
        out5[k0 * 5 + 2] = vx2;
        out5[k0 * 5 + 3] = vy2;
        out5[k0 * 5 + 4] = vs;
        if (write_cats) ocat[k0] = vc;
    }
}

// ---------------- launch ----------------------------------------------------
extern "C" void kernel_launch(void* const* d_in, const int* in_sizes, int n_in,
                              void* d_out, int out_size) {
    const float* boxes = (const float*)d_in[0];
    const float* confs = (const float*)d_in[1];
    if (n_in >= 2 && in_sizes[0] > in_sizes[1]) {
        boxes = (const float*)d_in[1];
        confs = (const float*)d_in[0];
    }
    float* out = (float*)d_out;

    if (out_size != BATCHES * MAX_OUT * 6)
        cudaMemsetAsync(d_out, 0, (size_t)out_size * sizeof(float), 0);

    cudaFuncSetAttribute(score_kernel,
                         cudaFuncAttributeMaxDynamicSharedMemorySize, SCORE_DYN);
    score_kernel<<<(BATCHES * NB) / (SB_ANCH * NTILES), SB_ANCH, SCORE_DYN>>>(confs);

    int write_cats = (out_size >= BATCHES * MAX_OUT * 6) ? 1 : 0;
    cudaFuncSetAttribute(fused_kernel,
                         cudaFuncAttributeMaxDynamicSharedMemorySize, FUSED_DYN);
    fused_kernel<<<BATCHES, 1024, FUSED_DYN>>>(boxes, out, write_cats);
}

// round 16
// speedup vs baseline: 3.8242x; 1.0771x over previous
#include <cuda_runtime.h>
#include <cstdint>

#define BATCHES 8
#define NB      32768
#define NCLS    81
#define PRE_K   2048
#define FKTGT   256
#define FCAP    1024
#define FLCAP   4096
#define CAP     4096
#define MAX_OUT 200
#define SB_ANCH 128
#define NTILES  4
#define TILE_ELEMS (SB_ANCH * NCLS)     /* 10368 floats = 41472 B */
#define NBINS   9024                    /* coarse bins; mult of 32 */
#define WALKCH  (NBINS / 32)
#define BINBASE 0x3D4CCu                /* bits(0.05f) >> 12 */
#define NFINE   96                      /* fine bins over [0.999,1.0), 8-bit gran */
#define MROWS   384
#define MWORDS  12                      /* 384/32 */
#define FUSED_DYN 69632
#define SCORE_DYN (2 * TILE_ELEMS * 4)  /* 82944 B double buffer */

// ---------------- scratch (device globals) ---------------------------------
__device__ unsigned long long g_keys[BATCHES * NB];    // (score_bits<<32)|(NB-1-idx), 0 if invalid
__device__ unsigned char      g_cat [BATCHES * NB];    // argmax class
__device__ unsigned int      g_hist[BATCHES * NBINS];  // coarse hist (zeroed by fused)
__device__ unsigned int      g_fhist[BATCHES * NFINE]; // fine hist, sb>=T0b (zeroed by fused)
__device__ unsigned int      g_flcnt[BATCHES];         // fastlist count (zeroed by fused)
__device__ unsigned long long g_flist[BATCHES * FLCAP];// keys with sb >= T0b (unordered)

// ---------------- kernel 1: score/argmax + hists + bootstrap fastlist ------
__global__ void __launch_bounds__(SB_ANCH)
score_kernel(const float* __restrict__ confs) {
    extern __shared__ float sbuf[];                  // 2 × TILE_ELEMS
    __shared__ alignas(8) unsigned long long mbar[2];

    const unsigned bytes = TILE_ELEMS * 4;
    unsigned mb0 = (unsigned)__cvta_generic_to_shared(&mbar[0]);
    unsigned mb1 = (unsigned)__cvta_generic_to_shared(&mbar[1]);
    unsigned sb0 = (unsigned)__cvta_generic_to_shared(sbuf);
    unsigned sb1 = (unsigned)__cvta_generic_to_shared(sbuf + TILE_ELEMS);
    const int tile0 = blockIdx.x * NTILES;
    const unsigned T0b = __float_as_uint(0.999f);
    const int lane = threadIdx.x & 31;

    if (threadIdx.x == 0) {
        asm volatile("mbarrier.init.shared.b64 [%0], 1;" :: "r"(mb0) : "memory");
        asm volatile("mbarrier.init.shared.b64 [%0], 1;" :: "r"(mb1) : "memory");
    }
    __syncthreads();
    if (threadIdx.x == 0) {
        asm volatile("mbarrier.arrive.expect_tx.shared.b64 _, [%0], %1;"
                     :: "r"(mb0), "r"(bytes) : "memory");
        asm volatile("cp.async.bulk.shared::cta.global.mbarrier::complete_tx::bytes [%0], [%1], %2, [%3];"
                     :: "r"(sb0), "l"(confs + (size_t)(tile0 + 0) * TILE_ELEMS),
                        "r"(bytes), "r"(mb0) : "memory");
        asm volatile("mbarrier.arrive.expect_tx.shared.b64 _, [%0], %1;"
                     :: "r"(mb1), "r"(bytes) : "memory");
        asm volatile("cp.async.bulk.shared::cta.global.mbarrier::complete_tx::bytes [%0], [%1], %2, [%3];"
                     :: "r"(sb1), "l"(confs + (size_t)(tile0 + 1) * TILE_ELEMS),
                        "r"(bytes), "r"(mb1) : "memory");
    }

    #pragma unroll
    for (int t = 0; t < NTILES; t++) {
        const unsigned mba = (t & 1) ? mb1 : mb0;
        const unsigned par = (unsigned)((t >> 1) & 1);
        unsigned done = 0;
        do {
            asm volatile("{\n\t.reg .pred P;\n\t"
                         "mbarrier.try_wait.parity.acquire.cta.shared::cta.b64 P, [%1], %2, 0x989680;\n\t"
                         "selp.b32 %0, 1, 0, P;\n\t}"
                         : "=r"(done) : "r"(mba), "r"(par) : "memory");
        } while (!done);

        const float* row = sbuf + (t & 1) * TILE_ELEMS + threadIdx.x * NCLS;
        float m = -1.0f; int mi = 0;
        #pragma unroll
        for (int j = 0; j < NCLS; j++) {
            float v = row[j];
            if (v > m) { m = v; mi = j; }        // ascending j + '>' keeps first max
        }
        const int a = (tile0 + t) * SB_ANCH + threadIdx.x;
        const int b = a >> 15;
        bool valid = (m > 0.05f) && (mi != 0);
        unsigned int n = (unsigned int)a & (NB - 1);
        unsigned long long key = 0ULL;
        unsigned int sbv = 0;
        if (valid) {
            sbv = __float_as_uint(m);
            key = (((unsigned long long)sbv) << 32) | (unsigned long long)(NB - 1u - n);
            unsigned int bucket = (sbv >> 12) - BINBASE;
            atomicAdd(&g_hist[b * NBINS + bucket], 1u);
        }
        g_keys[a] = key;
        g_cat[a]  = (unsigned char)mi;

        bool hot = valid && (sbv >= T0b);
        if (hot) atomicAdd(&g_fhist[b * NFINE + ((sbv - T0b) >> 8)], 1u);
        unsigned bal = __ballot_sync(0xffffffffu, hot);
        if (bal) {
            int leader = __ffs(bal) - 1;
            unsigned basep = 0;
            if (lane == leader) basep = atomicAdd(&g_flcnt[b], (unsigned)__popc(bal));
            basep = __shfl_sync(0xffffffffu, basep, leader);
            if (hot) {
                unsigned pos = basep + (unsigned)__popc(bal & ((1u << lane) - 1u));
                if (pos < FLCAP) g_flist[(size_t)b * FLCAP + pos] = key;
            }
        }

        __syncthreads();
        if (t + 2 < NTILES && threadIdx.x == 0) {
            const unsigned dsb = (t & 1) ? sb1 : sb0;
            asm volatile("mbarrier.arrive.expect_tx.shared.b64 _, [%0], %1;"
                         :: "r"(mba), "r"(bytes) : "memory");
            asm volatile("cp.async.bulk.shared::cta.global.mbarrier::complete_tx::bytes [%0], [%1], %2, [%3];"
                         :: "r"(dsb), "l"(confs + (size_t)(tile0 + t + 2) * TILE_ELEMS),
                            "r"(bytes), "r"(mba) : "memory");
        }
    }
}

// ---------------- full-path NMS (warp-serial; slow path only) --------------
__device__ __forceinline__ int run_nms_warp(const float4* scand, const short* scls,
                                            short* kept_idx, int lim, int lane) {
    float kx1[7], ky1[7], kx2[7], ky2[7], kar[7];
    short kcl[7];
    int nk = 0;
    for (int i = 0; i < lim && nk < MAX_OUT; i++) {
        short ci = scls[i];
        if (ci < 0) break;
        float4 bb = scand[i];
        float ar = fmaxf(bb.z - bb.x, 0.f) * fmaxf(bb.w - bb.y, 0.f);
        bool sup = false;
        const int ns = (nk + 31) >> 5;
        #pragma unroll
        for (int s = 0; s < 7; s++) {
            if (s >= ns) break;
            if ((s * 32 + lane) < nk && kcl[s] == ci) {
                float ix1 = fmaxf(bb.x, kx1[s]);
                float iy1 = fmaxf(bb.y, ky1[s]);
                float ix2 = fminf(bb.z, kx2[s]);
                float iy2 = fminf(bb.w, ky2[s]);
                float inter = fmaxf(ix2 - ix1, 0.f) * fmaxf(iy2 - iy1, 0.f);
                float uni   = ar + kar[s] - inter;
                if (inter / fmaxf(uni, 1e-9f) > 0.5f) sup = true;
            }
        }
        sup = __any_sync(0xffffffffu, sup);
        if (!sup) {
            int slot = nk >> 5;
            if ((nk & 31) == lane) {
                #pragma unroll
                for (int s = 0; s < 7; s++) {
                    if (slot == s) {
                        kx1[s] = bb.x; ky1[s] = bb.y;
                        kx2[s] = bb.z; ky2[s] = bb.w;
                        kar[s] = ar;   kcl[s] = ci;
                    }
                }
            }
            if (lane == 0) kept_idx[nk] = (short)i;
            nk++;
        }
    }
    return nk;
}

// ---------------- kernel 2: FUSED everything -------------------------------
__global__ void __launch_bounds__(1024)
fused_kernel(const float* __restrict__ boxes, float* __restrict__ out, int write_cats) {
    extern __shared__ unsigned char dyn[];
    unsigned int*       fcand32 = (unsigned int*)dyn;
    unsigned long long* fcand = (unsigned long long*)dyn;
    float4*             scand = (float4*)(dyn + 8192);
    unsigned char*      cls8  = (unsigned char*)(dyn + 24576);
    unsigned int*       M     = (unsigned int*)(dyn + 25600);
    unsigned long long* cand   = (unsigned long long*)dyn;
    float4*             scand2 = (float4*)(dyn + 32768);
    short*              scls2  = (short*)(dyn + 65536);

    __shared__ unsigned int s_Tb, s_Tbf, s_scnt, s_fcnt, s_fc, s_cnt2, s_flcnt;
    __shared__ unsigned int s_tfF, s_fcntF, s_haveF;
    __shared__ int s_fullpath;
    __shared__ unsigned short clist[MROWS];
    __shared__ unsigned short coff[NCLS + 1];
    __shared__ unsigned int   cpos[NCLS];
    __shared__ short  kept_idx[MAX_OUT];
    __shared__ int    sh_nk;

    const int b = blockIdx.x;
    const int tid  = threadIdx.x;
    const int lane = tid & 31;
    const int warp = tid >> 5;
    const unsigned T0b = __float_as_uint(0.999f);

    if (tid == 0) {
        s_fc = 0; s_fullpath = 0; s_haveF = 0;
        s_flcnt = g_flcnt[b];
        g_flcnt[b] = 0;                  // self-zero for next replay
    }

    // ---- A1: warp-0 fine-hist walk (threshold at ~top-256, tight) ----
    unsigned int* gfh = g_fhist + (size_t)b * NFINE;
    unsigned int* gh  = g_hist  + (size_t)b * NBINS;
    if (warp == 0) {
        unsigned run = 0; int found = 0;
        unsigned tf = 0, fcv = 0;
        #pragma unroll
        for (int c = 0; c < NFINE / 32; c++) {
            int bin = NFINE - 1 - c * 32 - lane;
            unsigned v = gfh[bin];
            unsigned p = v;
            #pragma unroll
            for (int off = 1; off < 32; off <<= 1) {
                unsigned t = __shfl_up_sync(0xffffffffu, p, off);
                if (lane >= off) p += t;
            }
            unsigned cum = run + p;
            if (!found) {
                unsigned cr = __ballot_sync(0xffffffffu, cum >= FKTGT && cum - v < FKTGT);
                if (cr) {
                    int src = __ffs(cr) - 1;
                    tf  = __shfl_sync(0xffffffffu, (unsigned)bin, src);
                    fcv = __shfl_sync(0xffffffffu, cum, src);
                    found = 1;
                }
            }
            run = __shfl_sync(0xffffffffu, cum, 31);
        }
        if (lane == 0) { s_tfF = tf; s_fcntF = fcv; s_haveF = (unsigned)found; }
    }
    // ---- A2: warp-1 coarse-hist walk (top-2048 threshold + scnt) ----
    if (warp == 1) {
        unsigned run = 0;
        int foundf = 0, founds = 0;
        unsigned Tbf = 0, fcv = 0, Tb = 0, scv = 0;
        for (int c = 0; c < WALKCH; c++) {
            int bin = NBINS - 1 - c * 32 - lane;
            unsigned v = gh[bin];
            unsigned p = v;
            #pragma unroll
            for (int off = 1; off < 32; off <<= 1) {
                unsigned t = __shfl_up_sync(0xffffffffu, p, off);
                if (lane >= off) p += t;
            }
            unsigned cum = run + p;
            if (!foundf) {
                unsigned cr = __ballot_sync(0xffffffffu, cum >= FKTGT && cum - v < FKTGT);
                if (cr) {
                    int src = __ffs(cr) - 1;
                    Tbf = __shfl_sync(0xffffffffu, (unsigned)bin, src);
                    fcv = __shfl_sync(0xffffffffu, cum, src);
                    foundf = 1;
                }
            }
            if (!founds) {
                unsigned cr = __ballot_sync(0xffffffffu, cum >= PRE_K && cum - v < PRE_K);
                if (cr) {
                    int src = __ffs(cr) - 1;
                    Tb  = __shfl_sync(0xffffffffu, (unsigned)bin, src);
                    scv = __shfl_sync(0xffffffffu, cum, src);
                    founds = 1;
                }
            }
            run = __shfl_sync(0xffffffffu, cum, 31);
            if (founds) break;
        }
        if (!foundf) { Tbf = 0; fcv = run; }
        if (!founds) { Tb = 0;  scv = run; }
        if (lane == 0) { s_Tb = Tb; s_Tbf = Tbf; s_scnt = scv; s_fcnt = fcv; }
    }
    __syncthreads();

    // zero hists for next replay (after all reads)
    for (int i = tid; i < NBINS; i += 1024) gh[i] = 0u;
    if (tid < NFINE) gfh[tid] = 0u;

    const unsigned int Tsb = (s_Tb + BINBASE) << 12;
    const unsigned int fcntC = s_fcnt;
    const unsigned int scnt = s_scnt;
    const unsigned int flcnt = s_flcnt;
    const bool fine_ok = (s_haveF != 0) && (flcnt <= FLCAP);
    const unsigned int cnt_sel = fine_ok ? s_fcntF : fcntC;
    const unsigned long long* keys = g_keys + (size_t)b * NB;
    const float*         bxs  = boxes + (size_t)b * NB * 4;
    const unsigned char* cats = g_cat + (size_t)b * NB;
    float* out5 = out + (size_t)b * MAX_OUT * 5;
    float* ocat = out + (size_t)BATCHES * MAX_OUT * 5 + (size_t)b * MAX_OUT;

    if (cnt_sel <= FCAP) {
        // ================= FAST PATH =================
        if (fine_ok) {
            // ---- B': compact flist with u32 order-preserving keys ----
            const unsigned TfF = T0b + (s_tfF << 8);
            const unsigned long long* fl = g_flist + (size_t)b * FLCAP;
            #pragma unroll
            for (int it = 0; it < 4; it++) {
                int i = it * 1024 + tid;
                unsigned long long k = (i < (int)flcnt) ? fl[i] : 0ULL;
                unsigned sb = (unsigned)(k >> 32);
                bool cf = (sb >= TfF) && (k != 0ULL);
                unsigned balf = __ballot_sync(0xffffffffu, cf);
                if (balf) {
                    int leader = __ffs(balf) - 1;
                    unsigned int basep = 0;
                    if (lane == leader) basep = atomicAdd(&s_fc, (unsigned)__popc(balf));
                    basep = __shfl_sync(0xffffffffu, basep, leader);
                    if (cf) {
                        unsigned int pos = basep + (unsigned)__popc(balf & ((1u << lane) - 1u));
                        if (pos < FCAP)
                            fcand32[pos] = ((sb - T0b + 1u) << 15) | ((unsigned)k & 0x7FFFu);
                    }
                }
            }
        } else {
            // ---- B: full sweep of g_keys (u64) ----
            const unsigned Tf = (s_Tbf + BINBASE) << 12;
            #pragma unroll
            for (int it = 0; it < 8; it++) {
                unsigned long long kk[4];
                #pragma unroll
                for (int u = 0; u < 4; u++) kk[u] = keys[it * 4096 + u * 1024 + tid];
                #pragma unroll
                for (int u = 0; u < 4; u++) {
                    unsigned int sb = (unsigned int)(kk[u] >> 32);
                    bool cf = (sb >= Tf);
                    unsigned balf = __ballot_sync(0xffffffffu, cf);
                    if (balf) {
                        int leader = __ffs(balf) - 1;
                        unsigned int basep = 0;
                        if (lane == leader) basep = atomicAdd(&s_fc, (unsigned)__popc(balf));
                        basep = __shfl_sync(0xffffffffu, basep, leader);
                        if (cf) {
                            unsigned int pos = basep + (unsigned)__popc(balf & ((1u << lane) - 1u));
                            if (pos < FCAP) fcand[pos] = kk[u];
                        }
                    }
                }
            }
        }
        __syncthreads();
        unsigned int cnt = s_fc; if (cnt > FCAP) cnt = FCAP;

        int nsort = 64;
        while (nsort < (int)cnt) nsort <<= 1;       // <= 1024

        if (fine_ok) {
            // ---- C': u32 bitonic sort (descending) ----
            if (tid < nsort && tid >= (int)cnt) fcand32[tid] = 0u;
            __syncthreads();
            if (tid < nsort) {
                unsigned v = fcand32[tid];
                #pragma unroll
                for (int k = 2; k <= 32; k <<= 1) {
                    #pragma unroll
                    for (int j = k >> 1; j >= 1; j >>= 1) {
                        unsigned o = __shfl_xor_sync(0xffffffffu, v, j);
                        bool up    = ((tid & k) == 0);
                        bool lower = ((tid & j) == 0);
                        unsigned mx = v > o ? v : o;
                        unsigned mn = v > o ? o : v;
                        v = (up == lower) ? mx : mn;
                    }
                }
                fcand32[tid] = v;
            }
            __syncthreads();
            for (int k = 64; k <= nsort; k <<= 1) {
                for (int j = k >> 1; j >= 32; j >>= 1) {
                    if (tid < nsort) {
                        int l = tid ^ j;
                        if (l > tid) {
                            unsigned a = fcand32[tid], bb = fcand32[l];
                            bool up = ((tid & k) == 0);
                            if ((a < bb) == up) { fcand32[tid] = bb; fcand32[l] = a; }
                        }
                    }
                    __syncthreads();
                }
                if (tid < nsort) {
                    unsigned v = fcand32[tid];
                    #pragma unroll
                    for (int j = 16; j >= 1; j >>= 1) {
                        unsigned o = __shfl_xor_sync(0xffffffffu, v, j);
                        bool up    = ((tid & k) == 0);
                        bool lower = ((tid & j) == 0);
                        unsigned mx = v > o ? v : o;
                        unsigned mn = v > o ? o : v;
                        v = (up == lower) ? mx : mn;
                    }
                    fcand32[tid] = v;
                }
                __syncthreads();
            }
            // expand u32 -> u64 in place (all reads before all writes)
            unsigned v32 = (tid < (int)cnt) ? fcand32[tid] : 0u;
            __syncthreads();
            fcand[tid] = v32
                ? ((((unsigned long long)((v32 >> 15) - 1u + T0b)) << 32)
                   | (unsigned long long)(v32 & 0x7FFFu))
                : 0ULL;
            __syncthreads();
        } else {
            // ---- C: u64 bitonic sort (descending) ----
            if (tid < nsort && tid >= (int)cnt) fcand[tid] = 0ULL;
            __syncthreads();
            if (tid < nsort) {
                unsigned long long v = fcand[tid];
                #pragma unroll
                for (int k = 2; k <= 32; k <<= 1) {
                    #pragma unroll
                    for (int j = k >> 1; j >= 1; j >>= 1) {
                        unsigned long long o = __shfl_xor_sync(0xffffffffu, v, j);
                        bool up    = ((tid & k) == 0);
                        bool lower = ((tid & j) == 0);
                        unsigned long long mx = v > o ? v : o;
                        unsigned long long mn = v > o ? o : v;
                        v = (up == lower) ? mx : mn;
                    }
                }
                fcand[tid] = v;
            }
            __syncthreads();
            for (int k = 64; k <= nsort; k <<= 1) {
                for (int j = k >> 1; j >= 32; j >>= 1) {
                    if (tid < nsort) {
                        int l = tid ^ j;
                        if (l > tid) {
                            unsigned long long a = fcand[tid], bb = fcand[l];
                            bool up = ((tid & k) == 0);
                            if ((a < bb) == up) { fcand[tid] = bb; fcand[l] = a; }
                        }
                    }
                    __syncthreads();
                }
                if (tid < nsort) {
                    unsigned long long v = fcand[tid];
                    #pragma unroll
                    for (int j = 16; j >= 1; j >>= 1) {
                        unsigned long long o = __shfl_xor_sync(0xffffffffu, v, j);
                        bool up    = ((tid & k) == 0);
                        bool lower = ((tid & j) == 0);
                        unsigned long long mx = v > o ? v : o;
                        unsigned long long mn = v > o ? o : v;
                        v = (up == lower) ? mx : mn;
                    }
                    fcand[tid] = v;
                }
                __syncthreads();
            }
        }

        // ---- D: stage boxes/classes; zero matrix; class counters ----
        {
            unsigned long long k = (tid < (int)cnt) ? fcand[tid] : 0ULL;
            if (k == 0ULL) {
                cls8[tid] = 0xFF;
                scand[tid] = make_float4(0.f, 0.f, 0.f, 0.f);
            } else {
                int idx = (NB - 1) - (int)(unsigned int)k;
                scand[tid] = *(const float4*)(bxs + (size_t)idx * 4);
                cls8[tid]  = cats[idx];
            }
        }
        #pragma unroll
        for (int u = tid; u < MROWS * MWORDS; u += 1024) M[u] = 0u;
        if (tid < NCLS) cpos[tid] = 0u;
        __syncthreads();

        const int lim = ((int)cnt < MROWS) ? (int)cnt : MROWS;

        if (tid < lim) atomicAdd(&cpos[cls8[tid]], 1u);
        __syncthreads();
        if (warp == 0) {
            // parallel exclusive scan over 81 class counts
            unsigned carry = 0;
            if (lane == 0) coff[0] = 0;
            #pragma unroll
            for (int c0 = 0; c0 < NCLS; c0 += 32) {
                int idx = c0 + lane;
                unsigned v = (idx < NCLS) ? cpos[idx] : 0u;
                unsigned p = v;
                #pragma unroll
                for (int off = 1; off < 32; off <<= 1) {
                    unsigned t = __shfl_up_sync(0xffffffffu, p, off);
                    if (lane >= off) p += t;
                }
                if (idx < NCLS) coff[idx + 1] = (unsigned short)(carry + p);
                carry += __shfl_sync(0xffffffffu, p, 31);
            }
        }
        __syncthreads();
        if (tid < NCLS) cpos[tid] = coff[tid];
        __syncthreads();
        if (tid < lim) {
            unsigned p = atomicAdd(&cpos[cls8[tid]], 1u);
            clist[p] = (unsigned short)tid;
        }
        __syncthreads();

        // ---- E: suppression matrix via class lists ----
        if (tid < lim) {
            const int r = tid;
            const int c = cls8[r];
            float4 br = scand[r];
            float arr = fmaxf(br.z - br.x, 0.f) * fmaxf(br.w - br.y, 0.f);
            const int e0 = coff[c], e1 = coff[c + 1];
            for (int e = e0; e < e1; e++) {
                int j = clist[e];
                if (j == r) continue;
                float4 bj = scand[j];
                float ix1 = fmaxf(br.x, bj.x);
                float iy1 = fmaxf(br.y, bj.y);
                float ix2 = fminf(br.z, bj.z);
                float iy2 = fminf(br.w, bj.w);
                float inter = fmaxf(ix2 - ix1, 0.f) * fmaxf(iy2 - iy1, 0.f);
                float aj = fmaxf(bj.z - bj.x, 0.f) * fmaxf(bj.w - bj.y, 0.f);
                float uni = arr + aj - inter;
                if (inter / fmaxf(uni, 1e-9f) > 0.5f)
                    atomicOr(&M[r * MWORDS + (j >> 5)], 1u << (j & 31));
            }
        }
        __syncthreads();

        // ---- F: warp 0 greedy scan (ffs-driven, shfl-preloaded row word) ----
        if (tid < 32) {
            unsigned sup = 0;
            int nk = 0;
            const int nwords = (lim + 31) >> 5;
            for (int w = 0; w < nwords; w++) {
                int remain = lim - (w << 5);
                unsigned valid = (remain >= 32) ? 0xFFFFFFFFu : ((1u << remain) - 1u);
                unsigned rw = M[((w << 5) + lane) * MWORDS + w];
                unsigned cur = __shfl_sync(0xffffffffu, sup, w);
                unsigned rem = ~cur & valid;
                while (rem) {
                    int t = __ffs(rem) - 1;
                    int i = (w << 5) + t;
                    unsigned roww = __shfl_sync(0xffffffffu, rw, t);
                    if (lane < MWORDS) sup |= M[i * MWORDS + lane];
                    if (lane == 0) kept_idx[nk] = (short)i;
                    nk++;
                    if (nk >= MAX_OUT) { rem = 0; break; }
                    rem &= ~(roww | (1u << t));
                }
                if (nk >= MAX_OUT) break;
            }
            if (lane == 0) sh_nk = nk;
        }
        __syncthreads();

        const int nk = sh_nk;
        bool complete = (nk >= MAX_OUT) || ((int)cnt <= MROWS && cnt >= scnt);
        if (complete) {
            if (tid < MAX_OUT) {
                int k0 = tid;
                float vx1 = 0, vy1 = 0, vx2 = 0, vy2 = 0, vs = 0, vc = 0;
                if (k0 < nk) {
                    int i = kept_idx[k0];
                    float4 bbv = scand[i];
                    vx1 = bbv.x; vy1 = bbv.y; vx2 = bbv.z; vy2 = bbv.w;
                    vs  = __uint_as_float((unsigned int)(fcand[i] >> 32));
                    vc  = (float)cls8[i];
                }
                out5[k0 * 5 + 0] = vx1;
                out5[k0 * 5 + 1] = vy1;
                out5[k0 * 5 + 2] = vx2;
                out5[k0 * 5 + 3] = vy2;
                out5[k0 * 5 + 4] = vs;
                if (write_cats) ocat[k0] = vc;
            }
            return;
        }
        if (tid == 0) s_fullpath = 1;
    }
    __syncthreads();
    if (!s_fullpath && cnt_sel <= FCAP) return;

    // ================= FULL PATH (inline fallback) =================
    if (tid == 0) s_cnt2 = 0;
    __syncthreads();

    #pragma unroll
    for (int it = 0; it < 8; it++) {
        unsigned long long kk[4];
        #pragma unroll
        for (int u = 0; u < 4; u++) kk[u] = keys[it * 4096 + u * 1024 + tid];
        #pragma unroll
        for (int u = 0; u < 4; u++) {
            unsigned int sb = (unsigned int)(kk[u] >> 32);
            bool c = (sb >= Tsb);
            unsigned bal = __ballot_sync(0xffffffffu, c);
            if (bal) {
                int leader = __ffs(bal) - 1;
                unsigned int basep = 0;
                if (lane == leader) basep = atomicAdd(&s_cnt2, (unsigned)__popc(bal));
                basep = __shfl_sync(0xffffffffu, basep, leader);
                if (c) {
                    unsigned int pos = basep + (unsigned)__popc(bal & ((1u << lane) - 1u));
                    if (pos < CAP) cand[pos] = kk[u];
                }
            }
        }
    }
    __syncthreads();
    unsigned int cnt2 = s_cnt2; if (cnt2 > CAP) cnt2 = CAP;
    #pragma unroll
    for (int s = 0; s < 4; s++) {
        int i = s * 1024 + tid;
        if (i >= (int)cnt2) cand[i] = 0ULL;
    }
    __syncthreads();

    {
        unsigned long long v[4];
        #pragma unroll
        for (int s = 0; s < 4; s++) v[s] = cand[s * 1024 + tid];
        #pragma unroll
        for (int k = 2; k <= 32; k <<= 1) {
            #pragma unroll
            for (int j = k >> 1; j >= 1; j >>= 1) {
                #pragma unroll
                for (int s = 0; s < 4; s++) {
                    int i = s * 1024 + tid;
                    unsigned long long o = __shfl_xor_sync(0xffffffffu, v[s], j);
                    bool up    = ((i & k) == 0);
                    bool lower = ((i & j) == 0);
                    unsigned long long mx = v[s] > o ? v[s] : o;
                    unsigned long long mn = v[s] > o ? o : v[s];
                    v[s] = (up == lower) ? mx : mn;
                }
            }
        }
        #pragma unroll
        for (int s = 0; s < 4; s++) cand[s * 1024 + tid] = v[s];
    }
    __syncthreads();
    for (int k = 64; k <= CAP; k <<= 1) {
        for (int j = k >> 1; j >= 32; j >>= 1) {
            #pragma unroll
            for (int s0 = 0; s0 < CAP; s0 += 1024) {
                int i = s0 + tid;
                int l = i ^ j;
                if (l > i) {
                    unsigned long long a = cand[i], bb = cand[l];
                    bool up = ((i & k) == 0);
                    if ((a < bb) == up) { cand[i] = bb; cand[l] = a; }
                }
            }
            __syncthreads();
        }
        {
            unsigned long long v[4];
            #pragma unroll
            for (int s = 0; s < 4; s++) v[s] = cand[s * 1024 + tid];
            #pragma unroll
            for (int j = 16; j >= 1; j >>= 1) {
                #pragma unroll
                for (int s = 0; s < 4; s++) {
                    int i = s * 1024 + tid;
                    unsigned long long o = __shfl_xor_sync(0xffffffffu, v[s], j);
                    bool up    = ((i & k) == 0);
                    bool lower = ((i & j) == 0);
                    unsigned long long mx = v[s] > o ? v[s] : o;
                    unsigned long long mn = v[s] > o ? o : v[s];
                    v[s] = (up == lower) ? mx : mn;
                }
            }
            #pragma unroll
            for (int s = 0; s < 4; s++) cand[s * 1024 + tid] = v[s];
        }
        __syncthreads();
    }

    for (int i = tid; i < PRE_K; i += 1024) {
        unsigned long long k = cand[i];
        if (k == 0ULL) {
            scls2[i] = -1;
            scand2[i] = make_float4(0.f, 0.f, 0.f, 0.f);
        } else {
            int idx = (NB - 1) - (int)(unsigned int)k;
            scand2[i] = *(const float4*)(bxs + (size_t)idx * 4);
            scls2[i]  = (short)cats[idx];
        }
    }
    __syncthreads();

    if (tid < 32) {
        int nk = run_nms_warp(scand2, scls2, kept_idx, PRE_K, lane);
        if (lane == 0) sh_nk = nk;
    }
    __syncthreads();

    const int nk = sh_nk;
    for (int k0 = tid; k0 < MAX_OUT; k0 += 1024) {
        float vx1 = 0, vy1 = 0, vx2 = 0, vy2 = 0, vs = 0, vc = 0;
        if (k0 < nk) {
            int i = kept_idx[k0];
            float4 bbv = scand2[i];
            vx1 = bbv.x; vy1 = bbv.y; vx2 = bbv.z; vy2 = bbv.w;
            vs  = __uint_as_float((unsigned int)(cand[i] >> 32));
            vc  = (float)scls2[i];
        }
        out5[k0 * 5 + 0] = vx1;
        out5[k0 * 5 + 1] = vy1;
        out5[k0 * 5 + 2] = vx2;
        out5[k0 * 5 + 3] = vy2;
        out5[k0 * 5 + 4] = vs;
        if (write_cats) ocat[k0] = vc;
    }
}

// ---------------- launch ----------------------------------------------------
extern "C" void kernel_launch(void* const* d_in, const int* in_sizes, int n_in,
                              void* d_out, int out_size) {
    const float* boxes = (const float*)d_in[0];
    const float* confs = (const float*)d_in[1];
    if (n_in >= 2 && in_sizes[0] > in_sizes[1]) {
        boxes = (const float*)d_in[1];
        confs = (const float*)d_in[0];
    }
    float* out = (float*)d_out;

    if (out_size != BATCHES * MAX_OUT * 6)
        cudaMemsetAsync(d_out, 0, (size_t)out_size * sizeof(float), 0);

    cudaFuncSetAttribute(score_kernel,
                         cudaFuncAttributeMaxDynamicSharedMemorySize, SCORE_DYN);
    score_kernel<<<(BATCHES * NB) / (SB_ANCH * NTILES), SB_ANCH, SCORE_DYN>>>(confs);

    int write_cats = (out_size >= BATCHES * MAX_OUT * 6) ? 1 : 0;
    cudaFuncSetAttribute(fused_kernel,
                         cudaFuncAttributeMaxDynamicSharedMemorySize, FUSED_DYN);
    fused_kernel<<<BATCHES, 1024, FUSED_DYN>>>(boxes, out, write_cats);
}